// round 11
// baseline (speedup 1.0000x reference)
#include <cuda_runtime.h>
#include <cuda_bf16.h>
#include <math.h>
#include <stdint.h>

// Problem constants: B=4, T=16, T0=12, L=64, C=512, H=8, hd=64, NUM_SEEDS=4

// ---------------- scratch (static device globals; no allocations) -----------
__device__ int g_maskn[64];                // normalized ctx_mask [b*16 + t]

__device__ __align__(16) __nv_bfloat16 g_xh [3072 * 512], g_xl [3072 * 512];
__device__ __align__(16) __nv_bfloat16 g_xch[4096 * 512], g_xcl[4096 * 512];
__device__ __align__(16) __nv_bfloat16 g_dxh[4096 * 512], g_dxl[4096 * 512];
__device__ __align__(16) __nv_bfloat16 g_qwh[1536 * 512], g_qwl[1536 * 512];
__device__ __align__(16) __nv_bfloat16 g_kwh[ 512 * 512], g_kwl[ 512 * 512];
__device__ __align__(16) __nv_bfloat16 g_vwh[ 512 * 512], g_vwl[ 512 * 512];
__device__ __align__(16) __nv_bfloat16 g_pwh[ 512 * 512], g_pwl[ 512 * 512];
__device__ __align__(16) __nv_bfloat16 g_qkvh[3072 * 1536], g_qkvl[3072 * 1536];
__device__ __align__(16) __nv_bfloat16 g_kcth[4096 * 512],  g_kctl[4096 * 512];
__device__ __align__(16) __nv_bfloat16 g_vcth[4096 * 512],  g_vctl[4096 * 512];
__device__ __align__(16) __nv_bfloat16 g_ah [3072 * 512], g_al [3072 * 512];

// ---------------- helpers ----------------------------------------------------
__device__ __forceinline__ uint32_t s2u(const void* p) {
    uint32_t a;
    asm("{ .reg .u64 t; cvta.to.shared.u64 t, %1; cvt.u32.u64 %0, t; }"
        : "=r"(a) : "l"(p));
    return a;
}
__device__ __forceinline__ void cp16(uint32_t dst, const void* src) {
    asm volatile("cp.async.cg.shared.global [%0], [%1], 16;"
                 :: "r"(dst), "l"(src));
}
__device__ __forceinline__ void ldm_x4(uint32_t* r, uint32_t addr) {
    asm volatile("ldmatrix.sync.aligned.m8n8.x4.shared.b16 {%0,%1,%2,%3}, [%4];"
                 : "=r"(r[0]), "=r"(r[1]), "=r"(r[2]), "=r"(r[3]) : "r"(addr));
}
__device__ __forceinline__ void ldm_x4t(uint32_t* r, uint32_t addr) {
    asm volatile("ldmatrix.sync.aligned.m8n8.x4.trans.shared.b16 {%0,%1,%2,%3}, [%4];"
                 : "=r"(r[0]), "=r"(r[1]), "=r"(r[2]), "=r"(r[3]) : "r"(addr));
}
__device__ __forceinline__ void mma_bf16(float* c, const uint32_t* a, const uint32_t* b) {
    asm volatile(
        "mma.sync.aligned.m16n8k16.row.col.f32.bf16.bf16.f32 "
        "{%0,%1,%2,%3}, {%4,%5,%6,%7}, {%8,%9}, {%0,%1,%2,%3};"
        : "+f"(c[0]), "+f"(c[1]), "+f"(c[2]), "+f"(c[3])
        : "r"(a[0]), "r"(a[1]), "r"(a[2]), "r"(a[3]), "r"(b[0]), "r"(b[1]));
}
__device__ __forceinline__ uint32_t pack_bf(__nv_bfloat16 a, __nv_bfloat16 b) {
    return (uint32_t)__bfloat16_as_ushort(a) | ((uint32_t)__bfloat16_as_ushort(b) << 16);
}
__device__ __forceinline__ uint32_t pack_hi(float x, float y, float& rx, float& ry) {
    __nv_bfloat16 hx = __float2bfloat16(x), hy = __float2bfloat16(y);
    rx = x - __bfloat162float(hx);
    ry = y - __bfloat162float(hy);
    return pack_bf(hx, hy);
}

// ---------------- fused split: fp32 -> hi/lo bf16 ----------------------------
struct SplitArgs {
    const float4* src[4];
    uint2* hi[4];
    uint2* lo[4];
    int n4[4];
};
__global__ __launch_bounds__(256)
void split_all(SplitArgs a) {
    const int arr = blockIdx.y;
    const int n4 = a.n4[arr];
    const float4* __restrict__ s = a.src[arr];
    uint2* __restrict__ hp = a.hi[arr];
    uint2* __restrict__ lp = a.lo[arr];
    const int step = gridDim.x * 256;
    for (int i = blockIdx.x * 256 + threadIdx.x; i < n4; i += step) {
        float4 v = s[i];
        __nv_bfloat16 h0 = __float2bfloat16(v.x), h1 = __float2bfloat16(v.y);
        __nv_bfloat16 h2 = __float2bfloat16(v.z), h3 = __float2bfloat16(v.w);
        __nv_bfloat16 l0 = __float2bfloat16(v.x - __bfloat162float(h0));
        __nv_bfloat16 l1 = __float2bfloat16(v.y - __bfloat162float(h1));
        __nv_bfloat16 l2 = __float2bfloat16(v.z - __bfloat162float(h2));
        __nv_bfloat16 l3 = __float2bfloat16(v.w - __bfloat162float(h3));
        hp[i] = make_uint2(pack_bf(h0, h1), pack_bf(h2, h3));
        lp[i] = make_uint2(pack_bf(l0, l1), pack_bf(l2, l3));
    }
}

// ---------------- mask normalization (dtype-robust) --------------------------
__global__ void normalize_mask_kernel(const unsigned char* __restrict__ m8) {
    __shared__ int flag;
    int i = threadIdx.x;
    if (i == 0) flag = 0;
    __syncthreads();
    if ((i & 3) != 0 && m8[i] != 0) atomicOr(&flag, 1);
    __syncthreads();
    int v;
    if (flag) v = (m8[i] != 0) ? 1 : 0;
    else      v = (((const int*)m8)[i] != 0) ? 1 : 0;
    g_maskn[i] = v;
}

// ================= BIG GEMM: 128x128, 4-stage, for qkv (K=512) ===============
// Measured 55.5-56.5us for the 3072x1536 qkv GEMM (R8/R9).
#define PITCHB 80
#define TERM_B (128 * PITCHB)
#define BUF_B  (4 * TERM_B)
#define BGEMM_SMEM (4 * BUF_B)     // 163840

__global__ __launch_bounds__(256)
void gemm_big(const __nv_bfloat16* __restrict__ Ah, const __nv_bfloat16* __restrict__ Al,
              const __nv_bfloat16* __restrict__ Wh, const __nv_bfloat16* __restrict__ Wl,
              __nv_bfloat16* __restrict__ Ch, __nv_bfloat16* __restrict__ Cl,
              int M, int N) {
    extern __shared__ char smem[];
    const uint32_t sb = s2u(smem);
    const int tid = threadIdx.x;
    const int wid = tid >> 5, lane = tid & 31;
    const int gid = lane >> 2, tig = lane & 3;
    const int bm = blockIdx.y * 128, bn = blockIdx.x * 128;
    const int wm = wid >> 2, wn = wid & 3;

    float acc[4][4][4];
#pragma unroll
    for (int mf = 0; mf < 4; mf++)
#pragma unroll
        for (int nf = 0; nf < 4; nf++)
#pragma unroll
            for (int r = 0; r < 4; r++) acc[mf][nf][r] = 0.f;

    auto issue = [&](int c, int buf) {
        uint32_t base = sb + buf * BUF_B;
#pragma unroll
        for (int i = 0; i < 2; i++) {
            int f = tid + i * 256;
            int row = f >> 2, seg = f & 3;
            uint32_t d = base + row * PITCHB + seg * 16;
            const int ko = c * 32 + seg * 8;
            cp16(d,              Ah + (size_t)(bm + row) * 512 + ko);
            cp16(d + TERM_B,     Al + (size_t)(bm + row) * 512 + ko);
            cp16(d + 2 * TERM_B, Wh + (size_t)(bn + row) * 512 + ko);
            cp16(d + 3 * TERM_B, Wl + (size_t)(bn + row) * 512 + ko);
        }
        asm volatile("cp.async.commit_group;");
    };

    issue(0, 0); issue(1, 1); issue(2, 2);

    const uint32_t a_row16 = lane & 15;
    const uint32_t a_cofs  = (lane >> 4) * 16;
    const uint32_t b_nrow  = (lane & 7) + ((lane >> 4) & 1) * 8;
    const uint32_t b_kofs  = ((lane >> 3) & 1) * 16;

    for (int c = 0; c < 16; c++) {
        if (c <= 13)      asm volatile("cp.async.wait_group 2;");
        else if (c == 14) asm volatile("cp.async.wait_group 1;");
        else              asm volatile("cp.async.wait_group 0;");
        __syncthreads();
        if (c <= 12) issue(c + 3, (c + 3) & 3);

        const uint32_t abase = sb + (c & 3) * BUF_B;
        const uint32_t bbase = abase + 2 * TERM_B;

#pragma unroll
        for (int kf = 0; kf < 2; kf++) {
            uint32_t ah[4][4], al[4][4], bh[4][2], bl[4][2];
            const uint32_t kb = kf * 32;
#pragma unroll
            for (int mf = 0; mf < 4; mf++) {
                uint32_t ad = abase + (wm * 64 + mf * 16 + a_row16) * PITCHB
                            + a_cofs + kb;
                ldm_x4(ah[mf], ad);
                ldm_x4(al[mf], ad + TERM_B);
            }
#pragma unroll
            for (int pr = 0; pr < 2; pr++) {
                uint32_t bd = bbase + (wn * 32 + pr * 16 + b_nrow) * PITCHB
                            + b_kofs + kb;
                uint32_t th[4], tl[4];
                ldm_x4(th, bd);
                ldm_x4(tl, bd + TERM_B);
                bh[pr * 2 + 0][0] = th[0]; bh[pr * 2 + 0][1] = th[1];
                bh[pr * 2 + 1][0] = th[2]; bh[pr * 2 + 1][1] = th[3];
                bl[pr * 2 + 0][0] = tl[0]; bl[pr * 2 + 0][1] = tl[1];
                bl[pr * 2 + 1][0] = tl[2]; bl[pr * 2 + 1][1] = tl[3];
            }
#pragma unroll
            for (int mf = 0; mf < 4; mf++)
#pragma unroll
                for (int nf = 0; nf < 4; nf++) {
                    mma_bf16(acc[mf][nf], ah[mf], bh[nf]);
                    mma_bf16(acc[mf][nf], ah[mf], bl[nf]);
                    mma_bf16(acc[mf][nf], al[mf], bh[nf]);
                }
        }
    }

#pragma unroll
    for (int mf = 0; mf < 4; mf++) {
#pragma unroll
        for (int nf = 0; nf < 4; nf++) {
            int row = bm + wm * 64 + mf * 16 + gid;
            int col = bn + wn * 32 + nf * 8 + tig * 2;
            float r0, r1, r2, r3;
            uint32_t h0 = pack_hi(acc[mf][nf][0], acc[mf][nf][1], r0, r1);
            uint32_t h1 = pack_hi(acc[mf][nf][2], acc[mf][nf][3], r2, r3);
            *(uint32_t*)&Ch[(size_t)row * N + col] = h0;
            *(uint32_t*)&Ch[(size_t)(row + 8) * N + col] = h1;
            *(uint32_t*)&Cl[(size_t)row * N + col] =
                pack_bf(__float2bfloat16(r0), __float2bfloat16(r1));
            *(uint32_t*)&Cl[(size_t)(row + 8) * N + col] =
                pack_bf(__float2bfloat16(r2), __float2bfloat16(r3));
        }
    }
}

// ======= SMALL GEMM: 128x64, 2-stage, 2 CTA/SM (exact R7 / 194.7us body) =====
#define A_BYTES (128 * PITCHB)
#define B_BYTES (64 * PITCHB)
#define BUF_BYTES (2 * A_BYTES + 2 * B_BYTES)
#define SGEMM_SMEM (2 * BUF_BYTES)      // 61440

__global__ __launch_bounds__(256, 2)
void gemm_tc(const __nv_bfloat16* __restrict__ Ah, const __nv_bfloat16* __restrict__ Al,
             const __nv_bfloat16* __restrict__ Wh, const __nv_bfloat16* __restrict__ Wl,
             const float* __restrict__ bias, float* __restrict__ C,
             __nv_bfloat16* __restrict__ Ch, __nv_bfloat16* __restrict__ Cl,
             int M, int N, int K) {
    extern __shared__ char smem[];
    const uint32_t sb = s2u(smem);
    const int tid = threadIdx.x;
    const int wid = tid >> 5, lane = tid & 31;
    const int gid = lane >> 2, tig = lane & 3;
    const int bm = blockIdx.y * 128, bn = blockIdx.x * 64;
    const int wm = wid & 3, wn = wid >> 2;

    const int arow = tid >> 2;
    const int aseg = tid & 3;

    float acc[2][4][4];
#pragma unroll
    for (int mf = 0; mf < 2; mf++)
#pragma unroll
        for (int nf = 0; nf < 4; nf++)
#pragma unroll
            for (int r = 0; r < 4; r++) acc[mf][nf][r] = 0.f;

    const int nc = K >> 5;

    auto issue = [&](int c, int buf) {
        uint32_t base = sb + buf * BUF_BYTES;
        const int kofs = c * 32 + aseg * 8;
#pragma unroll
        for (int i = 0; i < 2; i++) {
            int row = arow + i * 64;
            uint32_t d = base + row * PITCHB + aseg * 16;
            cp16(d,            Ah + (size_t)(bm + row) * K + kofs);
            cp16(d + A_BYTES,  Al + (size_t)(bm + row) * K + kofs);
        }
        {
            int row = arow;
            uint32_t d = base + 2 * A_BYTES + row * PITCHB + aseg * 16;
            cp16(d,            Wh + (size_t)(bn + row) * K + kofs);
            cp16(d + B_BYTES,  Wl + (size_t)(bn + row) * K + kofs);
        }
        asm volatile("cp.async.commit_group;");
    };

    issue(0, 0);

    const uint32_t a_row16 = lane & 15;
    const uint32_t a_cofs  = (lane >> 4) * 16;
    const uint32_t b_nrow  = (lane & 7) + ((lane >> 4) & 1) * 8;
    const uint32_t b_kofs  = ((lane >> 3) & 1) * 16;

    for (int c = 0; c < nc; c++) {
        const int buf = c & 1;
        if (c + 1 < nc) {
            issue(c + 1, buf ^ 1);
            asm volatile("cp.async.wait_group 1;");
        } else {
            asm volatile("cp.async.wait_group 0;");
        }
        __syncthreads();

        const uint32_t abase = sb + buf * BUF_BYTES;
        const uint32_t bbase = abase + 2 * A_BYTES;

#pragma unroll
        for (int kf = 0; kf < 2; kf++) {
            uint32_t ah[2][4], al[2][4], bh[4][2], bl[4][2];
            const uint32_t kb = kf * 32;
#pragma unroll
            for (int mf = 0; mf < 2; mf++) {
                uint32_t ad = abase + (wm * 32 + mf * 16 + a_row16) * PITCHB
                            + a_cofs + kb;
                ldm_x4(ah[mf], ad);
                ldm_x4(al[mf], ad + A_BYTES);
            }
#pragma unroll
            for (int pr = 0; pr < 2; pr++) {
                uint32_t bd = bbase + (wn * 32 + pr * 16 + b_nrow) * PITCHB
                            + b_kofs + kb;
                uint32_t th[4], tl[4];
                ldm_x4(th, bd);
                ldm_x4(tl, bd + B_BYTES);
                bh[pr * 2 + 0][0] = th[0]; bh[pr * 2 + 0][1] = th[1];
                bh[pr * 2 + 1][0] = th[2]; bh[pr * 2 + 1][1] = th[3];
                bl[pr * 2 + 0][0] = tl[0]; bl[pr * 2 + 0][1] = tl[1];
                bl[pr * 2 + 1][0] = tl[2]; bl[pr * 2 + 1][1] = tl[3];
            }
#pragma unroll
            for (int mf = 0; mf < 2; mf++)
#pragma unroll
                for (int nf = 0; nf < 4; nf++) {
                    mma_bf16(acc[mf][nf], ah[mf], bh[nf]);
                    mma_bf16(acc[mf][nf], ah[mf], bl[nf]);
                    mma_bf16(acc[mf][nf], al[mf], bh[nf]);
                }
        }
        __syncthreads();
    }

    if (Ch) {
#pragma unroll
        for (int mf = 0; mf < 2; mf++) {
#pragma unroll
            for (int nf = 0; nf < 4; nf++) {
                int row = bm + wm * 32 + mf * 16 + gid;
                int col = bn + wn * 32 + nf * 8 + tig * 2;
                float r0, r1, r2, r3;
                uint32_t h0 = pack_hi(acc[mf][nf][0], acc[mf][nf][1], r0, r1);
                uint32_t h1 = pack_hi(acc[mf][nf][2], acc[mf][nf][3], r2, r3);
                *(uint32_t*)&Ch[(size_t)row * N + col] = h0;
                *(uint32_t*)&Ch[(size_t)(row + 8) * N + col] = h1;
                *(uint32_t*)&Cl[(size_t)row * N + col] =
                    pack_bf(__float2bfloat16(r0), __float2bfloat16(r1));
                *(uint32_t*)&Cl[(size_t)(row + 8) * N + col] =
                    pack_bf(__float2bfloat16(r2), __float2bfloat16(r3));
            }
        }
    } else {
#pragma unroll
        for (int mf = 0; mf < 2; mf++) {
#pragma unroll
            for (int nf = 0; nf < 4; nf++) {
                int row = bm + wm * 32 + mf * 16 + gid;
                int col = bn + wn * 32 + nf * 8 + tig * 2;
                float b0 = bias ? bias[col] : 0.f;
                float b1 = bias ? bias[col + 1] : 0.f;
                float2 v0 = make_float2(acc[mf][nf][0] + b0, acc[mf][nf][1] + b1);
                float2 v1 = make_float2(acc[mf][nf][2] + b0, acc[mf][nf][3] + b1);
                *(float2*)&C[(size_t)row * N + col] = v0;
                *(float2*)&C[(size_t)(row + 8) * N + col] = v1;
            }
        }
    }
}

// ---------------- tensor-core flash attention (unchanged, validated) ---------
#define APITCH 144
#define TILE_B 9216
#define QH_OFF 0
#define QL_OFF TILE_B
#define KV_OFF (2 * TILE_B)
#define KVBUF_B (4 * TILE_B)
#define ATTN_SMEM (2 * TILE_B + 2 * KVBUF_B)   // 92160

__global__ __launch_bounds__(128)
void attn_tc(const __nv_bfloat16* __restrict__ qkvh, const __nv_bfloat16* __restrict__ qkvl,
             const __nv_bfloat16* __restrict__ kcth, const __nv_bfloat16* __restrict__ kctl,
             const __nv_bfloat16* __restrict__ vcth, const __nv_bfloat16* __restrict__ vctl,
             __nv_bfloat16* __restrict__ outh, __nv_bfloat16* __restrict__ outl) {
    extern __shared__ char smem[];
    const uint32_t sb = s2u(smem);
    const int t0 = blockIdx.x, h = blockIdx.y, b = blockIdx.z;
    const int tid = threadIdx.x;
    const int w = tid >> 5, lane = tid & 31;
    const int gid = lane >> 2, tig = lane & 3;

    int ids[17], nv = 0;
    for (int t = 0; t < 16; t++)
        if (g_maskn[b * 16 + t] && t != t0 + 4) ids[nv++] = t;
    ids[nv++] = 16;

    const int seg = tid & 7;
    const int r0 = tid >> 3;

    {
        const size_t base = (size_t)(b * 768 + t0 * 64) * 1536 + h * 64 + seg * 8;
#pragma unroll
        for (int i = 0; i < 4; i++) {
            int row = r0 + i * 16;
            uint32_t d = sb + row * APITCH + seg * 16;
            cp16(d + QH_OFF, qkvh + base + (size_t)row * 1536);
            cp16(d + QL_OFF, qkvl + base + (size_t)row * 1536);
        }
    }

    auto issueKV = [&](int id, int buf) {
        const __nv_bfloat16 *ksh, *ksl, *vsh, *vsl;
        size_t kbase, vbase, rs;
        if (id < 16) {
            rs = 512;
            kbase = (size_t)(b * 1024 + id * 64) * 512 + h * 64 + seg * 8;
            vbase = kbase;
            ksh = kcth; ksl = kctl; vsh = vcth; vsl = vctl;
        } else {
            rs = 1536;
            size_t rb = (size_t)(b * 768 + t0 * 64) * 1536 + h * 64 + seg * 8;
            kbase = rb + 512; vbase = rb + 1024;
            ksh = qkvh; ksl = qkvl; vsh = qkvh; vsl = qkvl;
        }
        uint32_t base = sb + KV_OFF + buf * KVBUF_B;
#pragma unroll
        for (int i = 0; i < 4; i++) {
            int row = r0 + i * 16;
            uint32_t d = base + row * APITCH + seg * 16;
            cp16(d,              ksh + kbase + (size_t)row * rs);
            cp16(d + TILE_B,     ksl + kbase + (size_t)row * rs);
            cp16(d + 2 * TILE_B, vsh + vbase + (size_t)row * rs);
            cp16(d + 3 * TILE_B, vsl + vbase + (size_t)row * rs);
        }
        asm volatile("cp.async.commit_group;");
    };

    issueKV(ids[0], 0);

    const uint32_t a_row16 = lane & 15;
    const uint32_t a_cofs  = (lane >> 4) * 16;
    const uint32_t b_nrow  = (lane & 7) + ((lane >> 4) & 1) * 8;
    const uint32_t b_kofs  = ((lane >> 3) & 1) * 16;
    const uint32_t v_krow = lane & 15;
    const uint32_t v_dofs = (lane >> 4) * 16;

    uint32_t qh[4][4], ql[4][4];
    float of[8][4];
#pragma unroll
    for (int f = 0; f < 8; f++)
#pragma unroll
        for (int r = 0; r < 4; r++) of[f][r] = 0.f;
    float m1 = -INFINITY, m2 = -INFINITY, l1 = 0.f, l2 = 0.f;

    for (int i = 0; i < nv; i++) {
        if (i + 1 < nv) {
            issueKV(ids[i + 1], (i + 1) & 1);
            asm volatile("cp.async.wait_group 1;");
        } else {
            asm volatile("cp.async.wait_group 0;");
        }
        __syncthreads();

        if (i == 0) {
#pragma unroll
            for (int kf = 0; kf < 4; kf++) {
                uint32_t ad = sb + (w * 16 + a_row16) * APITCH + a_cofs + kf * 32;
                ldm_x4(qh[kf], ad + QH_OFF);
                ldm_x4(ql[kf], ad + QL_OFF);
            }
        }

        const uint32_t kvb = sb + KV_OFF + (i & 1) * KVBUF_B;

        float sf[8][4];
#pragma unroll
        for (int f = 0; f < 8; f++)
#pragma unroll
            for (int r = 0; r < 4; r++) sf[f][r] = 0.f;

#pragma unroll
        for (int nfp = 0; nfp < 4; nfp++) {
#pragma unroll
            for (int kf = 0; kf < 4; kf++) {
                uint32_t th[4], tl[4];
                uint32_t kd = kvb + (nfp * 16 + b_nrow) * APITCH + b_kofs + kf * 32;
                ldm_x4(th, kd);
                ldm_x4(tl, kd + TILE_B);
                mma_bf16(sf[nfp * 2 + 0], qh[kf], &th[0]);
                mma_bf16(sf[nfp * 2 + 0], qh[kf], &tl[0]);
                mma_bf16(sf[nfp * 2 + 0], ql[kf], &th[0]);
                mma_bf16(sf[nfp * 2 + 1], qh[kf], &th[2]);
                mma_bf16(sf[nfp * 2 + 1], qh[kf], &tl[2]);
                mma_bf16(sf[nfp * 2 + 1], ql[kf], &th[2]);
            }
        }

        float cm1 = -INFINITY, cm2 = -INFINITY;
#pragma unroll
        for (int f = 0; f < 8; f++) {
            sf[f][0] *= 0.125f; sf[f][1] *= 0.125f;
            sf[f][2] *= 0.125f; sf[f][3] *= 0.125f;
            cm1 = fmaxf(cm1, fmaxf(sf[f][0], sf[f][1]));
            cm2 = fmaxf(cm2, fmaxf(sf[f][2], sf[f][3]));
        }
        cm1 = fmaxf(cm1, __shfl_xor_sync(0xffffffffu, cm1, 1));
        cm1 = fmaxf(cm1, __shfl_xor_sync(0xffffffffu, cm1, 2));
        cm2 = fmaxf(cm2, __shfl_xor_sync(0xffffffffu, cm2, 1));
        cm2 = fmaxf(cm2, __shfl_xor_sync(0xffffffffu, cm2, 2));
        float mn1 = fmaxf(m1, cm1), mn2 = fmaxf(m2, cm2);
        float f1 = __expf(m1 - mn1), f2 = __expf(m2 - mn2);
        float rs1 = 0.f, rs2 = 0.f;
#pragma unroll
        for (int f = 0; f < 8; f++) {
            sf[f][0] = __expf(sf[f][0] - mn1);
            sf[f][1] = __expf(sf[f][1] - mn1);
            sf[f][2] = __expf(sf[f][2] - mn2);
            sf[f][3] = __expf(sf[f][3] - mn2);
            rs1 += sf[f][0] + sf[f][1];
            rs2 += sf[f][2] + sf[f][3];
        }
        rs1 += __shfl_xor_sync(0xffffffffu, rs1, 1);
        rs1 += __shfl_xor_sync(0xffffffffu, rs1, 2);
        rs2 += __shfl_xor_sync(0xffffffffu, rs2, 1);
        rs2 += __shfl_xor_sync(0xffffffffu, rs2, 2);
        l1 = l1 * f1 + rs1; l2 = l2 * f2 + rs2;
        m1 = mn1; m2 = mn2;
#pragma unroll
        for (int f = 0; f < 8; f++) {
            of[f][0] *= f1; of[f][1] *= f1;
            of[f][2] *= f2; of[f][3] *= f2;
        }

        uint32_t ph[4][4], pl[4][4];
#pragma unroll
        for (int kf = 0; kf < 4; kf++) {
            float r0a, r1a, r2a, r3a;
            ph[kf][0] = pack_hi(sf[2 * kf][0], sf[2 * kf][1], r0a, r1a);
            pl[kf][0] = pack_bf(__float2bfloat16(r0a), __float2bfloat16(r1a));
            ph[kf][1] = pack_hi(sf[2 * kf][2], sf[2 * kf][3], r0a, r1a);
            pl[kf][1] = pack_bf(__float2bfloat16(r0a), __float2bfloat16(r1a));
            ph[kf][2] = pack_hi(sf[2 * kf + 1][0], sf[2 * kf + 1][1], r2a, r3a);
            pl[kf][2] = pack_bf(__float2bfloat16(r2a), __float2bfloat16(r3a));
            ph[kf][3] = pack_hi(sf[2 * kf + 1][2], sf[2 * kf + 1][3], r2a, r3a);
            pl[kf][3] = pack_bf(__float2bfloat16(r2a), __float2bfloat16(r3a));
        }

        const uint32_t vb = kvb + 2 * TILE_B;
#pragma unroll
        for (int nfp = 0; nfp < 4; nfp++) {
#pragma unroll
            for (int kf = 0; kf < 4; kf++) {
                uint32_t vh_[4], vl_[4];
                uint32_t vd = vb + (kf * 16 + v_krow) * APITCH + nfp * 32 + v_dofs;
                ldm_x4t(vh_, vd);
                ldm_x4t(vl_, vd + TILE_B);
                mma_bf16(of[nfp * 2 + 0], ph[kf], &vh_[0]);
                mma_bf16(of[nfp * 2 + 0], ph[kf], &vl_[0]);
                mma_bf16(of[nfp * 2 + 0], pl[kf], &vh_[0]);
                mma_bf16(of[nfp * 2 + 1], ph[kf], &vh_[2]);
                mma_bf16(of[nfp * 2 + 1], ph[kf], &vl_[2]);
                mma_bf16(of[nfp * 2 + 1], pl[kf], &vh_[2]);
            }
        }
        __syncthreads();
    }

    const float inv1 = 1.0f / l1, inv2 = 1.0f / l2;
    const size_t row1 = (size_t)(b * 768 + t0 * 64 + w * 16 + gid);
    const size_t row2 = row1 + 8;
#pragma unroll
    for (int nf = 0; nf < 8; nf++) {
        int col = h * 64 + nf * 8 + tig * 2;
        float r0a, r1a;
        uint32_t h0 = pack_hi(of[nf][0] * inv1, of[nf][1] * inv1, r0a, r1a);
        *(uint32_t*)&outh[row1 * 512 + col] = h0;
        *(uint32_t*)&outl[row1 * 512 + col] =
            pack_bf(__float2bfloat16(r0a), __float2bfloat16(r1a));
        uint32_t h1 = pack_hi(of[nf][2] * inv2, of[nf][3] * inv2, r0a, r1a);
        *(uint32_t*)&outh[row2 * 512 + col] = h1;
        *(uint32_t*)&outl[row2 * 512 + col] =
            pack_bf(__float2bfloat16(r0a), __float2bfloat16(r1a));
    }
}

// ---------------- launcher ---------------------------------------------------
extern "C" void kernel_launch(void* const* d_in, const int* in_sizes, int n_in,
                              void* d_out, int out_size) {
    const float* x      = (const float*)d_in[0];
    const float* x_ctx  = (const float*)d_in[1];
    const float* dx_ctx = (const float*)d_in[2];
    const unsigned char* mask = (const unsigned char*)d_in[3];
    const float* qkv_w  = (const float*)d_in[4];
    const float* k_w    = (const float*)d_in[5];
    const float* v_w    = (const float*)d_in[6];
    const float* proj_w = (const float*)d_in[7];
    const float* proj_b = (const float*)d_in[8];
    float* out = (float*)d_out;

    __nv_bfloat16 *xh, *xl, *xch, *xcl, *dxh, *dxl, *qwh, *qwl,
                  *kwh, *kwl, *vwh, *vwl, *pwh, *pwl, *ah, *al,
                  *qkvh, *qkvl, *kcth, *kctl, *vcth, *vctl;
    cudaGetSymbolAddress((void**)&xh,  g_xh);  cudaGetSymbolAddress((void**)&xl,  g_xl);
    cudaGetSymbolAddress((void**)&xch, g_xch); cudaGetSymbolAddress((void**)&xcl, g_xcl);
    cudaGetSymbolAddress((void**)&dxh, g_dxh); cudaGetSymbolAddress((void**)&dxl, g_dxl);
    cudaGetSymbolAddress((void**)&qwh, g_qwh); cudaGetSymbolAddress((void**)&qwl, g_qwl);
    cudaGetSymbolAddress((void**)&kwh, g_kwh); cudaGetSymbolAddress((void**)&kwl, g_kwl);
    cudaGetSymbolAddress((void**)&vwh, g_vwh); cudaGetSymbolAddress((void**)&vwl, g_vwl);
    cudaGetSymbolAddress((void**)&pwh, g_pwh); cudaGetSymbolAddress((void**)&pwl, g_pwl);
    cudaGetSymbolAddress((void**)&ah,  g_ah);  cudaGetSymbolAddress((void**)&al,  g_al);
    cudaGetSymbolAddress((void**)&qkvh, g_qkvh); cudaGetSymbolAddress((void**)&qkvl, g_qkvl);
    cudaGetSymbolAddress((void**)&kcth, g_kcth); cudaGetSymbolAddress((void**)&kctl, g_kctl);
    cudaGetSymbolAddress((void**)&vcth, g_vcth); cudaGetSymbolAddress((void**)&vctl, g_vctl);

    cudaFuncSetAttribute(gemm_big, cudaFuncAttributeMaxDynamicSharedMemorySize, BGEMM_SMEM);
    cudaFuncSetAttribute(gemm_tc,  cudaFuncAttributeMaxDynamicSharedMemorySize, SGEMM_SMEM);
    cudaFuncSetAttribute(attn_tc,  cudaFuncAttributeMaxDynamicSharedMemorySize, ATTN_SMEM);

    // 1: mask
    normalize_mask_kernel<<<1, 64>>>(mask);

    // 2: big splits
    SplitArgs sa;
    sa.src[0] = (const float4*)x;      sa.hi[0] = (uint2*)xh;  sa.lo[0] = (uint2*)xl;  sa.n4[0] = 3072 * 512 / 4;
    sa.src[1] = (const float4*)x_ctx;  sa.hi[1] = (uint2*)xch; sa.lo[1] = (uint2*)xcl; sa.n4[1] = 4096 * 512 / 4;
    sa.src[2] = (const float4*)dx_ctx; sa.hi[2] = (uint2*)dxh; sa.lo[2] = (uint2*)dxl; sa.n4[2] = 4096 * 512 / 4;
    sa.src[3] = (const float4*)qkv_w;  sa.hi[3] = (uint2*)qwh; sa.lo[3] = (uint2*)qwl; sa.n4[3] = 1536 * 512 / 4;
    split_all<<<dim3(296, 4), 256>>>(sa);

    // 3: small splits
    SplitArgs sb_;
    sb_.src[0] = (const float4*)k_w;    sb_.hi[0] = (uint2*)kwh; sb_.lo[0] = (uint2*)kwl; sb_.n4[0] = 512 * 512 / 4;
    sb_.src[1] = (const float4*)v_w;    sb_.hi[1] = (uint2*)vwh; sb_.lo[1] = (uint2*)vwl; sb_.n4[1] = 512 * 512 / 4;
    sb_.src[2] = (const float4*)proj_w; sb_.hi[2] = (uint2*)pwh; sb_.lo[2] = (uint2*)pwl; sb_.n4[2] = 512 * 512 / 4;
    sb_.src[3] = (const float4*)proj_w; sb_.hi[3] = (uint2*)pwh; sb_.lo[3] = (uint2*)pwl; sb_.n4[3] = 0;
    split_all<<<dim3(128, 3), 256>>>(sb_);

    // 4: qkv = x @ qkv_w^T -> hi/lo bf16 (measured-faster big kernel)
    gemm_big<<<dim3(1536 / 128, 3072 / 128), 256, BGEMM_SMEM>>>(
        xh, xl, qwh, qwl, qkvh, qkvl, 3072, 1536);

    // 5: k_ctx = dx_ctx @ k_w^T -> hi/lo bf16 (exact R7 small kernel)
    gemm_tc<<<dim3(512 / 64, 4096 / 128), 256, SGEMM_SMEM>>>(
        dxh, dxl, kwh, kwl, nullptr, nullptr, kcth, kctl, 4096, 512, 512);
    // 6: v_ctx = x_ctx @ v_w^T -> hi/lo bf16
    gemm_tc<<<dim3(512 / 64, 4096 / 128), 256, SGEMM_SMEM>>>(
        xch, xcl, vwh, vwl, nullptr, nullptr, vcth, vctl, 4096, 512, 512);

    // 7: tensor-core flash attention -> hi/lo bf16
    attn_tc<<<dim3(12, 8, 4), 128, ATTN_SMEM>>>(
        qkvh, qkvl, kcth, kctl, vcth, vctl, ah, al);

    // 8: final projection + bias -> d_out (fp32)
    gemm_tc<<<dim3(512 / 64, 3072 / 128), 256, SGEMM_SMEM>>>(
        ah, al, pwh, pwl, proj_b, out, nullptr, nullptr, 3072, 512, 512);
}

// round 12
// speedup vs baseline: 1.0853x; 1.0853x over previous
#include <cuda_runtime.h>
#include <cuda_bf16.h>
#include <math.h>
#include <stdint.h>

// Problem constants: B=4, T=16, T0=12, L=64, C=512, H=8, hd=64, NUM_SEEDS=4

// ---------------- scratch (static device globals; no allocations) -----------
__device__ int g_maskn[64];                // normalized ctx_mask [b*16 + t]

__device__ __align__(16) __nv_bfloat16 g_xh [3072 * 512], g_xl [3072 * 512];
__device__ __align__(16) __nv_bfloat16 g_xch[4096 * 512], g_xcl[4096 * 512];
__device__ __align__(16) __nv_bfloat16 g_dxh[4096 * 512], g_dxl[4096 * 512];
__device__ __align__(16) __nv_bfloat16 g_qwh[1536 * 512], g_qwl[1536 * 512];
__device__ __align__(16) __nv_bfloat16 g_kwh[ 512 * 512], g_kwl[ 512 * 512];
__device__ __align__(16) __nv_bfloat16 g_vwh[ 512 * 512], g_vwl[ 512 * 512];
__device__ __align__(16) __nv_bfloat16 g_pwh[ 512 * 512], g_pwl[ 512 * 512];
__device__ __align__(16) __nv_bfloat16 g_qkvh[3072 * 1536], g_qkvl[3072 * 1536];
__device__ __align__(16) __nv_bfloat16 g_kcth[4096 * 512],  g_kctl[4096 * 512];
__device__ __align__(16) __nv_bfloat16 g_vcth[4096 * 512],  g_vctl[4096 * 512];
__device__ __align__(16) __nv_bfloat16 g_ah [3072 * 512], g_al [3072 * 512];

// ---------------- helpers ----------------------------------------------------
__device__ __forceinline__ uint32_t s2u(const void* p) {
    uint32_t a;
    asm("{ .reg .u64 t; cvta.to.shared.u64 t, %1; cvt.u32.u64 %0, t; }"
        : "=r"(a) : "l"(p));
    return a;
}
__device__ __forceinline__ void cp16(uint32_t dst, const void* src) {
    asm volatile("cp.async.cg.shared.global [%0], [%1], 16;"
                 :: "r"(dst), "l"(src));
}
__device__ __forceinline__ void ldm_x4(uint32_t* r, uint32_t addr) {
    asm volatile("ldmatrix.sync.aligned.m8n8.x4.shared.b16 {%0,%1,%2,%3}, [%4];"
                 : "=r"(r[0]), "=r"(r[1]), "=r"(r[2]), "=r"(r[3]) : "r"(addr));
}
__device__ __forceinline__ void ldm_x4t(uint32_t* r, uint32_t addr) {
    asm volatile("ldmatrix.sync.aligned.m8n8.x4.trans.shared.b16 {%0,%1,%2,%3}, [%4];"
                 : "=r"(r[0]), "=r"(r[1]), "=r"(r[2]), "=r"(r[3]) : "r"(addr));
}
__device__ __forceinline__ void mma_bf16(float* c, const uint32_t* a, const uint32_t* b) {
    asm volatile(
        "mma.sync.aligned.m16n8k16.row.col.f32.bf16.bf16.f32 "
        "{%0,%1,%2,%3}, {%4,%5,%6,%7}, {%8,%9}, {%0,%1,%2,%3};"
        : "+f"(c[0]), "+f"(c[1]), "+f"(c[2]), "+f"(c[3])
        : "r"(a[0]), "r"(a[1]), "r"(a[2]), "r"(a[3]), "r"(b[0]), "r"(b[1]));
}
__device__ __forceinline__ uint32_t pack_bf(__nv_bfloat16 a, __nv_bfloat16 b) {
    return (uint32_t)__bfloat16_as_ushort(a) | ((uint32_t)__bfloat16_as_ushort(b) << 16);
}
__device__ __forceinline__ uint32_t pack_hi(float x, float y, float& rx, float& ry) {
    __nv_bfloat16 hx = __float2bfloat16(x), hy = __float2bfloat16(y);
    rx = x - __bfloat162float(hx);
    ry = y - __bfloat162float(hy);
    return pack_bf(hx, hy);
}

// ---------------- fused split: fp32 -> hi/lo bf16 (ONE launch, 7 arrays) -----
struct SplitArgs {
    const float4* src[7];
    uint2* hi[7];
    uint2* lo[7];
    int n4[7];
};
__global__ __launch_bounds__(256)
void split_all(SplitArgs a) {
    const int arr = blockIdx.y;
    const int n4 = a.n4[arr];
    const float4* __restrict__ s = a.src[arr];
    uint2* __restrict__ hp = a.hi[arr];
    uint2* __restrict__ lp = a.lo[arr];
    const int step = gridDim.x * 256;
    for (int i = blockIdx.x * 256 + threadIdx.x; i < n4; i += step) {
        float4 v = s[i];
        __nv_bfloat16 h0 = __float2bfloat16(v.x), h1 = __float2bfloat16(v.y);
        __nv_bfloat16 h2 = __float2bfloat16(v.z), h3 = __float2bfloat16(v.w);
        __nv_bfloat16 l0 = __float2bfloat16(v.x - __bfloat162float(h0));
        __nv_bfloat16 l1 = __float2bfloat16(v.y - __bfloat162float(h1));
        __nv_bfloat16 l2 = __float2bfloat16(v.z - __bfloat162float(h2));
        __nv_bfloat16 l3 = __float2bfloat16(v.w - __bfloat162float(h3));
        hp[i] = make_uint2(pack_bf(h0, h1), pack_bf(h2, h3));
        lp[i] = make_uint2(pack_bf(l0, l1), pack_bf(l2, l3));
    }
}

// ---------------- mask normalization (dtype-robust) --------------------------
__global__ void normalize_mask_kernel(const unsigned char* __restrict__ m8) {
    __shared__ int flag;
    int i = threadIdx.x;
    if (i == 0) flag = 0;
    __syncthreads();
    if ((i & 3) != 0 && m8[i] != 0) atomicOr(&flag, 1);
    __syncthreads();
    int v;
    if (flag) v = (m8[i] != 0) ? 1 : 0;
    else      v = (((const int*)m8)[i] != 0) ? 1 : 0;
    g_maskn[i] = v;
}

// ======== SMALL GEMM body constants (128x64, BK=32, 2-stage, 2 CTA/SM) =======
#define PITCHB 80
#define A_BYTES (128 * PITCHB)
#define B_BYTES (64 * PITCHB)
#define BUF_BYTES (2 * A_BYTES + 2 * B_BYTES)
#define SGEMM_SMEM (2 * BUF_BYTES)      // 61440

// ---- fused qkv + kctx + vctx: one launch, 1088 blocks, proven R7 body -------
// blocks [0,576): qkv (24 n-tiles x 24 m-tiles, N=1536)
// blocks [576,832): kctx (8 x 32, N=512); [832,1088): vctx (8 x 32, N=512)
struct Gemm3 {
    const __nv_bfloat16* Ah[3];
    const __nv_bfloat16* Al[3];
    const __nv_bfloat16* Wh[3];
    const __nv_bfloat16* Wl[3];
    __nv_bfloat16* Ch[3];
    __nv_bfloat16* Cl[3];
};

__global__ __launch_bounds__(256, 2)
void gemm3_fused(Gemm3 g) {
    const int idx = blockIdx.x;
    const int prob = (idx >= 576) + (idx >= 832);
    const int local = idx - (prob == 0 ? 0 : (prob == 1 ? 576 : 832));
    const int nbx = (prob == 0) ? 24 : 8;
    const int N   = (prob == 0) ? 1536 : 512;
    const int bx = local % nbx, by = local / nbx;

    const __nv_bfloat16* __restrict__ Ah = g.Ah[prob];
    const __nv_bfloat16* __restrict__ Al = g.Al[prob];
    const __nv_bfloat16* __restrict__ Wh = g.Wh[prob];
    const __nv_bfloat16* __restrict__ Wl = g.Wl[prob];
    __nv_bfloat16* __restrict__ Ch = g.Ch[prob];
    __nv_bfloat16* __restrict__ Cl = g.Cl[prob];

    extern __shared__ char smem[];
    const uint32_t sb = s2u(smem);
    const int tid = threadIdx.x;
    const int wid = tid >> 5, lane = tid & 31;
    const int gid = lane >> 2, tig = lane & 3;
    const int bm = by * 128, bn = bx * 64;
    const int wm = wid & 3, wn = wid >> 2;

    const int arow = tid >> 2;
    const int aseg = tid & 3;

    float acc[2][4][4];
#pragma unroll
    for (int mf = 0; mf < 2; mf++)
#pragma unroll
        for (int nf = 0; nf < 4; nf++)
#pragma unroll
            for (int r = 0; r < 4; r++) acc[mf][nf][r] = 0.f;

    auto issue = [&](int c, int buf) {
        uint32_t base = sb + buf * BUF_BYTES;
        const int kofs = c * 32 + aseg * 8;
#pragma unroll
        for (int i = 0; i < 2; i++) {
            int row = arow + i * 64;
            uint32_t d = base + row * PITCHB + aseg * 16;
            cp16(d,            Ah + (size_t)(bm + row) * 512 + kofs);
            cp16(d + A_BYTES,  Al + (size_t)(bm + row) * 512 + kofs);
        }
        {
            int row = arow;
            uint32_t d = base + 2 * A_BYTES + row * PITCHB + aseg * 16;
            cp16(d,            Wh + (size_t)(bn + row) * 512 + kofs);
            cp16(d + B_BYTES,  Wl + (size_t)(bn + row) * 512 + kofs);
        }
        asm volatile("cp.async.commit_group;");
    };

    issue(0, 0);

    const uint32_t a_row16 = lane & 15;
    const uint32_t a_cofs  = (lane >> 4) * 16;
    const uint32_t b_nrow  = (lane & 7) + ((lane >> 4) & 1) * 8;
    const uint32_t b_kofs  = ((lane >> 3) & 1) * 16;

    for (int c = 0; c < 16; c++) {
        const int buf = c & 1;
        if (c + 1 < 16) {
            issue(c + 1, buf ^ 1);
            asm volatile("cp.async.wait_group 1;");
        } else {
            asm volatile("cp.async.wait_group 0;");
        }
        __syncthreads();

        const uint32_t abase = sb + buf * BUF_BYTES;
        const uint32_t bbase = abase + 2 * A_BYTES;

#pragma unroll
        for (int kf = 0; kf < 2; kf++) {
            uint32_t ah[2][4], al[2][4], bh[4][2], bl[4][2];
            const uint32_t kb = kf * 32;
#pragma unroll
            for (int mf = 0; mf < 2; mf++) {
                uint32_t ad = abase + (wm * 32 + mf * 16 + a_row16) * PITCHB
                            + a_cofs + kb;
                ldm_x4(ah[mf], ad);
                ldm_x4(al[mf], ad + A_BYTES);
            }
#pragma unroll
            for (int pr = 0; pr < 2; pr++) {
                uint32_t bd = bbase + (wn * 32 + pr * 16 + b_nrow) * PITCHB
                            + b_kofs + kb;
                uint32_t th[4], tl[4];
                ldm_x4(th, bd);
                ldm_x4(tl, bd + B_BYTES);
                bh[pr * 2 + 0][0] = th[0]; bh[pr * 2 + 0][1] = th[1];
                bh[pr * 2 + 1][0] = th[2]; bh[pr * 2 + 1][1] = th[3];
                bl[pr * 2 + 0][0] = tl[0]; bl[pr * 2 + 0][1] = tl[1];
                bl[pr * 2 + 1][0] = tl[2]; bl[pr * 2 + 1][1] = tl[3];
            }
#pragma unroll
            for (int mf = 0; mf < 2; mf++)
#pragma unroll
                for (int nf = 0; nf < 4; nf++) {
                    mma_bf16(acc[mf][nf], ah[mf], bh[nf]);
                    mma_bf16(acc[mf][nf], ah[mf], bl[nf]);
                    mma_bf16(acc[mf][nf], al[mf], bh[nf]);
                }
        }
        __syncthreads();
    }

#pragma unroll
    for (int mf = 0; mf < 2; mf++) {
#pragma unroll
        for (int nf = 0; nf < 4; nf++) {
            int row = bm + wm * 32 + mf * 16 + gid;
            int col = bn + wn * 32 + nf * 8 + tig * 2;
            float r0, r1, r2, r3;
            uint32_t h0 = pack_hi(acc[mf][nf][0], acc[mf][nf][1], r0, r1);
            uint32_t h1 = pack_hi(acc[mf][nf][2], acc[mf][nf][3], r2, r3);
            *(uint32_t*)&Ch[(size_t)row * N + col] = h0;
            *(uint32_t*)&Ch[(size_t)(row + 8) * N + col] = h1;
            *(uint32_t*)&Cl[(size_t)row * N + col] =
                pack_bf(__float2bfloat16(r0), __float2bfloat16(r1));
            *(uint32_t*)&Cl[(size_t)(row + 8) * N + col] =
                pack_bf(__float2bfloat16(r2), __float2bfloat16(r3));
        }
    }
}

// ---- proj GEMM: exact R7 small kernel (fp32 + bias output path) -------------
__global__ __launch_bounds__(256, 2)
void gemm_tc(const __nv_bfloat16* __restrict__ Ah, const __nv_bfloat16* __restrict__ Al,
             const __nv_bfloat16* __restrict__ Wh, const __nv_bfloat16* __restrict__ Wl,
             const float* __restrict__ bias, float* __restrict__ C,
             int M, int N, int K) {
    extern __shared__ char smem[];
    const uint32_t sb = s2u(smem);
    const int tid = threadIdx.x;
    const int wid = tid >> 5, lane = tid & 31;
    const int gid = lane >> 2, tig = lane & 3;
    const int bm = blockIdx.y * 128, bn = blockIdx.x * 64;
    const int wm = wid & 3, wn = wid >> 2;

    const int arow = tid >> 2;
    const int aseg = tid & 3;

    float acc[2][4][4];
#pragma unroll
    for (int mf = 0; mf < 2; mf++)
#pragma unroll
        for (int nf = 0; nf < 4; nf++)
#pragma unroll
            for (int r = 0; r < 4; r++) acc[mf][nf][r] = 0.f;

    const int nc = K >> 5;

    auto issue = [&](int c, int buf) {
        uint32_t base = sb + buf * BUF_BYTES;
        const int kofs = c * 32 + aseg * 8;
#pragma unroll
        for (int i = 0; i < 2; i++) {
            int row = arow + i * 64;
            uint32_t d = base + row * PITCHB + aseg * 16;
            cp16(d,            Ah + (size_t)(bm + row) * K + kofs);
            cp16(d + A_BYTES,  Al + (size_t)(bm + row) * K + kofs);
        }
        {
            int row = arow;
            uint32_t d = base + 2 * A_BYTES + row * PITCHB + aseg * 16;
            cp16(d,            Wh + (size_t)(bn + row) * K + kofs);
            cp16(d + B_BYTES,  Wl + (size_t)(bn + row) * K + kofs);
        }
        asm volatile("cp.async.commit_group;");
    };

    issue(0, 0);

    const uint32_t a_row16 = lane & 15;
    const uint32_t a_cofs  = (lane >> 4) * 16;
    const uint32_t b_nrow  = (lane & 7) + ((lane >> 4) & 1) * 8;
    const uint32_t b_kofs  = ((lane >> 3) & 1) * 16;

    for (int c = 0; c < nc; c++) {
        const int buf = c & 1;
        if (c + 1 < nc) {
            issue(c + 1, buf ^ 1);
            asm volatile("cp.async.wait_group 1;");
        } else {
            asm volatile("cp.async.wait_group 0;");
        }
        __syncthreads();

        const uint32_t abase = sb + buf * BUF_BYTES;
        const uint32_t bbase = abase + 2 * A_BYTES;

#pragma unroll
        for (int kf = 0; kf < 2; kf++) {
            uint32_t ah[2][4], al[2][4], bh[4][2], bl[4][2];
            const uint32_t kb = kf * 32;
#pragma unroll
            for (int mf = 0; mf < 2; mf++) {
                uint32_t ad = abase + (wm * 32 + mf * 16 + a_row16) * PITCHB
                            + a_cofs + kb;
                ldm_x4(ah[mf], ad);
                ldm_x4(al[mf], ad + A_BYTES);
            }
#pragma unroll
            for (int pr = 0; pr < 2; pr++) {
                uint32_t bd = bbase + (wn * 32 + pr * 16 + b_nrow) * PITCHB
                            + b_kofs + kb;
                uint32_t th[4], tl[4];
                ldm_x4(th, bd);
                ldm_x4(tl, bd + B_BYTES);
                bh[pr * 2 + 0][0] = th[0]; bh[pr * 2 + 0][1] = th[1];
                bh[pr * 2 + 1][0] = th[2]; bh[pr * 2 + 1][1] = th[3];
                bl[pr * 2 + 0][0] = tl[0]; bl[pr * 2 + 0][1] = tl[1];
                bl[pr * 2 + 1][0] = tl[2]; bl[pr * 2 + 1][1] = tl[3];
            }
#pragma unroll
            for (int mf = 0; mf < 2; mf++)
#pragma unroll
                for (int nf = 0; nf < 4; nf++) {
                    mma_bf16(acc[mf][nf], ah[mf], bh[nf]);
                    mma_bf16(acc[mf][nf], ah[mf], bl[nf]);
                    mma_bf16(acc[mf][nf], al[mf], bh[nf]);
                }
        }
        __syncthreads();
    }

#pragma unroll
    for (int mf = 0; mf < 2; mf++) {
#pragma unroll
        for (int nf = 0; nf < 4; nf++) {
            int row = bm + wm * 32 + mf * 16 + gid;
            int col = bn + wn * 32 + nf * 8 + tig * 2;
            float b0 = bias ? bias[col] : 0.f;
            float b1 = bias ? bias[col + 1] : 0.f;
            float2 v0 = make_float2(acc[mf][nf][0] + b0, acc[mf][nf][1] + b1);
            float2 v1 = make_float2(acc[mf][nf][2] + b0, acc[mf][nf][3] + b1);
            *(float2*)&C[(size_t)row * N + col] = v0;
            *(float2*)&C[(size_t)(row + 8) * N + col] = v1;
        }
    }
}

// ---------------- tensor-core flash attention (unchanged, validated) ---------
#define APITCH 144
#define TILE_B 9216
#define QH_OFF 0
#define QL_OFF TILE_B
#define KV_OFF (2 * TILE_B)
#define KVBUF_B (4 * TILE_B)
#define ATTN_SMEM (2 * TILE_B + 2 * KVBUF_B)   // 92160

__global__ __launch_bounds__(128)
void attn_tc(const __nv_bfloat16* __restrict__ qkvh, const __nv_bfloat16* __restrict__ qkvl,
             const __nv_bfloat16* __restrict__ kcth, const __nv_bfloat16* __restrict__ kctl,
             const __nv_bfloat16* __restrict__ vcth, const __nv_bfloat16* __restrict__ vctl,
             __nv_bfloat16* __restrict__ outh, __nv_bfloat16* __restrict__ outl) {
    extern __shared__ char smem[];
    const uint32_t sb = s2u(smem);
    const int t0 = blockIdx.x, h = blockIdx.y, b = blockIdx.z;
    const int tid = threadIdx.x;
    const int w = tid >> 5, lane = tid & 31;
    const int gid = lane >> 2, tig = lane & 3;

    int ids[17], nv = 0;
    for (int t = 0; t < 16; t++)
        if (g_maskn[b * 16 + t] && t != t0 + 4) ids[nv++] = t;
    ids[nv++] = 16;

    const int seg = tid & 7;
    const int r0 = tid >> 3;

    {
        const size_t base = (size_t)(b * 768 + t0 * 64) * 1536 + h * 64 + seg * 8;
#pragma unroll
        for (int i = 0; i < 4; i++) {
            int row = r0 + i * 16;
            uint32_t d = sb + row * APITCH + seg * 16;
            cp16(d + QH_OFF, qkvh + base + (size_t)row * 1536);
            cp16(d + QL_OFF, qkvl + base + (size_t)row * 1536);
        }
    }

    auto issueKV = [&](int id, int buf) {
        const __nv_bfloat16 *ksh, *ksl, *vsh, *vsl;
        size_t kbase, vbase, rs;
        if (id < 16) {
            rs = 512;
            kbase = (size_t)(b * 1024 + id * 64) * 512 + h * 64 + seg * 8;
            vbase = kbase;
            ksh = kcth; ksl = kctl; vsh = vcth; vsl = vctl;
        } else {
            rs = 1536;
            size_t rb = (size_t)(b * 768 + t0 * 64) * 1536 + h * 64 + seg * 8;
            kbase = rb + 512; vbase = rb + 1024;
            ksh = qkvh; ksl = qkvl; vsh = qkvh; vsl = qkvl;
        }
        uint32_t base = sb + KV_OFF + buf * KVBUF_B;
#pragma unroll
        for (int i = 0; i < 4; i++) {
            int row = r0 + i * 16;
            uint32_t d = base + row * APITCH + seg * 16;
            cp16(d,              ksh + kbase + (size_t)row * rs);
            cp16(d + TILE_B,     ksl + kbase + (size_t)row * rs);
            cp16(d + 2 * TILE_B, vsh + vbase + (size_t)row * rs);
            cp16(d + 3 * TILE_B, vsl + vbase + (size_t)row * rs);
        }
        asm volatile("cp.async.commit_group;");
    };

    issueKV(ids[0], 0);

    const uint32_t a_row16 = lane & 15;
    const uint32_t a_cofs  = (lane >> 4) * 16;
    const uint32_t b_nrow  = (lane & 7) + ((lane >> 4) & 1) * 8;
    const uint32_t b_kofs  = ((lane >> 3) & 1) * 16;
    const uint32_t v_krow = lane & 15;
    const uint32_t v_dofs = (lane >> 4) * 16;

    uint32_t qh[4][4], ql[4][4];
    float of[8][4];
#pragma unroll
    for (int f = 0; f < 8; f++)
#pragma unroll
        for (int r = 0; r < 4; r++) of[f][r] = 0.f;
    float m1 = -INFINITY, m2 = -INFINITY, l1 = 0.f, l2 = 0.f;

    for (int i = 0; i < nv; i++) {
        if (i + 1 < nv) {
            issueKV(ids[i + 1], (i + 1) & 1);
            asm volatile("cp.async.wait_group 1;");
        } else {
            asm volatile("cp.async.wait_group 0;");
        }
        __syncthreads();

        if (i == 0) {
#pragma unroll
            for (int kf = 0; kf < 4; kf++) {
                uint32_t ad = sb + (w * 16 + a_row16) * APITCH + a_cofs + kf * 32;
                ldm_x4(qh[kf], ad + QH_OFF);
                ldm_x4(ql[kf], ad + QL_OFF);
            }
        }

        const uint32_t kvb = sb + KV_OFF + (i & 1) * KVBUF_B;

        float sf[8][4];
#pragma unroll
        for (int f = 0; f < 8; f++)
#pragma unroll
            for (int r = 0; r < 4; r++) sf[f][r] = 0.f;

#pragma unroll
        for (int nfp = 0; nfp < 4; nfp++) {
#pragma unroll
            for (int kf = 0; kf < 4; kf++) {
                uint32_t th[4], tl[4];
                uint32_t kd = kvb + (nfp * 16 + b_nrow) * APITCH + b_kofs + kf * 32;
                ldm_x4(th, kd);
                ldm_x4(tl, kd + TILE_B);
                mma_bf16(sf[nfp * 2 + 0], qh[kf], &th[0]);
                mma_bf16(sf[nfp * 2 + 0], qh[kf], &tl[0]);
                mma_bf16(sf[nfp * 2 + 0], ql[kf], &th[0]);
                mma_bf16(sf[nfp * 2 + 1], qh[kf], &th[2]);
                mma_bf16(sf[nfp * 2 + 1], qh[kf], &tl[2]);
                mma_bf16(sf[nfp * 2 + 1], ql[kf], &th[2]);
            }
        }

        float cm1 = -INFINITY, cm2 = -INFINITY;
#pragma unroll
        for (int f = 0; f < 8; f++) {
            sf[f][0] *= 0.125f; sf[f][1] *= 0.125f;
            sf[f][2] *= 0.125f; sf[f][3] *= 0.125f;
            cm1 = fmaxf(cm1, fmaxf(sf[f][0], sf[f][1]));
            cm2 = fmaxf(cm2, fmaxf(sf[f][2], sf[f][3]));
        }
        cm1 = fmaxf(cm1, __shfl_xor_sync(0xffffffffu, cm1, 1));
        cm1 = fmaxf(cm1, __shfl_xor_sync(0xffffffffu, cm1, 2));
        cm2 = fmaxf(cm2, __shfl_xor_sync(0xffffffffu, cm2, 1));
        cm2 = fmaxf(cm2, __shfl_xor_sync(0xffffffffu, cm2, 2));
        float mn1 = fmaxf(m1, cm1), mn2 = fmaxf(m2, cm2);
        float f1 = __expf(m1 - mn1), f2 = __expf(m2 - mn2);
        float rs1 = 0.f, rs2 = 0.f;
#pragma unroll
        for (int f = 0; f < 8; f++) {
            sf[f][0] = __expf(sf[f][0] - mn1);
            sf[f][1] = __expf(sf[f][1] - mn1);
            sf[f][2] = __expf(sf[f][2] - mn2);
            sf[f][3] = __expf(sf[f][3] - mn2);
            rs1 += sf[f][0] + sf[f][1];
            rs2 += sf[f][2] + sf[f][3];
        }
        rs1 += __shfl_xor_sync(0xffffffffu, rs1, 1);
        rs1 += __shfl_xor_sync(0xffffffffu, rs1, 2);
        rs2 += __shfl_xor_sync(0xffffffffu, rs2, 1);
        rs2 += __shfl_xor_sync(0xffffffffu, rs2, 2);
        l1 = l1 * f1 + rs1; l2 = l2 * f2 + rs2;
        m1 = mn1; m2 = mn2;
#pragma unroll
        for (int f = 0; f < 8; f++) {
            of[f][0] *= f1; of[f][1] *= f1;
            of[f][2] *= f2; of[f][3] *= f2;
        }

        uint32_t ph[4][4], pl[4][4];
#pragma unroll
        for (int kf = 0; kf < 4; kf++) {
            float r0a, r1a, r2a, r3a;
            ph[kf][0] = pack_hi(sf[2 * kf][0], sf[2 * kf][1], r0a, r1a);
            pl[kf][0] = pack_bf(__float2bfloat16(r0a), __float2bfloat16(r1a));
            ph[kf][1] = pack_hi(sf[2 * kf][2], sf[2 * kf][3], r0a, r1a);
            pl[kf][1] = pack_bf(__float2bfloat16(r0a), __float2bfloat16(r1a));
            ph[kf][2] = pack_hi(sf[2 * kf + 1][0], sf[2 * kf + 1][1], r2a, r3a);
            pl[kf][2] = pack_bf(__float2bfloat16(r2a), __float2bfloat16(r3a));
            ph[kf][3] = pack_hi(sf[2 * kf + 1][2], sf[2 * kf + 1][3], r2a, r3a);
            pl[kf][3] = pack_bf(__float2bfloat16(r2a), __float2bfloat16(r3a));
        }

        const uint32_t vb = kvb + 2 * TILE_B;
#pragma unroll
        for (int nfp = 0; nfp < 4; nfp++) {
#pragma unroll
            for (int kf = 0; kf < 4; kf++) {
                uint32_t vh_[4], vl_[4];
                uint32_t vd = vb + (kf * 16 + v_krow) * APITCH + nfp * 32 + v_dofs;
                ldm_x4t(vh_, vd);
                ldm_x4t(vl_, vd + TILE_B);
                mma_bf16(of[nfp * 2 + 0], ph[kf], &vh_[0]);
                mma_bf16(of[nfp * 2 + 0], ph[kf], &vl_[0]);
                mma_bf16(of[nfp * 2 + 0], pl[kf], &vh_[0]);
                mma_bf16(of[nfp * 2 + 1], ph[kf], &vh_[2]);
                mma_bf16(of[nfp * 2 + 1], ph[kf], &vl_[2]);
                mma_bf16(of[nfp * 2 + 1], pl[kf], &vh_[2]);
            }
        }
        __syncthreads();
    }

    const float inv1 = 1.0f / l1, inv2 = 1.0f / l2;
    const size_t row1 = (size_t)(b * 768 + t0 * 64 + w * 16 + gid);
    const size_t row2 = row1 + 8;
#pragma unroll
    for (int nf = 0; nf < 8; nf++) {
        int col = h * 64 + nf * 8 + tig * 2;
        float r0a, r1a;
        uint32_t h0 = pack_hi(of[nf][0] * inv1, of[nf][1] * inv1, r0a, r1a);
        *(uint32_t*)&outh[row1 * 512 + col] = h0;
        *(uint32_t*)&outl[row1 * 512 + col] =
            pack_bf(__float2bfloat16(r0a), __float2bfloat16(r1a));
        uint32_t h1 = pack_hi(of[nf][2] * inv2, of[nf][3] * inv2, r0a, r1a);
        *(uint32_t*)&outh[row2 * 512 + col] = h1;
        *(uint32_t*)&outl[row2 * 512 + col] =
            pack_bf(__float2bfloat16(r0a), __float2bfloat16(r1a));
    }
}

// ---------------- launcher ---------------------------------------------------
extern "C" void kernel_launch(void* const* d_in, const int* in_sizes, int n_in,
                              void* d_out, int out_size) {
    const float* x      = (const float*)d_in[0];
    const float* x_ctx  = (const float*)d_in[1];
    const float* dx_ctx = (const float*)d_in[2];
    const unsigned char* mask = (const unsigned char*)d_in[3];
    const float* qkv_w  = (const float*)d_in[4];
    const float* k_w    = (const float*)d_in[5];
    const float* v_w    = (const float*)d_in[6];
    const float* proj_w = (const float*)d_in[7];
    const float* proj_b = (const float*)d_in[8];
    float* out = (float*)d_out;

    __nv_bfloat16 *xh, *xl, *xch, *xcl, *dxh, *dxl, *qwh, *qwl,
                  *kwh, *kwl, *vwh, *vwl, *pwh, *pwl, *ah, *al,
                  *qkvh, *qkvl, *kcth, *kctl, *vcth, *vctl;
    cudaGetSymbolAddress((void**)&xh,  g_xh);  cudaGetSymbolAddress((void**)&xl,  g_xl);
    cudaGetSymbolAddress((void**)&xch, g_xch); cudaGetSymbolAddress((void**)&xcl, g_xcl);
    cudaGetSymbolAddress((void**)&dxh, g_dxh); cudaGetSymbolAddress((void**)&dxl, g_dxl);
    cudaGetSymbolAddress((void**)&qwh, g_qwh); cudaGetSymbolAddress((void**)&qwl, g_qwl);
    cudaGetSymbolAddress((void**)&kwh, g_kwh); cudaGetSymbolAddress((void**)&kwl, g_kwl);
    cudaGetSymbolAddress((void**)&vwh, g_vwh); cudaGetSymbolAddress((void**)&vwl, g_vwl);
    cudaGetSymbolAddress((void**)&pwh, g_pwh); cudaGetSymbolAddress((void**)&pwl, g_pwl);
    cudaGetSymbolAddress((void**)&ah,  g_ah);  cudaGetSymbolAddress((void**)&al,  g_al);
    cudaGetSymbolAddress((void**)&qkvh, g_qkvh); cudaGetSymbolAddress((void**)&qkvl, g_qkvl);
    cudaGetSymbolAddress((void**)&kcth, g_kcth); cudaGetSymbolAddress((void**)&kctl, g_kctl);
    cudaGetSymbolAddress((void**)&vcth, g_vcth); cudaGetSymbolAddress((void**)&vctl, g_vctl);

    cudaFuncSetAttribute(gemm3_fused, cudaFuncAttributeMaxDynamicSharedMemorySize, SGEMM_SMEM);
    cudaFuncSetAttribute(gemm_tc,     cudaFuncAttributeMaxDynamicSharedMemorySize, SGEMM_SMEM);
    cudaFuncSetAttribute(attn_tc,     cudaFuncAttributeMaxDynamicSharedMemorySize, ATTN_SMEM);

    // 1: mask
    normalize_mask_kernel<<<1, 64>>>(mask);

    // 2: all input splits in ONE launch (R7 structure)
    SplitArgs sa;
    sa.src[0] = (const float4*)x;      sa.hi[0] = (uint2*)xh;  sa.lo[0] = (uint2*)xl;  sa.n4[0] = 3072 * 512 / 4;
    sa.src[1] = (const float4*)x_ctx;  sa.hi[1] = (uint2*)xch; sa.lo[1] = (uint2*)xcl; sa.n4[1] = 4096 * 512 / 4;
    sa.src[2] = (const float4*)dx_ctx; sa.hi[2] = (uint2*)dxh; sa.lo[2] = (uint2*)dxl; sa.n4[2] = 4096 * 512 / 4;
    sa.src[3] = (const float4*)qkv_w;  sa.hi[3] = (uint2*)qwh; sa.lo[3] = (uint2*)qwl; sa.n4[3] = 1536 * 512 / 4;
    sa.src[4] = (const float4*)k_w;    sa.hi[4] = (uint2*)kwh; sa.lo[4] = (uint2*)kwl; sa.n4[4] = 512 * 512 / 4;
    sa.src[5] = (const float4*)v_w;    sa.hi[5] = (uint2*)vwh; sa.lo[5] = (uint2*)vwl; sa.n4[5] = 512 * 512 / 4;
    sa.src[6] = (const float4*)proj_w; sa.hi[6] = (uint2*)pwh; sa.lo[6] = (uint2*)pwl; sa.n4[6] = 512 * 512 / 4;
    split_all<<<dim3(296, 7), 256>>>(sa);

    // 3: qkv + kctx + vctx in ONE fused launch (1088 blocks, proven body)
    Gemm3 g3;
    g3.Ah[0] = xh;  g3.Al[0] = xl;  g3.Wh[0] = qwh; g3.Wl[0] = qwl;
    g3.Ch[0] = qkvh; g3.Cl[0] = qkvl;
    g3.Ah[1] = dxh; g3.Al[1] = dxl; g3.Wh[1] = kwh; g3.Wl[1] = kwl;
    g3.Ch[1] = kcth; g3.Cl[1] = kctl;
    g3.Ah[2] = xch; g3.Al[2] = xcl; g3.Wh[2] = vwh; g3.Wl[2] = vwl;
    g3.Ch[2] = vcth; g3.Cl[2] = vctl;
    gemm3_fused<<<1088, 256, SGEMM_SMEM>>>(g3);

    // 4: tensor-core flash attention -> hi/lo bf16
    attn_tc<<<dim3(12, 8, 4), 128, ATTN_SMEM>>>(
        qkvh, qkvl, kcth, kctl, vcth, vctl, ah, al);

    // 5: final projection + bias -> d_out (fp32)
    gemm_tc<<<dim3(512 / 64, 3072 / 128), 256, SGEMM_SMEM>>>(
        ah, al, pwh, pwl, proj_b, out, 3072, 512, 512);
}

// round 13
// speedup vs baseline: 1.1717x; 1.0796x over previous
#include <cuda_runtime.h>
#include <cuda_bf16.h>
#include <math.h>
#include <stdint.h>

// Problem constants: B=4, T=16, T0=12, L=64, C=512, H=8, hd=64, NUM_SEEDS=4

// ---------------- scratch (static device globals; no allocations) -----------
__device__ int g_maskn[64];                // normalized ctx_mask [b*16 + t]

__device__ __align__(16) __nv_bfloat16 g_xh [3072 * 512], g_xl [3072 * 512];
__device__ __align__(16) __nv_bfloat16 g_xch[4096 * 512], g_xcl[4096 * 512];
__device__ __align__(16) __nv_bfloat16 g_dxh[4096 * 512], g_dxl[4096 * 512];
__device__ __align__(16) __nv_bfloat16 g_qwh[1536 * 512], g_qwl[1536 * 512];
__device__ __align__(16) __nv_bfloat16 g_kwh[ 512 * 512], g_kwl[ 512 * 512];
__device__ __align__(16) __nv_bfloat16 g_vwh[ 512 * 512], g_vwl[ 512 * 512];
__device__ __align__(16) __nv_bfloat16 g_pwh[ 512 * 512], g_pwl[ 512 * 512];
__device__ __align__(16) __nv_bfloat16 g_qkvh[3072 * 1536], g_qkvl[3072 * 1536];
__device__ __align__(16) __nv_bfloat16 g_kcth[4096 * 512],  g_kctl[4096 * 512];
__device__ __align__(16) __nv_bfloat16 g_vcth[4096 * 512],  g_vctl[4096 * 512];
__device__ __align__(16) __nv_bfloat16 g_ah [3072 * 512], g_al [3072 * 512];

// ---------------- helpers ----------------------------------------------------
__device__ __forceinline__ uint32_t s2u(const void* p) {
    uint32_t a;
    asm("{ .reg .u64 t; cvta.to.shared.u64 t, %1; cvt.u32.u64 %0, t; }"
        : "=r"(a) : "l"(p));
    return a;
}
__device__ __forceinline__ void cp16(uint32_t dst, const void* src) {
    asm volatile("cp.async.cg.shared.global [%0], [%1], 16;"
                 :: "r"(dst), "l"(src));
}
__device__ __forceinline__ void ldm_x4(uint32_t* r, uint32_t addr) {
    asm volatile("ldmatrix.sync.aligned.m8n8.x4.shared.b16 {%0,%1,%2,%3}, [%4];"
                 : "=r"(r[0]), "=r"(r[1]), "=r"(r[2]), "=r"(r[3]) : "r"(addr));
}
__device__ __forceinline__ void ldm_x4t(uint32_t* r, uint32_t addr) {
    asm volatile("ldmatrix.sync.aligned.m8n8.x4.trans.shared.b16 {%0,%1,%2,%3}, [%4];"
                 : "=r"(r[0]), "=r"(r[1]), "=r"(r[2]), "=r"(r[3]) : "r"(addr));
}
__device__ __forceinline__ void mma_bf16(float* c, const uint32_t* a, const uint32_t* b) {
    asm volatile(
        "mma.sync.aligned.m16n8k16.row.col.f32.bf16.bf16.f32 "
        "{%0,%1,%2,%3}, {%4,%5,%6,%7}, {%8,%9}, {%0,%1,%2,%3};"
        : "+f"(c[0]), "+f"(c[1]), "+f"(c[2]), "+f"(c[3])
        : "r"(a[0]), "r"(a[1]), "r"(a[2]), "r"(a[3]), "r"(b[0]), "r"(b[1]));
}
__device__ __forceinline__ uint32_t pack_bf(__nv_bfloat16 a, __nv_bfloat16 b) {
    return (uint32_t)__bfloat16_as_ushort(a) | ((uint32_t)__bfloat16_as_ushort(b) << 16);
}
__device__ __forceinline__ uint32_t pack_hi(float x, float y, float& rx, float& ry) {
    __nv_bfloat16 hx = __float2bfloat16(x), hy = __float2bfloat16(y);
    rx = x - __bfloat162float(hx);
    ry = y - __bfloat162float(hy);
    return pack_bf(hx, hy);
}

// ---------------- fused split: fp32 -> hi/lo bf16 (ONE launch, 7 arrays) -----
struct SplitArgs {
    const float4* src[7];
    uint2* hi[7];
    uint2* lo[7];
    int n4[7];
};
__global__ __launch_bounds__(256)
void split_all(SplitArgs a) {
    const int arr = blockIdx.y;
    const int n4 = a.n4[arr];
    const float4* __restrict__ s = a.src[arr];
    uint2* __restrict__ hp = a.hi[arr];
    uint2* __restrict__ lp = a.lo[arr];
    const int step = gridDim.x * 256;
    for (int i = blockIdx.x * 256 + threadIdx.x; i < n4; i += step) {
        float4 v = s[i];
        __nv_bfloat16 h0 = __float2bfloat16(v.x), h1 = __float2bfloat16(v.y);
        __nv_bfloat16 h2 = __float2bfloat16(v.z), h3 = __float2bfloat16(v.w);
        __nv_bfloat16 l0 = __float2bfloat16(v.x - __bfloat162float(h0));
        __nv_bfloat16 l1 = __float2bfloat16(v.y - __bfloat162float(h1));
        __nv_bfloat16 l2 = __float2bfloat16(v.z - __bfloat162float(h2));
        __nv_bfloat16 l3 = __float2bfloat16(v.w - __bfloat162float(h3));
        hp[i] = make_uint2(pack_bf(h0, h1), pack_bf(h2, h3));
        lp[i] = make_uint2(pack_bf(l0, l1), pack_bf(l2, l3));
    }
}

// ---------------- mask normalization (dtype-robust) --------------------------
__global__ void normalize_mask_kernel(const unsigned char* __restrict__ m8) {
    __shared__ int flag;
    int i = threadIdx.x;
    if (i == 0) flag = 0;
    __syncthreads();
    if ((i & 3) != 0 && m8[i] != 0) atomicOr(&flag, 1);
    __syncthreads();
    int v;
    if (flag) v = (m8[i] != 0) ? 1 : 0;
    else      v = (((const int*)m8)[i] != 0) ? 1 : 0;
    g_maskn[i] = v;
}

// ======== SMALL GEMM body (128x64, BK=64, 2-stage, 2 CTA/SM) ================
// K chunk = 64 (128 bytes/row): halves the barrier count vs BK=32.
#define GPITCH 144                       // 128B row + 16B pad (36 words, conflict-free)
#define GA_B (128 * GPITCH)              // 18432 per A term
#define GB_B (64 * GPITCH)               // 9216 per B term
#define GBUF (2 * GA_B + 2 * GB_B)       // 55296 per stage
#define SGEMM_SMEM (2 * GBUF)            // 110592

// ---- fused qkv + kctx + vctx: one launch, 1088 blocks -----------------------
// blocks [0,576): qkv (24 n-tiles x 24 m-tiles, N=1536)
// blocks [576,832): kctx (8 x 32, N=512); [832,1088): vctx (8 x 32, N=512)
struct Gemm3 {
    const __nv_bfloat16* Ah[3];
    const __nv_bfloat16* Al[3];
    const __nv_bfloat16* Wh[3];
    const __nv_bfloat16* Wl[3];
    __nv_bfloat16* Ch[3];
    __nv_bfloat16* Cl[3];
};

__global__ __launch_bounds__(256, 2)
void gemm3_fused(Gemm3 g) {
    const int idx = blockIdx.x;
    const int prob = (idx >= 576) + (idx >= 832);
    const int local = idx - (prob == 0 ? 0 : (prob == 1 ? 576 : 832));
    const int nbx = (prob == 0) ? 24 : 8;
    const int N   = (prob == 0) ? 1536 : 512;
    const int bx = local % nbx, by = local / nbx;

    const __nv_bfloat16* __restrict__ Ah = g.Ah[prob];
    const __nv_bfloat16* __restrict__ Al = g.Al[prob];
    const __nv_bfloat16* __restrict__ Wh = g.Wh[prob];
    const __nv_bfloat16* __restrict__ Wl = g.Wl[prob];
    __nv_bfloat16* __restrict__ Ch = g.Ch[prob];
    __nv_bfloat16* __restrict__ Cl = g.Cl[prob];

    extern __shared__ char smem[];
    const uint32_t sb = s2u(smem);
    const int tid = threadIdx.x;
    const int wid = tid >> 5, lane = tid & 31;
    const int gid = lane >> 2, tig = lane & 3;
    const int bm = by * 128, bn = bx * 64;
    const int wm = wid & 3, wn = wid >> 2;

    const int lrow = tid >> 3;       // 0..31 step for loads
    const int lseg = tid & 7;        // 16B segment within 128B row

    float acc[2][4][4];
#pragma unroll
    for (int mf = 0; mf < 2; mf++)
#pragma unroll
        for (int nf = 0; nf < 4; nf++)
#pragma unroll
            for (int r = 0; r < 4; r++) acc[mf][nf][r] = 0.f;

    auto issue = [&](int c, int buf) {
        uint32_t base = sb + buf * GBUF;
        const int kofs = c * 64 + lseg * 8;
#pragma unroll
        for (int i = 0; i < 4; i++) {
            int row = lrow + i * 32;    // 0..127
            uint32_t d = base + row * GPITCH + lseg * 16;
            cp16(d,         Ah + (size_t)(bm + row) * 512 + kofs);
            cp16(d + GA_B,  Al + (size_t)(bm + row) * 512 + kofs);
        }
#pragma unroll
        for (int i = 0; i < 2; i++) {
            int row = lrow + i * 32;    // 0..63
            uint32_t d = base + 2 * GA_B + row * GPITCH + lseg * 16;
            cp16(d,         Wh + (size_t)(bn + row) * 512 + kofs);
            cp16(d + GB_B,  Wl + (size_t)(bn + row) * 512 + kofs);
        }
        asm volatile("cp.async.commit_group;");
    };

    issue(0, 0);

    const uint32_t a_row16 = lane & 15;
    const uint32_t a_cofs  = (lane >> 4) * 16;
    const uint32_t b_nrow  = (lane & 7) + ((lane >> 4) & 1) * 8;
    const uint32_t b_kofs  = ((lane >> 3) & 1) * 16;

    for (int c = 0; c < 8; c++) {
        const int buf = c & 1;
        if (c + 1 < 8) {
            issue(c + 1, buf ^ 1);
            asm volatile("cp.async.wait_group 1;");
        } else {
            asm volatile("cp.async.wait_group 0;");
        }
        __syncthreads();

        const uint32_t abase = sb + buf * GBUF;
        const uint32_t bbase = abase + 2 * GA_B;

#pragma unroll
        for (int kf = 0; kf < 4; kf++) {
            uint32_t ah[2][4], al[2][4], bh[4][2], bl[4][2];
            const uint32_t kb = kf * 32;
#pragma unroll
            for (int mf = 0; mf < 2; mf++) {
                uint32_t ad = abase + (wm * 32 + mf * 16 + a_row16) * GPITCH
                            + a_cofs + kb;
                ldm_x4(ah[mf], ad);
                ldm_x4(al[mf], ad + GA_B);
            }
#pragma unroll
            for (int pr = 0; pr < 2; pr++) {
                uint32_t bd = bbase + (wn * 32 + pr * 16 + b_nrow) * GPITCH
                            + b_kofs + kb;
                uint32_t th[4], tl[4];
                ldm_x4(th, bd);
                ldm_x4(tl, bd + GB_B);
                bh[pr * 2 + 0][0] = th[0]; bh[pr * 2 + 0][1] = th[1];
                bh[pr * 2 + 1][0] = th[2]; bh[pr * 2 + 1][1] = th[3];
                bl[pr * 2 + 0][0] = tl[0]; bl[pr * 2 + 0][1] = tl[1];
                bl[pr * 2 + 1][0] = tl[2]; bl[pr * 2 + 1][1] = tl[3];
            }
#pragma unroll
            for (int mf = 0; mf < 2; mf++)
#pragma unroll
                for (int nf = 0; nf < 4; nf++) {
                    mma_bf16(acc[mf][nf], ah[mf], bh[nf]);
                    mma_bf16(acc[mf][nf], ah[mf], bl[nf]);
                    mma_bf16(acc[mf][nf], al[mf], bh[nf]);
                }
        }
        __syncthreads();
    }

#pragma unroll
    for (int mf = 0; mf < 2; mf++) {
#pragma unroll
        for (int nf = 0; nf < 4; nf++) {
            int row = bm + wm * 32 + mf * 16 + gid;
            int col = bn + wn * 32 + nf * 8 + tig * 2;
            float r0, r1, r2, r3;
            uint32_t h0 = pack_hi(acc[mf][nf][0], acc[mf][nf][1], r0, r1);
            uint32_t h1 = pack_hi(acc[mf][nf][2], acc[mf][nf][3], r2, r3);
            *(uint32_t*)&Ch[(size_t)row * N + col] = h0;
            *(uint32_t*)&Ch[(size_t)(row + 8) * N + col] = h1;
            *(uint32_t*)&Cl[(size_t)row * N + col] =
                pack_bf(__float2bfloat16(r0), __float2bfloat16(r1));
            *(uint32_t*)&Cl[(size_t)(row + 8) * N + col] =
                pack_bf(__float2bfloat16(r2), __float2bfloat16(r3));
        }
    }
}

// ---- proj GEMM: same BK=64 body, fp32 + bias output path --------------------
__global__ __launch_bounds__(256, 2)
void gemm_tc(const __nv_bfloat16* __restrict__ Ah, const __nv_bfloat16* __restrict__ Al,
             const __nv_bfloat16* __restrict__ Wh, const __nv_bfloat16* __restrict__ Wl,
             const float* __restrict__ bias, float* __restrict__ C,
             int M, int N, int K) {
    extern __shared__ char smem[];
    const uint32_t sb = s2u(smem);
    const int tid = threadIdx.x;
    const int wid = tid >> 5, lane = tid & 31;
    const int gid = lane >> 2, tig = lane & 3;
    const int bm = blockIdx.y * 128, bn = blockIdx.x * 64;
    const int wm = wid & 3, wn = wid >> 2;

    const int lrow = tid >> 3;
    const int lseg = tid & 7;

    float acc[2][4][4];
#pragma unroll
    for (int mf = 0; mf < 2; mf++)
#pragma unroll
        for (int nf = 0; nf < 4; nf++)
#pragma unroll
            for (int r = 0; r < 4; r++) acc[mf][nf][r] = 0.f;

    const int nc = K >> 6;

    auto issue = [&](int c, int buf) {
        uint32_t base = sb + buf * GBUF;
        const int kofs = c * 64 + lseg * 8;
#pragma unroll
        for (int i = 0; i < 4; i++) {
            int row = lrow + i * 32;
            uint32_t d = base + row * GPITCH + lseg * 16;
            cp16(d,         Ah + (size_t)(bm + row) * K + kofs);
            cp16(d + GA_B,  Al + (size_t)(bm + row) * K + kofs);
        }
#pragma unroll
        for (int i = 0; i < 2; i++) {
            int row = lrow + i * 32;
            uint32_t d = base + 2 * GA_B + row * GPITCH + lseg * 16;
            cp16(d,         Wh + (size_t)(bn + row) * K + kofs);
            cp16(d + GB_B,  Wl + (size_t)(bn + row) * K + kofs);
        }
        asm volatile("cp.async.commit_group;");
    };

    issue(0, 0);

    const uint32_t a_row16 = lane & 15;
    const uint32_t a_cofs  = (lane >> 4) * 16;
    const uint32_t b_nrow  = (lane & 7) + ((lane >> 4) & 1) * 8;
    const uint32_t b_kofs  = ((lane >> 3) & 1) * 16;

    for (int c = 0; c < nc; c++) {
        const int buf = c & 1;
        if (c + 1 < nc) {
            issue(c + 1, buf ^ 1);
            asm volatile("cp.async.wait_group 1;");
        } else {
            asm volatile("cp.async.wait_group 0;");
        }
        __syncthreads();

        const uint32_t abase = sb + buf * GBUF;
        const uint32_t bbase = abase + 2 * GA_B;

#pragma unroll
        for (int kf = 0; kf < 4; kf++) {
            uint32_t ah[2][4], al[2][4], bh[4][2], bl[4][2];
            const uint32_t kb = kf * 32;
#pragma unroll
            for (int mf = 0; mf < 2; mf++) {
                uint32_t ad = abase + (wm * 32 + mf * 16 + a_row16) * GPITCH
                            + a_cofs + kb;
                ldm_x4(ah[mf], ad);
                ldm_x4(al[mf], ad + GA_B);
            }
#pragma unroll
            for (int pr = 0; pr < 2; pr++) {
                uint32_t bd = bbase + (wn * 32 + pr * 16 + b_nrow) * GPITCH
                            + b_kofs + kb;
                uint32_t th[4], tl[4];
                ldm_x4(th, bd);
                ldm_x4(tl, bd + GB_B);
                bh[pr * 2 + 0][0] = th[0]; bh[pr * 2 + 0][1] = th[1];
                bh[pr * 2 + 1][0] = th[2]; bh[pr * 2 + 1][1] = th[3];
                bl[pr * 2 + 0][0] = tl[0]; bl[pr * 2 + 0][1] = tl[1];
                bl[pr * 2 + 1][0] = tl[2]; bl[pr * 2 + 1][1] = tl[3];
            }
#pragma unroll
            for (int mf = 0; mf < 2; mf++)
#pragma unroll
                for (int nf = 0; nf < 4; nf++) {
                    mma_bf16(acc[mf][nf], ah[mf], bh[nf]);
                    mma_bf16(acc[mf][nf], ah[mf], bl[nf]);
                    mma_bf16(acc[mf][nf], al[mf], bh[nf]);
                }
        }
        __syncthreads();
    }

#pragma unroll
    for (int mf = 0; mf < 2; mf++) {
#pragma unroll
        for (int nf = 0; nf < 4; nf++) {
            int row = bm + wm * 32 + mf * 16 + gid;
            int col = bn + wn * 32 + nf * 8 + tig * 2;
            float b0 = bias ? bias[col] : 0.f;
            float b1 = bias ? bias[col + 1] : 0.f;
            float2 v0 = make_float2(acc[mf][nf][0] + b0, acc[mf][nf][1] + b1);
            float2 v1 = make_float2(acc[mf][nf][2] + b0, acc[mf][nf][3] + b1);
            *(float2*)&C[(size_t)row * N + col] = v0;
            *(float2*)&C[(size_t)(row + 8) * N + col] = v1;
        }
    }
}

// ---------------- tensor-core flash attention (unchanged, validated) ---------
#define APITCH 144
#define TILE_B 9216
#define QH_OFF 0
#define QL_OFF TILE_B
#define KV_OFF (2 * TILE_B)
#define KVBUF_B (4 * TILE_B)
#define ATTN_SMEM (2 * TILE_B + 2 * KVBUF_B)   // 92160

__global__ __launch_bounds__(128)
void attn_tc(const __nv_bfloat16* __restrict__ qkvh, const __nv_bfloat16* __restrict__ qkvl,
             const __nv_bfloat16* __restrict__ kcth, const __nv_bfloat16* __restrict__ kctl,
             const __nv_bfloat16* __restrict__ vcth, const __nv_bfloat16* __restrict__ vctl,
             __nv_bfloat16* __restrict__ outh, __nv_bfloat16* __restrict__ outl) {
    extern __shared__ char smem[];
    const uint32_t sb = s2u(smem);
    const int t0 = blockIdx.x, h = blockIdx.y, b = blockIdx.z;
    const int tid = threadIdx.x;
    const int w = tid >> 5, lane = tid & 31;
    const int gid = lane >> 2, tig = lane & 3;

    int ids[17], nv = 0;
    for (int t = 0; t < 16; t++)
        if (g_maskn[b * 16 + t] && t != t0 + 4) ids[nv++] = t;
    ids[nv++] = 16;

    const int seg = tid & 7;
    const int r0 = tid >> 3;

    {
        const size_t base = (size_t)(b * 768 + t0 * 64) * 1536 + h * 64 + seg * 8;
#pragma unroll
        for (int i = 0; i < 4; i++) {
            int row = r0 + i * 16;
            uint32_t d = sb + row * APITCH + seg * 16;
            cp16(d + QH_OFF, qkvh + base + (size_t)row * 1536);
            cp16(d + QL_OFF, qkvl + base + (size_t)row * 1536);
        }
    }

    auto issueKV = [&](int id, int buf) {
        const __nv_bfloat16 *ksh, *ksl, *vsh, *vsl;
        size_t kbase, vbase, rs;
        if (id < 16) {
            rs = 512;
            kbase = (size_t)(b * 1024 + id * 64) * 512 + h * 64 + seg * 8;
            vbase = kbase;
            ksh = kcth; ksl = kctl; vsh = vcth; vsl = vctl;
        } else {
            rs = 1536;
            size_t rb = (size_t)(b * 768 + t0 * 64) * 1536 + h * 64 + seg * 8;
            kbase = rb + 512; vbase = rb + 1024;
            ksh = qkvh; ksl = qkvl; vsh = qkvh; vsl = qkvl;
        }
        uint32_t base = sb + KV_OFF + buf * KVBUF_B;
#pragma unroll
        for (int i = 0; i < 4; i++) {
            int row = r0 + i * 16;
            uint32_t d = base + row * APITCH + seg * 16;
            cp16(d,              ksh + kbase + (size_t)row * rs);
            cp16(d + TILE_B,     ksl + kbase + (size_t)row * rs);
            cp16(d + 2 * TILE_B, vsh + vbase + (size_t)row * rs);
            cp16(d + 3 * TILE_B, vsl + vbase + (size_t)row * rs);
        }
        asm volatile("cp.async.commit_group;");
    };

    issueKV(ids[0], 0);

    const uint32_t a_row16 = lane & 15;
    const uint32_t a_cofs  = (lane >> 4) * 16;
    const uint32_t b_nrow  = (lane & 7) + ((lane >> 4) & 1) * 8;
    const uint32_t b_kofs  = ((lane >> 3) & 1) * 16;
    const uint32_t v_krow = lane & 15;
    const uint32_t v_dofs = (lane >> 4) * 16;

    uint32_t qh[4][4], ql[4][4];
    float of[8][4];
#pragma unroll
    for (int f = 0; f < 8; f++)
#pragma unroll
        for (int r = 0; r < 4; r++) of[f][r] = 0.f;
    float m1 = -INFINITY, m2 = -INFINITY, l1 = 0.f, l2 = 0.f;

    for (int i = 0; i < nv; i++) {
        if (i + 1 < nv) {
            issueKV(ids[i + 1], (i + 1) & 1);
            asm volatile("cp.async.wait_group 1;");
        } else {
            asm volatile("cp.async.wait_group 0;");
        }
        __syncthreads();

        if (i == 0) {
#pragma unroll
            for (int kf = 0; kf < 4; kf++) {
                uint32_t ad = sb + (w * 16 + a_row16) * APITCH + a_cofs + kf * 32;
                ldm_x4(qh[kf], ad + QH_OFF);
                ldm_x4(ql[kf], ad + QL_OFF);
            }
        }

        const uint32_t kvb = sb + KV_OFF + (i & 1) * KVBUF_B;

        float sf[8][4];
#pragma unroll
        for (int f = 0; f < 8; f++)
#pragma unroll
            for (int r = 0; r < 4; r++) sf[f][r] = 0.f;

#pragma unroll
        for (int nfp = 0; nfp < 4; nfp++) {
#pragma unroll
            for (int kf = 0; kf < 4; kf++) {
                uint32_t th[4], tl[4];
                uint32_t kd = kvb + (nfp * 16 + b_nrow) * APITCH + b_kofs + kf * 32;
                ldm_x4(th, kd);
                ldm_x4(tl, kd + TILE_B);
                mma_bf16(sf[nfp * 2 + 0], qh[kf], &th[0]);
                mma_bf16(sf[nfp * 2 + 0], qh[kf], &tl[0]);
                mma_bf16(sf[nfp * 2 + 0], ql[kf], &th[0]);
                mma_bf16(sf[nfp * 2 + 1], qh[kf], &th[2]);
                mma_bf16(sf[nfp * 2 + 1], qh[kf], &tl[2]);
                mma_bf16(sf[nfp * 2 + 1], ql[kf], &th[2]);
            }
        }

        float cm1 = -INFINITY, cm2 = -INFINITY;
#pragma unroll
        for (int f = 0; f < 8; f++) {
            sf[f][0] *= 0.125f; sf[f][1] *= 0.125f;
            sf[f][2] *= 0.125f; sf[f][3] *= 0.125f;
            cm1 = fmaxf(cm1, fmaxf(sf[f][0], sf[f][1]));
            cm2 = fmaxf(cm2, fmaxf(sf[f][2], sf[f][3]));
        }
        cm1 = fmaxf(cm1, __shfl_xor_sync(0xffffffffu, cm1, 1));
        cm1 = fmaxf(cm1, __shfl_xor_sync(0xffffffffu, cm1, 2));
        cm2 = fmaxf(cm2, __shfl_xor_sync(0xffffffffu, cm2, 1));
        cm2 = fmaxf(cm2, __shfl_xor_sync(0xffffffffu, cm2, 2));
        float mn1 = fmaxf(m1, cm1), mn2 = fmaxf(m2, cm2);
        float f1 = __expf(m1 - mn1), f2 = __expf(m2 - mn2);
        float rs1 = 0.f, rs2 = 0.f;
#pragma unroll
        for (int f = 0; f < 8; f++) {
            sf[f][0] = __expf(sf[f][0] - mn1);
            sf[f][1] = __expf(sf[f][1] - mn1);
            sf[f][2] = __expf(sf[f][2] - mn2);
            sf[f][3] = __expf(sf[f][3] - mn2);
            rs1 += sf[f][0] + sf[f][1];
            rs2 += sf[f][2] + sf[f][3];
        }
        rs1 += __shfl_xor_sync(0xffffffffu, rs1, 1);
        rs1 += __shfl_xor_sync(0xffffffffu, rs1, 2);
        rs2 += __shfl_xor_sync(0xffffffffu, rs2, 1);
        rs2 += __shfl_xor_sync(0xffffffffu, rs2, 2);
        l1 = l1 * f1 + rs1; l2 = l2 * f2 + rs2;
        m1 = mn1; m2 = mn2;
#pragma unroll
        for (int f = 0; f < 8; f++) {
            of[f][0] *= f1; of[f][1] *= f1;
            of[f][2] *= f2; of[f][3] *= f2;
        }

        uint32_t ph[4][4], pl[4][4];
#pragma unroll
        for (int kf = 0; kf < 4; kf++) {
            float r0a, r1a, r2a, r3a;
            ph[kf][0] = pack_hi(sf[2 * kf][0], sf[2 * kf][1], r0a, r1a);
            pl[kf][0] = pack_bf(__float2bfloat16(r0a), __float2bfloat16(r1a));
            ph[kf][1] = pack_hi(sf[2 * kf][2], sf[2 * kf][3], r0a, r1a);
            pl[kf][1] = pack_bf(__float2bfloat16(r0a), __float2bfloat16(r1a));
            ph[kf][2] = pack_hi(sf[2 * kf + 1][0], sf[2 * kf + 1][1], r2a, r3a);
            pl[kf][2] = pack_bf(__float2bfloat16(r2a), __float2bfloat16(r3a));
            ph[kf][3] = pack_hi(sf[2 * kf + 1][2], sf[2 * kf + 1][3], r2a, r3a);
            pl[kf][3] = pack_bf(__float2bfloat16(r2a), __float2bfloat16(r3a));
        }

        const uint32_t vb = kvb + 2 * TILE_B;
#pragma unroll
        for (int nfp = 0; nfp < 4; nfp++) {
#pragma unroll
            for (int kf = 0; kf < 4; kf++) {
                uint32_t vh_[4], vl_[4];
                uint32_t vd = vb + (kf * 16 + v_krow) * APITCH + nfp * 32 + v_dofs;
                ldm_x4t(vh_, vd);
                ldm_x4t(vl_, vd + TILE_B);
                mma_bf16(of[nfp * 2 + 0], ph[kf], &vh_[0]);
                mma_bf16(of[nfp * 2 + 0], ph[kf], &vl_[0]);
                mma_bf16(of[nfp * 2 + 0], pl[kf], &vh_[0]);
                mma_bf16(of[nfp * 2 + 1], ph[kf], &vh_[2]);
                mma_bf16(of[nfp * 2 + 1], ph[kf], &vl_[2]);
                mma_bf16(of[nfp * 2 + 1], pl[kf], &vh_[2]);
            }
        }
        __syncthreads();
    }

    const float inv1 = 1.0f / l1, inv2 = 1.0f / l2;
    const size_t row1 = (size_t)(b * 768 + t0 * 64 + w * 16 + gid);
    const size_t row2 = row1 + 8;
#pragma unroll
    for (int nf = 0; nf < 8; nf++) {
        int col = h * 64 + nf * 8 + tig * 2;
        float r0a, r1a;
        uint32_t h0 = pack_hi(of[nf][0] * inv1, of[nf][1] * inv1, r0a, r1a);
        *(uint32_t*)&outh[row1 * 512 + col] = h0;
        *(uint32_t*)&outl[row1 * 512 + col] =
            pack_bf(__float2bfloat16(r0a), __float2bfloat16(r1a));
        uint32_t h1 = pack_hi(of[nf][2] * inv2, of[nf][3] * inv2, r0a, r1a);
        *(uint32_t*)&outh[row2 * 512 + col] = h1;
        *(uint32_t*)&outl[row2 * 512 + col] =
            pack_bf(__float2bfloat16(r0a), __float2bfloat16(r1a));
    }
}

// ---------------- launcher ---------------------------------------------------
extern "C" void kernel_launch(void* const* d_in, const int* in_sizes, int n_in,
                              void* d_out, int out_size) {
    const float* x      = (const float*)d_in[0];
    const float* x_ctx  = (const float*)d_in[1];
    const float* dx_ctx = (const float*)d_in[2];
    const unsigned char* mask = (const unsigned char*)d_in[3];
    const float* qkv_w  = (const float*)d_in[4];
    const float* k_w    = (const float*)d_in[5];
    const float* v_w    = (const float*)d_in[6];
    const float* proj_w = (const float*)d_in[7];
    const float* proj_b = (const float*)d_in[8];
    float* out = (float*)d_out;

    __nv_bfloat16 *xh, *xl, *xch, *xcl, *dxh, *dxl, *qwh, *qwl,
                  *kwh, *kwl, *vwh, *vwl, *pwh, *pwl, *ah, *al,
                  *qkvh, *qkvl, *kcth, *kctl, *vcth, *vctl;
    cudaGetSymbolAddress((void**)&xh,  g_xh);  cudaGetSymbolAddress((void**)&xl,  g_xl);
    cudaGetSymbolAddress((void**)&xch, g_xch); cudaGetSymbolAddress((void**)&xcl, g_xcl);
    cudaGetSymbolAddress((void**)&dxh, g_dxh); cudaGetSymbolAddress((void**)&dxl, g_dxl);
    cudaGetSymbolAddress((void**)&qwh, g_qwh); cudaGetSymbolAddress((void**)&qwl, g_qwl);
    cudaGetSymbolAddress((void**)&kwh, g_kwh); cudaGetSymbolAddress((void**)&kwl, g_kwl);
    cudaGetSymbolAddress((void**)&vwh, g_vwh); cudaGetSymbolAddress((void**)&vwl, g_vwl);
    cudaGetSymbolAddress((void**)&pwh, g_pwh); cudaGetSymbolAddress((void**)&pwl, g_pwl);
    cudaGetSymbolAddress((void**)&ah,  g_ah);  cudaGetSymbolAddress((void**)&al,  g_al);
    cudaGetSymbolAddress((void**)&qkvh, g_qkvh); cudaGetSymbolAddress((void**)&qkvl, g_qkvl);
    cudaGetSymbolAddress((void**)&kcth, g_kcth); cudaGetSymbolAddress((void**)&kctl, g_kctl);
    cudaGetSymbolAddress((void**)&vcth, g_vcth); cudaGetSymbolAddress((void**)&vctl, g_vctl);

    cudaFuncSetAttribute(gemm3_fused, cudaFuncAttributeMaxDynamicSharedMemorySize, SGEMM_SMEM);
    cudaFuncSetAttribute(gemm_tc,     cudaFuncAttributeMaxDynamicSharedMemorySize, SGEMM_SMEM);
    cudaFuncSetAttribute(attn_tc,     cudaFuncAttributeMaxDynamicSharedMemorySize, ATTN_SMEM);

    // 1: mask
    normalize_mask_kernel<<<1, 64>>>(mask);

    // 2: all input splits in ONE launch
    SplitArgs sa;
    sa.src[0] = (const float4*)x;      sa.hi[0] = (uint2*)xh;  sa.lo[0] = (uint2*)xl;  sa.n4[0] = 3072 * 512 / 4;
    sa.src[1] = (const float4*)x_ctx;  sa.hi[1] = (uint2*)xch; sa.lo[1] = (uint2*)xcl; sa.n4[1] = 4096 * 512 / 4;
    sa.src[2] = (const float4*)dx_ctx; sa.hi[2] = (uint2*)dxh; sa.lo[2] = (uint2*)dxl; sa.n4[2] = 4096 * 512 / 4;
    sa.src[3] = (const float4*)qkv_w;  sa.hi[3] = (uint2*)qwh; sa.lo[3] = (uint2*)qwl; sa.n4[3] = 1536 * 512 / 4;
    sa.src[4] = (const float4*)k_w;    sa.hi[4] = (uint2*)kwh; sa.lo[4] = (uint2*)kwl; sa.n4[4] = 512 * 512 / 4;
    sa.src[5] = (const float4*)v_w;    sa.hi[5] = (uint2*)vwh; sa.lo[5] = (uint2*)vwl; sa.n4[5] = 512 * 512 / 4;
    sa.src[6] = (const float4*)proj_w; sa.hi[6] = (uint2*)pwh; sa.lo[6] = (uint2*)pwl; sa.n4[6] = 512 * 512 / 4;
    split_all<<<dim3(296, 7), 256>>>(sa);

    // 3: qkv + kctx + vctx in ONE fused launch (1088 blocks, BK=64 body)
    Gemm3 g3;
    g3.Ah[0] = xh;  g3.Al[0] = xl;  g3.Wh[0] = qwh; g3.Wl[0] = qwl;
    g3.Ch[0] = qkvh; g3.Cl[0] = qkvl;
    g3.Ah[1] = dxh; g3.Al[1] = dxl; g3.Wh[1] = kwh; g3.Wl[1] = kwl;
    g3.Ch[1] = kcth; g3.Cl[1] = kctl;
    g3.Ah[2] = xch; g3.Al[2] = xcl; g3.Wh[2] = vwh; g3.Wl[2] = vwl;
    g3.Ch[2] = vcth; g3.Cl[2] = vctl;
    gemm3_fused<<<1088, 256, SGEMM_SMEM>>>(g3);

    // 4: tensor-core flash attention -> hi/lo bf16
    attn_tc<<<dim3(12, 8, 4), 128, ATTN_SMEM>>>(
        qkvh, qkvl, kcth, kctl, vcth, vctl, ah, al);

    // 5: final projection + bias -> d_out (fp32)
    gemm_tc<<<dim3(512 / 64, 3072 / 128), 256, SGEMM_SMEM>>>(
        ah, al, pwh, pwl, proj_b, out, 3072, 512, 512);
}

// round 14
// speedup vs baseline: 1.2143x; 1.0364x over previous
#include <cuda_runtime.h>
#include <cuda_bf16.h>
#include <math.h>
#include <stdint.h>

// Problem constants: B=4, T=16, T0=12, L=64, C=512, H=8, hd=64, NUM_SEEDS=4

// ---------------- scratch (static device globals; no allocations) -----------
__device__ int g_maskn[64];                // normalized ctx_mask [b*16 + t]

__device__ __align__(16) __nv_bfloat16 g_xh [3072 * 512], g_xl [3072 * 512];
__device__ __align__(16) __nv_bfloat16 g_xch[4096 * 512], g_xcl[4096 * 512];
__device__ __align__(16) __nv_bfloat16 g_dxh[4096 * 512], g_dxl[4096 * 512];
__device__ __align__(16) __nv_bfloat16 g_qwh[1536 * 512], g_qwl[1536 * 512];
__device__ __align__(16) __nv_bfloat16 g_kwh[ 512 * 512], g_kwl[ 512 * 512];
__device__ __align__(16) __nv_bfloat16 g_vwh[ 512 * 512], g_vwl[ 512 * 512];
__device__ __align__(16) __nv_bfloat16 g_pwh[ 512 * 512], g_pwl[ 512 * 512];
__device__ __align__(16) __nv_bfloat16 g_qkvh[3072 * 1536], g_qkvl[3072 * 1536];
__device__ __align__(16) __nv_bfloat16 g_kcth[4096 * 512],  g_kctl[4096 * 512];
__device__ __align__(16) __nv_bfloat16 g_vcth[4096 * 512],  g_vctl[4096 * 512];
__device__ __align__(16) __nv_bfloat16 g_ah [3072 * 512], g_al [3072 * 512];

// ---------------- helpers ----------------------------------------------------
__device__ __forceinline__ uint32_t s2u(const void* p) {
    uint32_t a;
    asm("{ .reg .u64 t; cvta.to.shared.u64 t, %1; cvt.u32.u64 %0, t; }"
        : "=r"(a) : "l"(p));
    return a;
}
__device__ __forceinline__ void cp16(uint32_t dst, const void* src) {
    asm volatile("cp.async.cg.shared.global [%0], [%1], 16;"
                 :: "r"(dst), "l"(src));
}
__device__ __forceinline__ void ldm_x4(uint32_t* r, uint32_t addr) {
    asm volatile("ldmatrix.sync.aligned.m8n8.x4.shared.b16 {%0,%1,%2,%3}, [%4];"
                 : "=r"(r[0]), "=r"(r[1]), "=r"(r[2]), "=r"(r[3]) : "r"(addr));
}
__device__ __forceinline__ void ldm_x4t(uint32_t* r, uint32_t addr) {
    asm volatile("ldmatrix.sync.aligned.m8n8.x4.trans.shared.b16 {%0,%1,%2,%3}, [%4];"
                 : "=r"(r[0]), "=r"(r[1]), "=r"(r[2]), "=r"(r[3]) : "r"(addr));
}
__device__ __forceinline__ void mma_bf16(float* c, const uint32_t* a, const uint32_t* b) {
    asm volatile(
        "mma.sync.aligned.m16n8k16.row.col.f32.bf16.bf16.f32 "
        "{%0,%1,%2,%3}, {%4,%5,%6,%7}, {%8,%9}, {%0,%1,%2,%3};"
        : "+f"(c[0]), "+f"(c[1]), "+f"(c[2]), "+f"(c[3])
        : "r"(a[0]), "r"(a[1]), "r"(a[2]), "r"(a[3]), "r"(b[0]), "r"(b[1]));
}
__device__ __forceinline__ uint32_t pack_bf(__nv_bfloat16 a, __nv_bfloat16 b) {
    return (uint32_t)__bfloat16_as_ushort(a) | ((uint32_t)__bfloat16_as_ushort(b) << 16);
}
__device__ __forceinline__ uint32_t pack_hi(float x, float y, float& rx, float& ry) {
    __nv_bfloat16 hx = __float2bfloat16(x), hy = __float2bfloat16(y);
    rx = x - __bfloat162float(hx);
    ry = y - __bfloat162float(hy);
    return pack_bf(hx, hy);
}

// ---------------- fused split: fp32 -> hi/lo bf16 (ONE launch, 7 arrays) -----
struct SplitArgs {
    const float4* src[7];
    uint2* hi[7];
    uint2* lo[7];
    int n4[7];
};
__global__ __launch_bounds__(256)
void split_all(SplitArgs a) {
    const int arr = blockIdx.y;
    const int n4 = a.n4[arr];
    const float4* __restrict__ s = a.src[arr];
    uint2* __restrict__ hp = a.hi[arr];
    uint2* __restrict__ lp = a.lo[arr];
    const int step = gridDim.x * 256;
    for (int i = blockIdx.x * 256 + threadIdx.x; i < n4; i += step) {
        float4 v = s[i];
        __nv_bfloat16 h0 = __float2bfloat16(v.x), h1 = __float2bfloat16(v.y);
        __nv_bfloat16 h2 = __float2bfloat16(v.z), h3 = __float2bfloat16(v.w);
        __nv_bfloat16 l0 = __float2bfloat16(v.x - __bfloat162float(h0));
        __nv_bfloat16 l1 = __float2bfloat16(v.y - __bfloat162float(h1));
        __nv_bfloat16 l2 = __float2bfloat16(v.z - __bfloat162float(h2));
        __nv_bfloat16 l3 = __float2bfloat16(v.w - __bfloat162float(h3));
        hp[i] = make_uint2(pack_bf(h0, h1), pack_bf(h2, h3));
        lp[i] = make_uint2(pack_bf(l0, l1), pack_bf(l2, l3));
    }
}

// ---------------- mask normalization (dtype-robust) --------------------------
__global__ void normalize_mask_kernel(const unsigned char* __restrict__ m8) {
    __shared__ int flag;
    int i = threadIdx.x;
    if (i == 0) flag = 0;
    __syncthreads();
    if ((i & 3) != 0 && m8[i] != 0) atomicOr(&flag, 1);
    __syncthreads();
    int v;
    if (flag) v = (m8[i] != 0) ? 1 : 0;
    else      v = (((const int*)m8)[i] != 0) ? 1 : 0;
    g_maskn[i] = v;
}

// ======== SMALL GEMM body (128x64, BK=64, 2-stage, 2 CTA/SM) ================
#define GPITCH 144
#define GA_B (128 * GPITCH)
#define GB_B (64 * GPITCH)
#define GBUF (2 * GA_B + 2 * GB_B)       // 55296 per stage
#define SGEMM_SMEM (2 * GBUF)            // 110592

// ---- fused qkv + kctx + vctx: one launch, 1088 blocks -----------------------
struct Gemm3 {
    const __nv_bfloat16* Ah[3];
    const __nv_bfloat16* Al[3];
    const __nv_bfloat16* Wh[3];
    const __nv_bfloat16* Wl[3];
    __nv_bfloat16* Ch[3];
    __nv_bfloat16* Cl[3];
};

__global__ __launch_bounds__(256, 2)
void gemm3_fused(Gemm3 g) {
    const int idx = blockIdx.x;
    const int prob = (idx >= 576) + (idx >= 832);
    const int local = idx - (prob == 0 ? 0 : (prob == 1 ? 576 : 832));
    const int nbx = (prob == 0) ? 24 : 8;
    const int N   = (prob == 0) ? 1536 : 512;
    const int bx = local % nbx, by = local / nbx;

    const __nv_bfloat16* __restrict__ Ah = g.Ah[prob];
    const __nv_bfloat16* __restrict__ Al = g.Al[prob];
    const __nv_bfloat16* __restrict__ Wh = g.Wh[prob];
    const __nv_bfloat16* __restrict__ Wl = g.Wl[prob];
    __nv_bfloat16* __restrict__ Ch = g.Ch[prob];
    __nv_bfloat16* __restrict__ Cl = g.Cl[prob];

    extern __shared__ char smem[];
    const uint32_t sb = s2u(smem);
    const int tid = threadIdx.x;
    const int wid = tid >> 5, lane = tid & 31;
    const int gid = lane >> 2, tig = lane & 3;
    const int bm = by * 128, bn = bx * 64;
    const int wm = wid & 3, wn = wid >> 2;

    const int lrow = tid >> 3;
    const int lseg = tid & 7;

    float acc[2][4][4];
#pragma unroll
    for (int mf = 0; mf < 2; mf++)
#pragma unroll
        for (int nf = 0; nf < 4; nf++)
#pragma unroll
            for (int r = 0; r < 4; r++) acc[mf][nf][r] = 0.f;

    auto issue = [&](int c, int buf) {
        uint32_t base = sb + buf * GBUF;
        const int kofs = c * 64 + lseg * 8;
#pragma unroll
        for (int i = 0; i < 4; i++) {
            int row = lrow + i * 32;
            uint32_t d = base + row * GPITCH + lseg * 16;
            cp16(d,         Ah + (size_t)(bm + row) * 512 + kofs);
            cp16(d + GA_B,  Al + (size_t)(bm + row) * 512 + kofs);
        }
#pragma unroll
        for (int i = 0; i < 2; i++) {
            int row = lrow + i * 32;
            uint32_t d = base + 2 * GA_B + row * GPITCH + lseg * 16;
            cp16(d,         Wh + (size_t)(bn + row) * 512 + kofs);
            cp16(d + GB_B,  Wl + (size_t)(bn + row) * 512 + kofs);
        }
        asm volatile("cp.async.commit_group;");
    };

    issue(0, 0);

    const uint32_t a_row16 = lane & 15;
    const uint32_t a_cofs  = (lane >> 4) * 16;
    const uint32_t b_nrow  = (lane & 7) + ((lane >> 4) & 1) * 8;
    const uint32_t b_kofs  = ((lane >> 3) & 1) * 16;

    for (int c = 0; c < 8; c++) {
        const int buf = c & 1;
        if (c + 1 < 8) {
            issue(c + 1, buf ^ 1);
            asm volatile("cp.async.wait_group 1;");
        } else {
            asm volatile("cp.async.wait_group 0;");
        }
        __syncthreads();

        const uint32_t abase = sb + buf * GBUF;
        const uint32_t bbase = abase + 2 * GA_B;

#pragma unroll
        for (int kf = 0; kf < 4; kf++) {
            uint32_t ah[2][4], al[2][4], bh[4][2], bl[4][2];
            const uint32_t kb = kf * 32;
#pragma unroll
            for (int mf = 0; mf < 2; mf++) {
                uint32_t ad = abase + (wm * 32 + mf * 16 + a_row16) * GPITCH
                            + a_cofs + kb;
                ldm_x4(ah[mf], ad);
                ldm_x4(al[mf], ad + GA_B);
            }
#pragma unroll
            for (int pr = 0; pr < 2; pr++) {
                uint32_t bd = bbase + (wn * 32 + pr * 16 + b_nrow) * GPITCH
                            + b_kofs + kb;
                uint32_t th[4], tl[4];
                ldm_x4(th, bd);
                ldm_x4(tl, bd + GB_B);
                bh[pr * 2 + 0][0] = th[0]; bh[pr * 2 + 0][1] = th[1];
                bh[pr * 2 + 1][0] = th[2]; bh[pr * 2 + 1][1] = th[3];
                bl[pr * 2 + 0][0] = tl[0]; bl[pr * 2 + 0][1] = tl[1];
                bl[pr * 2 + 1][0] = tl[2]; bl[pr * 2 + 1][1] = tl[3];
            }
#pragma unroll
            for (int mf = 0; mf < 2; mf++)
#pragma unroll
                for (int nf = 0; nf < 4; nf++) {
                    mma_bf16(acc[mf][nf], ah[mf], bh[nf]);
                    mma_bf16(acc[mf][nf], ah[mf], bl[nf]);
                    mma_bf16(acc[mf][nf], al[mf], bh[nf]);
                }
        }
        __syncthreads();
    }

#pragma unroll
    for (int mf = 0; mf < 2; mf++) {
#pragma unroll
        for (int nf = 0; nf < 4; nf++) {
            int row = bm + wm * 32 + mf * 16 + gid;
            int col = bn + wn * 32 + nf * 8 + tig * 2;
            float r0, r1, r2, r3;
            uint32_t h0 = pack_hi(acc[mf][nf][0], acc[mf][nf][1], r0, r1);
            uint32_t h1 = pack_hi(acc[mf][nf][2], acc[mf][nf][3], r2, r3);
            *(uint32_t*)&Ch[(size_t)row * N + col] = h0;
            *(uint32_t*)&Ch[(size_t)(row + 8) * N + col] = h1;
            *(uint32_t*)&Cl[(size_t)row * N + col] =
                pack_bf(__float2bfloat16(r0), __float2bfloat16(r1));
            *(uint32_t*)&Cl[(size_t)(row + 8) * N + col] =
                pack_bf(__float2bfloat16(r2), __float2bfloat16(r3));
        }
    }
}

// ---- proj GEMM: same BK=64 body, fp32 + bias output path --------------------
__global__ __launch_bounds__(256, 2)
void gemm_tc(const __nv_bfloat16* __restrict__ Ah, const __nv_bfloat16* __restrict__ Al,
             const __nv_bfloat16* __restrict__ Wh, const __nv_bfloat16* __restrict__ Wl,
             const float* __restrict__ bias, float* __restrict__ C,
             int M, int N, int K) {
    extern __shared__ char smem[];
    const uint32_t sb = s2u(smem);
    const int tid = threadIdx.x;
    const int wid = tid >> 5, lane = tid & 31;
    const int gid = lane >> 2, tig = lane & 3;
    const int bm = blockIdx.y * 128, bn = blockIdx.x * 64;
    const int wm = wid & 3, wn = wid >> 2;

    const int lrow = tid >> 3;
    const int lseg = tid & 7;

    float acc[2][4][4];
#pragma unroll
    for (int mf = 0; mf < 2; mf++)
#pragma unroll
        for (int nf = 0; nf < 4; nf++)
#pragma unroll
            for (int r = 0; r < 4; r++) acc[mf][nf][r] = 0.f;

    const int nc = K >> 6;

    auto issue = [&](int c, int buf) {
        uint32_t base = sb + buf * GBUF;
        const int kofs = c * 64 + lseg * 8;
#pragma unroll
        for (int i = 0; i < 4; i++) {
            int row = lrow + i * 32;
            uint32_t d = base + row * GPITCH + lseg * 16;
            cp16(d,         Ah + (size_t)(bm + row) * K + kofs);
            cp16(d + GA_B,  Al + (size_t)(bm + row) * K + kofs);
        }
#pragma unroll
        for (int i = 0; i < 2; i++) {
            int row = lrow + i * 32;
            uint32_t d = base + 2 * GA_B + row * GPITCH + lseg * 16;
            cp16(d,         Wh + (size_t)(bn + row) * K + kofs);
            cp16(d + GB_B,  Wl + (size_t)(bn + row) * K + kofs);
        }
        asm volatile("cp.async.commit_group;");
    };

    issue(0, 0);

    const uint32_t a_row16 = lane & 15;
    const uint32_t a_cofs  = (lane >> 4) * 16;
    const uint32_t b_nrow  = (lane & 7) + ((lane >> 4) & 1) * 8;
    const uint32_t b_kofs  = ((lane >> 3) & 1) * 16;

    for (int c = 0; c < nc; c++) {
        const int buf = c & 1;
        if (c + 1 < nc) {
            issue(c + 1, buf ^ 1);
            asm volatile("cp.async.wait_group 1;");
        } else {
            asm volatile("cp.async.wait_group 0;");
        }
        __syncthreads();

        const uint32_t abase = sb + buf * GBUF;
        const uint32_t bbase = abase + 2 * GA_B;

#pragma unroll
        for (int kf = 0; kf < 4; kf++) {
            uint32_t ah[2][4], al[2][4], bh[4][2], bl[4][2];
            const uint32_t kb = kf * 32;
#pragma unroll
            for (int mf = 0; mf < 2; mf++) {
                uint32_t ad = abase + (wm * 32 + mf * 16 + a_row16) * GPITCH
                            + a_cofs + kb;
                ldm_x4(ah[mf], ad);
                ldm_x4(al[mf], ad + GA_B);
            }
#pragma unroll
            for (int pr = 0; pr < 2; pr++) {
                uint32_t bd = bbase + (wn * 32 + pr * 16 + b_nrow) * GPITCH
                            + b_kofs + kb;
                uint32_t th[4], tl[4];
                ldm_x4(th, bd);
                ldm_x4(tl, bd + GB_B);
                bh[pr * 2 + 0][0] = th[0]; bh[pr * 2 + 0][1] = th[1];
                bh[pr * 2 + 1][0] = th[2]; bh[pr * 2 + 1][1] = th[3];
                bl[pr * 2 + 0][0] = tl[0]; bl[pr * 2 + 0][1] = tl[1];
                bl[pr * 2 + 1][0] = tl[2]; bl[pr * 2 + 1][1] = tl[3];
            }
#pragma unroll
            for (int mf = 0; mf < 2; mf++)
#pragma unroll
                for (int nf = 0; nf < 4; nf++) {
                    mma_bf16(acc[mf][nf], ah[mf], bh[nf]);
                    mma_bf16(acc[mf][nf], ah[mf], bl[nf]);
                    mma_bf16(acc[mf][nf], al[mf], bh[nf]);
                }
        }
        __syncthreads();
    }

#pragma unroll
    for (int mf = 0; mf < 2; mf++) {
#pragma unroll
        for (int nf = 0; nf < 4; nf++) {
            int row = bm + wm * 32 + mf * 16 + gid;
            int col = bn + wn * 32 + nf * 8 + tig * 2;
            float b0 = bias ? bias[col] : 0.f;
            float b1 = bias ? bias[col + 1] : 0.f;
            float2 v0 = make_float2(acc[mf][nf][0] + b0, acc[mf][nf][1] + b1);
            float2 v1 = make_float2(acc[mf][nf][2] + b0, acc[mf][nf][3] + b1);
            *(float2*)&C[(size_t)row * N + col] = v0;
            *(float2*)&C[(size_t)(row + 8) * N + col] = v1;
        }
    }
}

// ---------------- tensor-core flash attention --------------------------------
// Q staged in KV buffer 1 (fragments read once before KV1 overwrites it):
// smem = 2 KV buffers only -> 73728 B -> 3 CTAs/SM, single wave for 384 blocks.
#define APITCH 144
#define TILE_B 9216
#define KVBUF_B (4 * TILE_B)
#define ATTN_SMEM (2 * KVBUF_B)   // 73728

__global__ __launch_bounds__(128)
void attn_tc(const __nv_bfloat16* __restrict__ qkvh, const __nv_bfloat16* __restrict__ qkvl,
             const __nv_bfloat16* __restrict__ kcth, const __nv_bfloat16* __restrict__ kctl,
             const __nv_bfloat16* __restrict__ vcth, const __nv_bfloat16* __restrict__ vctl,
             __nv_bfloat16* __restrict__ outh, __nv_bfloat16* __restrict__ outl) {
    extern __shared__ char smem[];
    const uint32_t sb = s2u(smem);
    const int t0 = blockIdx.x, h = blockIdx.y, b = blockIdx.z;
    const int tid = threadIdx.x;
    const int w = tid >> 5, lane = tid & 31;
    const int gid = lane >> 2, tig = lane & 3;

    int ids[17], nv = 0;
    for (int t = 0; t < 16; t++)
        if (g_maskn[b * 16 + t] && t != t0 + 4) ids[nv++] = t;
    ids[nv++] = 16;

    const int seg = tid & 7;
    const int r0 = tid >> 3;

    // Q staged into KV buffer 1 (tiles 0,1): read once, then overwritten by KV1
    {
        const size_t base = (size_t)(b * 768 + t0 * 64) * 1536 + h * 64 + seg * 8;
        const uint32_t qdst = sb + KVBUF_B;
#pragma unroll
        for (int i = 0; i < 4; i++) {
            int row = r0 + i * 16;
            uint32_t d = qdst + row * APITCH + seg * 16;
            cp16(d,          qkvh + base + (size_t)row * 1536);
            cp16(d + TILE_B, qkvl + base + (size_t)row * 1536);
        }
    }

    auto issueKV = [&](int id, int buf) {
        const __nv_bfloat16 *ksh, *ksl, *vsh, *vsl;
        size_t kbase, vbase, rs;
        if (id < 16) {
            rs = 512;
            kbase = (size_t)(b * 1024 + id * 64) * 512 + h * 64 + seg * 8;
            vbase = kbase;
            ksh = kcth; ksl = kctl; vsh = vcth; vsl = vctl;
        } else {
            rs = 1536;
            size_t rb = (size_t)(b * 768 + t0 * 64) * 1536 + h * 64 + seg * 8;
            kbase = rb + 512; vbase = rb + 1024;
            ksh = qkvh; ksl = qkvl; vsh = qkvh; vsl = qkvl;
        }
        uint32_t base = sb + buf * KVBUF_B;
#pragma unroll
        for (int i = 0; i < 4; i++) {
            int row = r0 + i * 16;
            uint32_t d = base + row * APITCH + seg * 16;
            cp16(d,              ksh + kbase + (size_t)row * rs);
            cp16(d + TILE_B,     ksl + kbase + (size_t)row * rs);
            cp16(d + 2 * TILE_B, vsh + vbase + (size_t)row * rs);
            cp16(d + 3 * TILE_B, vsl + vbase + (size_t)row * rs);
        }
        asm volatile("cp.async.commit_group;");
    };

    // KV0 load joins the same commit group as Q
    issueKV(ids[0], 0);

    const uint32_t a_row16 = lane & 15;
    const uint32_t a_cofs  = (lane >> 4) * 16;
    const uint32_t b_nrow  = (lane & 7) + ((lane >> 4) & 1) * 8;
    const uint32_t b_kofs  = ((lane >> 3) & 1) * 16;
    const uint32_t v_krow = lane & 15;
    const uint32_t v_dofs = (lane >> 4) * 16;

    // Wait for Q + KV0, read Q fragments, release buffer 1
    asm volatile("cp.async.wait_group 0;");
    __syncthreads();

    uint32_t qh[4][4], ql[4][4];
    {
        const uint32_t qsrc = sb + KVBUF_B;
#pragma unroll
        for (int kf = 0; kf < 4; kf++) {
            uint32_t ad = qsrc + (w * 16 + a_row16) * APITCH + a_cofs + kf * 32;
            ldm_x4(qh[kf], ad);
            ldm_x4(ql[kf], ad + TILE_B);
        }
    }
    __syncthreads();   // all warps done reading Q before KV1 overwrites buf 1

    float of[8][4];
#pragma unroll
    for (int f = 0; f < 8; f++)
#pragma unroll
        for (int r = 0; r < 4; r++) of[f][r] = 0.f;
    float m1 = -INFINITY, m2 = -INFINITY, l1 = 0.f, l2 = 0.f;

    for (int i = 0; i < nv; i++) {
        if (i + 1 < nv) {
            issueKV(ids[i + 1], (i + 1) & 1);
            asm volatile("cp.async.wait_group 1;");
        } else {
            asm volatile("cp.async.wait_group 0;");
        }
        __syncthreads();

        const uint32_t kvb = sb + (i & 1) * KVBUF_B;

        float sf[8][4];
#pragma unroll
        for (int f = 0; f < 8; f++)
#pragma unroll
            for (int r = 0; r < 4; r++) sf[f][r] = 0.f;

#pragma unroll
        for (int nfp = 0; nfp < 4; nfp++) {
#pragma unroll
            for (int kf = 0; kf < 4; kf++) {
                uint32_t th[4], tl[4];
                uint32_t kd = kvb + (nfp * 16 + b_nrow) * APITCH + b_kofs + kf * 32;
                ldm_x4(th, kd);
                ldm_x4(tl, kd + TILE_B);
                mma_bf16(sf[nfp * 2 + 0], qh[kf], &th[0]);
                mma_bf16(sf[nfp * 2 + 0], qh[kf], &tl[0]);
                mma_bf16(sf[nfp * 2 + 0], ql[kf], &th[0]);
                mma_bf16(sf[nfp * 2 + 1], qh[kf], &th[2]);
                mma_bf16(sf[nfp * 2 + 1], qh[kf], &tl[2]);
                mma_bf16(sf[nfp * 2 + 1], ql[kf], &th[2]);
            }
        }

        float cm1 = -INFINITY, cm2 = -INFINITY;
#pragma unroll
        for (int f = 0; f < 8; f++) {
            sf[f][0] *= 0.125f; sf[f][1] *= 0.125f;
            sf[f][2] *= 0.125f; sf[f][3] *= 0.125f;
            cm1 = fmaxf(cm1, fmaxf(sf[f][0], sf[f][1]));
            cm2 = fmaxf(cm2, fmaxf(sf[f][2], sf[f][3]));
        }
        cm1 = fmaxf(cm1, __shfl_xor_sync(0xffffffffu, cm1, 1));
        cm1 = fmaxf(cm1, __shfl_xor_sync(0xffffffffu, cm1, 2));
        cm2 = fmaxf(cm2, __shfl_xor_sync(0xffffffffu, cm2, 1));
        cm2 = fmaxf(cm2, __shfl_xor_sync(0xffffffffu, cm2, 2));
        float mn1 = fmaxf(m1, cm1), mn2 = fmaxf(m2, cm2);
        float f1 = __expf(m1 - mn1), f2 = __expf(m2 - mn2);
        float rs1 = 0.f, rs2 = 0.f;
#pragma unroll
        for (int f = 0; f < 8; f++) {
            sf[f][0] = __expf(sf[f][0] - mn1);
            sf[f][1] = __expf(sf[f][1] - mn1);
            sf[f][2] = __expf(sf[f][2] - mn2);
            sf[f][3] = __expf(sf[f][3] - mn2);
            rs1 += sf[f][0] + sf[f][1];
            rs2 += sf[f][2] + sf[f][3];
        }
        rs1 += __shfl_xor_sync(0xffffffffu, rs1, 1);
        rs1 += __shfl_xor_sync(0xffffffffu, rs1, 2);
        rs2 += __shfl_xor_sync(0xffffffffu, rs2, 1);
        rs2 += __shfl_xor_sync(0xffffffffu, rs2, 2);
        l1 = l1 * f1 + rs1; l2 = l2 * f2 + rs2;
        m1 = mn1; m2 = mn2;
#pragma unroll
        for (int f = 0; f < 8; f++) {
            of[f][0] *= f1; of[f][1] *= f1;
            of[f][2] *= f2; of[f][3] *= f2;
        }

        uint32_t ph[4][4], pl[4][4];
#pragma unroll
        for (int kf = 0; kf < 4; kf++) {
            float r0a, r1a, r2a, r3a;
            ph[kf][0] = pack_hi(sf[2 * kf][0], sf[2 * kf][1], r0a, r1a);
            pl[kf][0] = pack_bf(__float2bfloat16(r0a), __float2bfloat16(r1a));
            ph[kf][1] = pack_hi(sf[2 * kf][2], sf[2 * kf][3], r0a, r1a);
            pl[kf][1] = pack_bf(__float2bfloat16(r0a), __float2bfloat16(r1a));
            ph[kf][2] = pack_hi(sf[2 * kf + 1][0], sf[2 * kf + 1][1], r2a, r3a);
            pl[kf][2] = pack_bf(__float2bfloat16(r2a), __float2bfloat16(r3a));
            ph[kf][3] = pack_hi(sf[2 * kf + 1][2], sf[2 * kf + 1][3], r2a, r3a);
            pl[kf][3] = pack_bf(__float2bfloat16(r2a), __float2bfloat16(r3a));
        }

        const uint32_t vb = kvb + 2 * TILE_B;
#pragma unroll
        for (int nfp = 0; nfp < 4; nfp++) {
#pragma unroll
            for (int kf = 0; kf < 4; kf++) {
                uint32_t vh_[4], vl_[4];
                uint32_t vd = vb + (kf * 16 + v_krow) * APITCH + nfp * 32 + v_dofs;
                ldm_x4t(vh_, vd);
                ldm_x4t(vl_, vd + TILE_B);
                mma_bf16(of[nfp * 2 + 0], ph[kf], &vh_[0]);
                mma_bf16(of[nfp * 2 + 0], ph[kf], &vl_[0]);
                mma_bf16(of[nfp * 2 + 0], pl[kf], &vh_[0]);
                mma_bf16(of[nfp * 2 + 1], ph[kf], &vh_[2]);
                mma_bf16(of[nfp * 2 + 1], ph[kf], &vl_[2]);
                mma_bf16(of[nfp * 2 + 1], pl[kf], &vh_[2]);
            }
        }
        __syncthreads();
    }

    const float inv1 = 1.0f / l1, inv2 = 1.0f / l2;
    const size_t row1 = (size_t)(b * 768 + t0 * 64 + w * 16 + gid);
    const size_t row2 = row1 + 8;
#pragma unroll
    for (int nf = 0; nf < 8; nf++) {
        int col = h * 64 + nf * 8 + tig * 2;
        float r0a, r1a;
        uint32_t h0 = pack_hi(of[nf][0] * inv1, of[nf][1] * inv1, r0a, r1a);
        *(uint32_t*)&outh[row1 * 512 + col] = h0;
        *(uint32_t*)&outl[row1 * 512 + col] =
            pack_bf(__float2bfloat16(r0a), __float2bfloat16(r1a));
        uint32_t h1 = pack_hi(of[nf][2] * inv2, of[nf][3] * inv2, r0a, r1a);
        *(uint32_t*)&outh[row2 * 512 + col] = h1;
        *(uint32_t*)&outl[row2 * 512 + col] =
            pack_bf(__float2bfloat16(r0a), __float2bfloat16(r1a));
    }
}

// ---------------- launcher ---------------------------------------------------
extern "C" void kernel_launch(void* const* d_in, const int* in_sizes, int n_in,
                              void* d_out, int out_size) {
    const float* x      = (const float*)d_in[0];
    const float* x_ctx  = (const float*)d_in[1];
    const float* dx_ctx = (const float*)d_in[2];
    const unsigned char* mask = (const unsigned char*)d_in[3];
    const float* qkv_w  = (const float*)d_in[4];
    const float* k_w    = (const float*)d_in[5];
    const float* v_w    = (const float*)d_in[6];
    const float* proj_w = (const float*)d_in[7];
    const float* proj_b = (const float*)d_in[8];
    float* out = (float*)d_out;

    __nv_bfloat16 *xh, *xl, *xch, *xcl, *dxh, *dxl, *qwh, *qwl,
                  *kwh, *kwl, *vwh, *vwl, *pwh, *pwl, *ah, *al,
                  *qkvh, *qkvl, *kcth, *kctl, *vcth, *vctl;
    cudaGetSymbolAddress((void**)&xh,  g_xh);  cudaGetSymbolAddress((void**)&xl,  g_xl);
    cudaGetSymbolAddress((void**)&xch, g_xch); cudaGetSymbolAddress((void**)&xcl, g_xcl);
    cudaGetSymbolAddress((void**)&dxh, g_dxh); cudaGetSymbolAddress((void**)&dxl, g_dxl);
    cudaGetSymbolAddress((void**)&qwh, g_qwh); cudaGetSymbolAddress((void**)&qwl, g_qwl);
    cudaGetSymbolAddress((void**)&kwh, g_kwh); cudaGetSymbolAddress((void**)&kwl, g_kwl);
    cudaGetSymbolAddress((void**)&vwh, g_vwh); cudaGetSymbolAddress((void**)&vwl, g_vwl);
    cudaGetSymbolAddress((void**)&pwh, g_pwh); cudaGetSymbolAddress((void**)&pwl, g_pwl);
    cudaGetSymbolAddress((void**)&ah,  g_ah);  cudaGetSymbolAddress((void**)&al,  g_al);
    cudaGetSymbolAddress((void**)&qkvh, g_qkvh); cudaGetSymbolAddress((void**)&qkvl, g_qkvl);
    cudaGetSymbolAddress((void**)&kcth, g_kcth); cudaGetSymbolAddress((void**)&kctl, g_kctl);
    cudaGetSymbolAddress((void**)&vcth, g_vcth); cudaGetSymbolAddress((void**)&vctl, g_vctl);

    cudaFuncSetAttribute(gemm3_fused, cudaFuncAttributeMaxDynamicSharedMemorySize, SGEMM_SMEM);
    cudaFuncSetAttribute(gemm_tc,     cudaFuncAttributeMaxDynamicSharedMemorySize, SGEMM_SMEM);
    cudaFuncSetAttribute(attn_tc,     cudaFuncAttributeMaxDynamicSharedMemorySize, ATTN_SMEM);

    // 1: mask
    normalize_mask_kernel<<<1, 64>>>(mask);

    // 2: all input splits in ONE launch
    SplitArgs sa;
    sa.src[0] = (const float4*)x;      sa.hi[0] = (uint2*)xh;  sa.lo[0] = (uint2*)xl;  sa.n4[0] = 3072 * 512 / 4;
    sa.src[1] = (const float4*)x_ctx;  sa.hi[1] = (uint2*)xch; sa.lo[1] = (uint2*)xcl; sa.n4[1] = 4096 * 512 / 4;
    sa.src[2] = (const float4*)dx_ctx; sa.hi[2] = (uint2*)dxh; sa.lo[2] = (uint2*)dxl; sa.n4[2] = 4096 * 512 / 4;
    sa.src[3] = (const float4*)qkv_w;  sa.hi[3] = (uint2*)qwh; sa.lo[3] = (uint2*)qwl; sa.n4[3] = 1536 * 512 / 4;
    sa.src[4] = (const float4*)k_w;    sa.hi[4] = (uint2*)kwh; sa.lo[4] = (uint2*)kwl; sa.n4[4] = 512 * 512 / 4;
    sa.src[5] = (const float4*)v_w;    sa.hi[5] = (uint2*)vwh; sa.lo[5] = (uint2*)vwl; sa.n4[5] = 512 * 512 / 4;
    sa.src[6] = (const float4*)proj_w; sa.hi[6] = (uint2*)pwh; sa.lo[6] = (uint2*)pwl; sa.n4[6] = 512 * 512 / 4;
    split_all<<<dim3(296, 7), 256>>>(sa);

    // 3: qkv + kctx + vctx in ONE fused launch (1088 blocks, BK=64 body)
    Gemm3 g3;
    g3.Ah[0] = xh;  g3.Al[0] = xl;  g3.Wh[0] = qwh; g3.Wl[0] = qwl;
    g3.Ch[0] = qkvh; g3.Cl[0] = qkvl;
    g3.Ah[1] = dxh; g3.Al[1] = dxl; g3.Wh[1] = kwh; g3.Wl[1] = kwl;
    g3.Ch[1] = kcth; g3.Cl[1] = kctl;
    g3.Ah[2] = xch; g3.Al[2] = xcl; g3.Wh[2] = vwh; g3.Wl[2] = vwl;
    g3.Ch[2] = vcth; g3.Cl[2] = vctl;
    gemm3_fused<<<1088, 256, SGEMM_SMEM>>>(g3);

    // 4: tensor-core flash attention -> hi/lo bf16 (3 CTAs/SM, single wave)
    attn_tc<<<dim3(12, 8, 4), 128, ATTN_SMEM>>>(
        qkvh, qkvl, kcth, kctl, vcth, vctl, ah, al);

    // 5: final projection + bias -> d_out (fp32)
    gemm_tc<<<dim3(512 / 64, 3072 / 128), 256, SGEMM_SMEM>>>(
        ah, al, pwh, pwl, proj_b, out, 3072, 512, 512);
}

// round 15
// speedup vs baseline: 1.2499x; 1.0293x over previous
#include <cuda_runtime.h>
#include <cuda_bf16.h>
#include <math.h>
#include <stdint.h>

// Problem constants: B=4, T=16, T0=12, L=64, C=512, H=8, hd=64, NUM_SEEDS=4

// ---------------- scratch (static device globals; no allocations) -----------
__device__ int g_maskn[64];                // normalized ctx_mask [b*16 + t]

__device__ __align__(16) __nv_bfloat16 g_xh [3072 * 512], g_xl [3072 * 512];
__device__ __align__(16) __nv_bfloat16 g_xch[4096 * 512], g_xcl[4096 * 512];
__device__ __align__(16) __nv_bfloat16 g_dxh[4096 * 512], g_dxl[4096 * 512];
__device__ __align__(16) __nv_bfloat16 g_qwh[1536 * 512], g_qwl[1536 * 512];
__device__ __align__(16) __nv_bfloat16 g_kwh[ 512 * 512], g_kwl[ 512 * 512];
__device__ __align__(16) __nv_bfloat16 g_vwh[ 512 * 512], g_vwl[ 512 * 512];
__device__ __align__(16) __nv_bfloat16 g_pwh[ 512 * 512], g_pwl[ 512 * 512];
__device__ __align__(16) __nv_bfloat16 g_qkvh[3072 * 1536], g_qkvl[3072 * 1536];
__device__ __align__(16) __nv_bfloat16 g_kcth[4096 * 512],  g_kctl[4096 * 512];
__device__ __align__(16) __nv_bfloat16 g_vcth[4096 * 512],  g_vctl[4096 * 512];
__device__ __align__(16) __nv_bfloat16 g_ah [3072 * 512], g_al [3072 * 512];

// ---------------- helpers ----------------------------------------------------
__device__ __forceinline__ uint32_t s2u(const void* p) {
    uint32_t a;
    asm("{ .reg .u64 t; cvta.to.shared.u64 t, %1; cvt.u32.u64 %0, t; }"
        : "=r"(a) : "l"(p));
    return a;
}
__device__ __forceinline__ void cp16(uint32_t dst, const void* src) {
    asm volatile("cp.async.cg.shared.global [%0], [%1], 16;"
                 :: "r"(dst), "l"(src));
}
__device__ __forceinline__ void ldm_x4(uint32_t* r, uint32_t addr) {
    asm volatile("ldmatrix.sync.aligned.m8n8.x4.shared.b16 {%0,%1,%2,%3}, [%4];"
                 : "=r"(r[0]), "=r"(r[1]), "=r"(r[2]), "=r"(r[3]) : "r"(addr));
}
__device__ __forceinline__ void ldm_x4t(uint32_t* r, uint32_t addr) {
    asm volatile("ldmatrix.sync.aligned.m8n8.x4.trans.shared.b16 {%0,%1,%2,%3}, [%4];"
                 : "=r"(r[0]), "=r"(r[1]), "=r"(r[2]), "=r"(r[3]) : "r"(addr));
}
__device__ __forceinline__ void mma_bf16(float* c, const uint32_t* a, const uint32_t* b) {
    asm volatile(
        "mma.sync.aligned.m16n8k16.row.col.f32.bf16.bf16.f32 "
        "{%0,%1,%2,%3}, {%4,%5,%6,%7}, {%8,%9}, {%0,%1,%2,%3};"
        : "+f"(c[0]), "+f"(c[1]), "+f"(c[2]), "+f"(c[3])
        : "r"(a[0]), "r"(a[1]), "r"(a[2]), "r"(a[3]), "r"(b[0]), "r"(b[1]));
}
__device__ __forceinline__ uint32_t pack_bf(__nv_bfloat16 a, __nv_bfloat16 b) {
    return (uint32_t)__bfloat16_as_ushort(a) | ((uint32_t)__bfloat16_as_ushort(b) << 16);
}
__device__ __forceinline__ uint32_t pack_hi(float x, float y, float& rx, float& ry) {
    __nv_bfloat16 hx = __float2bfloat16(x), hy = __float2bfloat16(y);
    rx = x - __bfloat162float(hx);
    ry = y - __bfloat162float(hy);
    return pack_bf(hx, hy);
}

// ---------------- fused split: fp32 -> hi/lo bf16 (ONE launch, 7 arrays) -----
struct SplitArgs {
    const float4* src[7];
    uint2* hi[7];
    uint2* lo[7];
    int n4[7];
};
__global__ __launch_bounds__(256)
void split_all(SplitArgs a) {
    const int arr = blockIdx.y;
    const int n4 = a.n4[arr];
    const float4* __restrict__ s = a.src[arr];
    uint2* __restrict__ hp = a.hi[arr];
    uint2* __restrict__ lp = a.lo[arr];
    const int step = gridDim.x * 256;
    for (int i = blockIdx.x * 256 + threadIdx.x; i < n4; i += step) {
        float4 v = s[i];
        __nv_bfloat16 h0 = __float2bfloat16(v.x), h1 = __float2bfloat16(v.y);
        __nv_bfloat16 h2 = __float2bfloat16(v.z), h3 = __float2bfloat16(v.w);
        __nv_bfloat16 l0 = __float2bfloat16(v.x - __bfloat162float(h0));
        __nv_bfloat16 l1 = __float2bfloat16(v.y - __bfloat162float(h1));
        __nv_bfloat16 l2 = __float2bfloat16(v.z - __bfloat162float(h2));
        __nv_bfloat16 l3 = __float2bfloat16(v.w - __bfloat162float(h3));
        hp[i] = make_uint2(pack_bf(h0, h1), pack_bf(h2, h3));
        lp[i] = make_uint2(pack_bf(l0, l1), pack_bf(l2, l3));
    }
}

// ---------------- mask normalization (dtype-robust) --------------------------
__global__ void normalize_mask_kernel(const unsigned char* __restrict__ m8) {
    __shared__ int flag;
    int i = threadIdx.x;
    if (i == 0) flag = 0;
    __syncthreads();
    if ((i & 3) != 0 && m8[i] != 0) atomicOr(&flag, 1);
    __syncthreads();
    int v;
    if (flag) v = (m8[i] != 0) ? 1 : 0;
    else      v = (((const int*)m8)[i] != 0) ? 1 : 0;
    g_maskn[i] = v;
}

// ======== SMALL GEMM body (128x64, BK=64, 2-stage, 2 CTA/SM) ================
#define GPITCH 144
#define GA_B (128 * GPITCH)
#define GB_B (64 * GPITCH)
#define GBUF (2 * GA_B + 2 * GB_B)       // 55296 per stage
#define SGEMM_SMEM (2 * GBUF)            // 110592

// ---- fused qkv + kctx + vctx: one launch, 1088 blocks -----------------------
struct Gemm3 {
    const __nv_bfloat16* Ah[3];
    const __nv_bfloat16* Al[3];
    const __nv_bfloat16* Wh[3];
    const __nv_bfloat16* Wl[3];
    __nv_bfloat16* Ch[3];
    __nv_bfloat16* Cl[3];
};

__global__ __launch_bounds__(256, 2)
void gemm3_fused(Gemm3 g) {
    const int idx = blockIdx.x;
    const int prob = (idx >= 576) + (idx >= 832);
    const int local = idx - (prob == 0 ? 0 : (prob == 1 ? 576 : 832));
    const int nbx = (prob == 0) ? 24 : 8;
    const int N   = (prob == 0) ? 1536 : 512;
    const int bx = local % nbx, by = local / nbx;

    // mask-aware early exit: a kctx/vctx m-tile covers exactly 2 context
    // frames; if both are ctx-masked, its output rows are never read.
    if (prob != 0) {
        const int batch = by >> 3;
        const int f0 = (by & 7) * 2;
        if (!g_maskn[batch * 16 + f0] && !g_maskn[batch * 16 + f0 + 1]) return;
    }

    const __nv_bfloat16* __restrict__ Ah = g.Ah[prob];
    const __nv_bfloat16* __restrict__ Al = g.Al[prob];
    const __nv_bfloat16* __restrict__ Wh = g.Wh[prob];
    const __nv_bfloat16* __restrict__ Wl = g.Wl[prob];
    __nv_bfloat16* __restrict__ Ch = g.Ch[prob];
    __nv_bfloat16* __restrict__ Cl = g.Cl[prob];

    extern __shared__ char smem[];
    const uint32_t sb = s2u(smem);
    const int tid = threadIdx.x;
    const int wid = tid >> 5, lane = tid & 31;
    const int gid = lane >> 2, tig = lane & 3;
    const int bm = by * 128, bn = bx * 64;
    const int wm = wid & 3, wn = wid >> 2;

    const int lrow = tid >> 3;
    const int lseg = tid & 7;

    float acc[2][4][4];
#pragma unroll
    for (int mf = 0; mf < 2; mf++)
#pragma unroll
        for (int nf = 0; nf < 4; nf++)
#pragma unroll
            for (int r = 0; r < 4; r++) acc[mf][nf][r] = 0.f;

    auto issue = [&](int c, int buf) {
        uint32_t base = sb + buf * GBUF;
        const int kofs = c * 64 + lseg * 8;
#pragma unroll
        for (int i = 0; i < 4; i++) {
            int row = lrow + i * 32;
            uint32_t d = base + row * GPITCH + lseg * 16;
            cp16(d,         Ah + (size_t)(bm + row) * 512 + kofs);
            cp16(d + GA_B,  Al + (size_t)(bm + row) * 512 + kofs);
        }
#pragma unroll
        for (int i = 0; i < 2; i++) {
            int row = lrow + i * 32;
            uint32_t d = base + 2 * GA_B + row * GPITCH + lseg * 16;
            cp16(d,         Wh + (size_t)(bn + row) * 512 + kofs);
            cp16(d + GB_B,  Wl + (size_t)(bn + row) * 512 + kofs);
        }
        asm volatile("cp.async.commit_group;");
    };

    issue(0, 0);

    const uint32_t a_row16 = lane & 15;
    const uint32_t a_cofs  = (lane >> 4) * 16;
    const uint32_t b_nrow  = (lane & 7) + ((lane >> 4) & 1) * 8;
    const uint32_t b_kofs  = ((lane >> 3) & 1) * 16;

    for (int c = 0; c < 8; c++) {
        const int buf = c & 1;
        if (c + 1 < 8) {
            issue(c + 1, buf ^ 1);
            asm volatile("cp.async.wait_group 1;");
        } else {
            asm volatile("cp.async.wait_group 0;");
        }
        __syncthreads();

        const uint32_t abase = sb + buf * GBUF;
        const uint32_t bbase = abase + 2 * GA_B;

#pragma unroll
        for (int kf = 0; kf < 4; kf++) {
            uint32_t ah[2][4], al[2][4], bh[4][2], bl[4][2];
            const uint32_t kb = kf * 32;
#pragma unroll
            for (int mf = 0; mf < 2; mf++) {
                uint32_t ad = abase + (wm * 32 + mf * 16 + a_row16) * GPITCH
                            + a_cofs + kb;
                ldm_x4(ah[mf], ad);
                ldm_x4(al[mf], ad + GA_B);
            }
#pragma unroll
            for (int pr = 0; pr < 2; pr++) {
                uint32_t bd = bbase + (wn * 32 + pr * 16 + b_nrow) * GPITCH
                            + b_kofs + kb;
                uint32_t th[4], tl[4];
                ldm_x4(th, bd);
                ldm_x4(tl, bd + GB_B);
                bh[pr * 2 + 0][0] = th[0]; bh[pr * 2 + 0][1] = th[1];
                bh[pr * 2 + 1][0] = th[2]; bh[pr * 2 + 1][1] = th[3];
                bl[pr * 2 + 0][0] = tl[0]; bl[pr * 2 + 0][1] = tl[1];
                bl[pr * 2 + 1][0] = tl[2]; bl[pr * 2 + 1][1] = tl[3];
            }
#pragma unroll
            for (int mf = 0; mf < 2; mf++)
#pragma unroll
                for (int nf = 0; nf < 4; nf++) {
                    mma_bf16(acc[mf][nf], ah[mf], bh[nf]);
                    mma_bf16(acc[mf][nf], ah[mf], bl[nf]);
                    mma_bf16(acc[mf][nf], al[mf], bh[nf]);
                }
        }
        __syncthreads();
    }

#pragma unroll
    for (int mf = 0; mf < 2; mf++) {
#pragma unroll
        for (int nf = 0; nf < 4; nf++) {
            int row = bm + wm * 32 + mf * 16 + gid;
            int col = bn + wn * 32 + nf * 8 + tig * 2;
            float r0, r1, r2, r3;
            uint32_t h0 = pack_hi(acc[mf][nf][0], acc[mf][nf][1], r0, r1);
            uint32_t h1 = pack_hi(acc[mf][nf][2], acc[mf][nf][3], r2, r3);
            *(uint32_t*)&Ch[(size_t)row * N + col] = h0;
            *(uint32_t*)&Ch[(size_t)(row + 8) * N + col] = h1;
            *(uint32_t*)&Cl[(size_t)row * N + col] =
                pack_bf(__float2bfloat16(r0), __float2bfloat16(r1));
            *(uint32_t*)&Cl[(size_t)(row + 8) * N + col] =
                pack_bf(__float2bfloat16(r2), __float2bfloat16(r3));
        }
    }
}

// ---- proj GEMM: same BK=64 body, fp32 + bias output path --------------------
__global__ __launch_bounds__(256, 2)
void gemm_tc(const __nv_bfloat16* __restrict__ Ah, const __nv_bfloat16* __restrict__ Al,
             const __nv_bfloat16* __restrict__ Wh, const __nv_bfloat16* __restrict__ Wl,
             const float* __restrict__ bias, float* __restrict__ C,
             int M, int N, int K) {
    extern __shared__ char smem[];
    const uint32_t sb = s2u(smem);
    const int tid = threadIdx.x;
    const int wid = tid >> 5, lane = tid & 31;
    const int gid = lane >> 2, tig = lane & 3;
    const int bm = blockIdx.y * 128, bn = blockIdx.x * 64;
    const int wm = wid & 3, wn = wid >> 2;

    const int lrow = tid >> 3;
    const int lseg = tid & 7;

    float acc[2][4][4];
#pragma unroll
    for (int mf = 0; mf < 2; mf++)
#pragma unroll
        for (int nf = 0; nf < 4; nf++)
#pragma unroll
            for (int r = 0; r < 4; r++) acc[mf][nf][r] = 0.f;

    const int nc = K >> 6;

    auto issue = [&](int c, int buf) {
        uint32_t base = sb + buf * GBUF;
        const int kofs = c * 64 + lseg * 8;
#pragma unroll
        for (int i = 0; i < 4; i++) {
            int row = lrow + i * 32;
            uint32_t d = base + row * GPITCH + lseg * 16;
            cp16(d,         Ah + (size_t)(bm + row) * K + kofs);
            cp16(d + GA_B,  Al + (size_t)(bm + row) * K + kofs);
        }
#pragma unroll
        for (int i = 0; i < 2; i++) {
            int row = lrow + i * 32;
            uint32_t d = base + 2 * GA_B + row * GPITCH + lseg * 16;
            cp16(d,         Wh + (size_t)(bn + row) * K + kofs);
            cp16(d + GB_B,  Wl + (size_t)(bn + row) * K + kofs);
        }
        asm volatile("cp.async.commit_group;");
    };

    issue(0, 0);

    const uint32_t a_row16 = lane & 15;
    const uint32_t a_cofs  = (lane >> 4) * 16;
    const uint32_t b_nrow  = (lane & 7) + ((lane >> 4) & 1) * 8;
    const uint32_t b_kofs  = ((lane >> 3) & 1) * 16;

    for (int c = 0; c < nc; c++) {
        const int buf = c & 1;
        if (c + 1 < nc) {
            issue(c + 1, buf ^ 1);
            asm volatile("cp.async.wait_group 1;");
        } else {
            asm volatile("cp.async.wait_group 0;");
        }
        __syncthreads();

        const uint32_t abase = sb + buf * GBUF;
        const uint32_t bbase = abase + 2 * GA_B;

#pragma unroll
        for (int kf = 0; kf < 4; kf++) {
            uint32_t ah[2][4], al[2][4], bh[4][2], bl[4][2];
            const uint32_t kb = kf * 32;
#pragma unroll
            for (int mf = 0; mf < 2; mf++) {
                uint32_t ad = abase + (wm * 32 + mf * 16 + a_row16) * GPITCH
                            + a_cofs + kb;
                ldm_x4(ah[mf], ad);
                ldm_x4(al[mf], ad + GA_B);
            }
#pragma unroll
            for (int pr = 0; pr < 2; pr++) {
                uint32_t bd = bbase + (wn * 32 + pr * 16 + b_nrow) * GPITCH
                            + b_kofs + kb;
                uint32_t th[4], tl[4];
                ldm_x4(th, bd);
                ldm_x4(tl, bd + GB_B);
                bh[pr * 2 + 0][0] = th[0]; bh[pr * 2 + 0][1] = th[1];
                bh[pr * 2 + 1][0] = th[2]; bh[pr * 2 + 1][1] = th[3];
                bl[pr * 2 + 0][0] = tl[0]; bl[pr * 2 + 0][1] = tl[1];
                bl[pr * 2 + 1][0] = tl[2]; bl[pr * 2 + 1][1] = tl[3];
            }
#pragma unroll
            for (int mf = 0; mf < 2; mf++)
#pragma unroll
                for (int nf = 0; nf < 4; nf++) {
                    mma_bf16(acc[mf][nf], ah[mf], bh[nf]);
                    mma_bf16(acc[mf][nf], ah[mf], bl[nf]);
                    mma_bf16(acc[mf][nf], al[mf], bh[nf]);
                }
        }
        __syncthreads();
    }

#pragma unroll
    for (int mf = 0; mf < 2; mf++) {
#pragma unroll
        for (int nf = 0; nf < 4; nf++) {
            int row = bm + wm * 32 + mf * 16 + gid;
            int col = bn + wn * 32 + nf * 8 + tig * 2;
            float b0 = bias ? bias[col] : 0.f;
            float b1 = bias ? bias[col + 1] : 0.f;
            float2 v0 = make_float2(acc[mf][nf][0] + b0, acc[mf][nf][1] + b1);
            float2 v1 = make_float2(acc[mf][nf][2] + b0, acc[mf][nf][3] + b1);
            *(float2*)&C[(size_t)row * N + col] = v0;
            *(float2*)&C[(size_t)(row + 8) * N + col] = v1;
        }
    }
}

// ---------------- tensor-core flash attention: key-split, 8 warps ------------
// 256 threads: warp = (qw, kh). qw in [0,4): q-rows qw*16..+16.
// kh in {0,1}: keys kh*32..+32 of every chunk. Independent online softmax per
// key half (exact), merged once at the end via smem scratch.
#define APITCH 144
#define TILE_B 9216
#define KVBUF_B (4 * TILE_B)
#define ATTN_SMEM (2 * KVBUF_B)   // 73728

__global__ __launch_bounds__(256, 2)
void attn_tc(const __nv_bfloat16* __restrict__ qkvh, const __nv_bfloat16* __restrict__ qkvl,
             const __nv_bfloat16* __restrict__ kcth, const __nv_bfloat16* __restrict__ kctl,
             const __nv_bfloat16* __restrict__ vcth, const __nv_bfloat16* __restrict__ vctl,
             __nv_bfloat16* __restrict__ outh, __nv_bfloat16* __restrict__ outl) {
    extern __shared__ char smem[];
    const uint32_t sb = s2u(smem);
    const int t0 = blockIdx.x, h = blockIdx.y, b = blockIdx.z;
    const int tid = threadIdx.x;
    const int wid = tid >> 5, lane = tid & 31;
    const int qw = wid & 3, kh = wid >> 2;
    const int gid = lane >> 2, tig = lane & 3;

    int ids[17], nv = 0;
    for (int t = 0; t < 16; t++)
        if (g_maskn[b * 16 + t] && t != t0 + 4) ids[nv++] = t;
    ids[nv++] = 16;

    const int seg = tid & 7;
    const int r0 = tid >> 3;    // 0..31

    // Q staged into KV buffer 1 (read once, then overwritten by KV1)
    {
        const size_t base = (size_t)(b * 768 + t0 * 64) * 1536 + h * 64 + seg * 8;
        const uint32_t qdst = sb + KVBUF_B;
#pragma unroll
        for (int i = 0; i < 2; i++) {
            int row = r0 + i * 32;
            uint32_t d = qdst + row * APITCH + seg * 16;
            cp16(d,          qkvh + base + (size_t)row * 1536);
            cp16(d + TILE_B, qkvl + base + (size_t)row * 1536);
        }
    }

    auto issueKV = [&](int id, int buf) {
        const __nv_bfloat16 *ksh, *ksl, *vsh, *vsl;
        size_t kbase, vbase, rs;
        if (id < 16) {
            rs = 512;
            kbase = (size_t)(b * 1024 + id * 64) * 512 + h * 64 + seg * 8;
            vbase = kbase;
            ksh = kcth; ksl = kctl; vsh = vcth; vsl = vctl;
        } else {
            rs = 1536;
            size_t rb = (size_t)(b * 768 + t0 * 64) * 1536 + h * 64 + seg * 8;
            kbase = rb + 512; vbase = rb + 1024;
            ksh = qkvh; ksl = qkvl; vsh = qkvh; vsl = qkvl;
        }
        uint32_t base = sb + buf * KVBUF_B;
#pragma unroll
        for (int i = 0; i < 2; i++) {
            int row = r0 + i * 32;
            uint32_t d = base + row * APITCH + seg * 16;
            cp16(d,              ksh + kbase + (size_t)row * rs);
            cp16(d + TILE_B,     ksl + kbase + (size_t)row * rs);
            cp16(d + 2 * TILE_B, vsh + vbase + (size_t)row * rs);
            cp16(d + 3 * TILE_B, vsl + vbase + (size_t)row * rs);
        }
        asm volatile("cp.async.commit_group;");
    };

    issueKV(ids[0], 0);

    const uint32_t a_row16 = lane & 15;
    const uint32_t a_cofs  = (lane >> 4) * 16;
    const uint32_t b_nrow  = (lane & 7) + ((lane >> 4) & 1) * 8;
    const uint32_t b_kofs  = ((lane >> 3) & 1) * 16;
    const uint32_t v_krow = lane & 15;
    const uint32_t v_dofs = (lane >> 4) * 16;

    asm volatile("cp.async.wait_group 0;");
    __syncthreads();

    uint32_t qh[4][4], ql[4][4];
    {
        const uint32_t qsrc = sb + KVBUF_B;
#pragma unroll
        for (int kf = 0; kf < 4; kf++) {
            uint32_t ad = qsrc + (qw * 16 + a_row16) * APITCH + a_cofs + kf * 32;
            ldm_x4(qh[kf], ad);
            ldm_x4(ql[kf], ad + TILE_B);
        }
    }
    __syncthreads();

    float of[8][4];
#pragma unroll
    for (int f = 0; f < 8; f++)
#pragma unroll
        for (int r = 0; r < 4; r++) of[f][r] = 0.f;
    float m1 = -INFINITY, m2 = -INFINITY, l1 = 0.f, l2 = 0.f;

    for (int i = 0; i < nv; i++) {
        if (i + 1 < nv) {
            issueKV(ids[i + 1], (i + 1) & 1);
            asm volatile("cp.async.wait_group 1;");
        } else {
            asm volatile("cp.async.wait_group 0;");
        }
        __syncthreads();

        const uint32_t kvb = sb + (i & 1) * KVBUF_B;

        // ---- S = Q @ K^T for this warp's 32 keys (4 n-frags) ----
        float sf[4][4];
#pragma unroll
        for (int f = 0; f < 4; f++)
#pragma unroll
            for (int r = 0; r < 4; r++) sf[f][r] = 0.f;

#pragma unroll
        for (int pr = 0; pr < 2; pr++) {
#pragma unroll
            for (int kf = 0; kf < 4; kf++) {
                uint32_t th[4], tl[4];
                uint32_t kd = kvb + (kh * 32 + pr * 16 + b_nrow) * APITCH
                            + b_kofs + kf * 32;
                ldm_x4(th, kd);
                ldm_x4(tl, kd + TILE_B);
                mma_bf16(sf[pr * 2 + 0], qh[kf], &th[0]);
                mma_bf16(sf[pr * 2 + 0], qh[kf], &tl[0]);
                mma_bf16(sf[pr * 2 + 0], ql[kf], &th[0]);
                mma_bf16(sf[pr * 2 + 1], qh[kf], &th[2]);
                mma_bf16(sf[pr * 2 + 1], qh[kf], &tl[2]);
                mma_bf16(sf[pr * 2 + 1], ql[kf], &th[2]);
            }
        }

        // ---- online softmax over this key half ----
        float cm1 = -INFINITY, cm2 = -INFINITY;
#pragma unroll
        for (int f = 0; f < 4; f++) {
            sf[f][0] *= 0.125f; sf[f][1] *= 0.125f;
            sf[f][2] *= 0.125f; sf[f][3] *= 0.125f;
            cm1 = fmaxf(cm1, fmaxf(sf[f][0], sf[f][1]));
            cm2 = fmaxf(cm2, fmaxf(sf[f][2], sf[f][3]));
        }
        cm1 = fmaxf(cm1, __shfl_xor_sync(0xffffffffu, cm1, 1));
        cm1 = fmaxf(cm1, __shfl_xor_sync(0xffffffffu, cm1, 2));
        cm2 = fmaxf(cm2, __shfl_xor_sync(0xffffffffu, cm2, 1));
        cm2 = fmaxf(cm2, __shfl_xor_sync(0xffffffffu, cm2, 2));
        float mn1 = fmaxf(m1, cm1), mn2 = fmaxf(m2, cm2);
        float f1 = __expf(m1 - mn1), f2 = __expf(m2 - mn2);
        float rs1 = 0.f, rs2 = 0.f;
#pragma unroll
        for (int f = 0; f < 4; f++) {
            sf[f][0] = __expf(sf[f][0] - mn1);
            sf[f][1] = __expf(sf[f][1] - mn1);
            sf[f][2] = __expf(sf[f][2] - mn2);
            sf[f][3] = __expf(sf[f][3] - mn2);
            rs1 += sf[f][0] + sf[f][1];
            rs2 += sf[f][2] + sf[f][3];
        }
        rs1 += __shfl_xor_sync(0xffffffffu, rs1, 1);
        rs1 += __shfl_xor_sync(0xffffffffu, rs1, 2);
        rs2 += __shfl_xor_sync(0xffffffffu, rs2, 1);
        rs2 += __shfl_xor_sync(0xffffffffu, rs2, 2);
        l1 = l1 * f1 + rs1; l2 = l2 * f2 + rs2;
        m1 = mn1; m2 = mn2;
#pragma unroll
        for (int f = 0; f < 8; f++) {
            of[f][0] *= f1; of[f][1] *= f1;
            of[f][2] *= f2; of[f][3] *= f2;
        }

        // ---- P -> A fragments (2 k16 frags over 32 keys) ----
        uint32_t ph[2][4], pl[2][4];
#pragma unroll
        for (int kf = 0; kf < 2; kf++) {
            float r0a, r1a, r2a, r3a;
            ph[kf][0] = pack_hi(sf[2 * kf][0], sf[2 * kf][1], r0a, r1a);
            pl[kf][0] = pack_bf(__float2bfloat16(r0a), __float2bfloat16(r1a));
            ph[kf][1] = pack_hi(sf[2 * kf][2], sf[2 * kf][3], r0a, r1a);
            pl[kf][1] = pack_bf(__float2bfloat16(r0a), __float2bfloat16(r1a));
            ph[kf][2] = pack_hi(sf[2 * kf + 1][0], sf[2 * kf + 1][1], r2a, r3a);
            pl[kf][2] = pack_bf(__float2bfloat16(r2a), __float2bfloat16(r3a));
            ph[kf][3] = pack_hi(sf[2 * kf + 1][2], sf[2 * kf + 1][3], r2a, r3a);
            pl[kf][3] = pack_bf(__float2bfloat16(r2a), __float2bfloat16(r3a));
        }

        // ---- O += P @ V over this warp's 32 key rows ----
        const uint32_t vb = kvb + 2 * TILE_B;
#pragma unroll
        for (int nfp = 0; nfp < 4; nfp++) {
#pragma unroll
            for (int kf = 0; kf < 2; kf++) {
                uint32_t vh_[4], vl_[4];
                uint32_t vd = vb + (kh * 32 + kf * 16 + v_krow) * APITCH
                            + nfp * 32 + v_dofs;
                ldm_x4t(vh_, vd);
                ldm_x4t(vl_, vd + TILE_B);
                mma_bf16(of[nfp * 2 + 0], ph[kf], &vh_[0]);
                mma_bf16(of[nfp * 2 + 0], ph[kf], &vl_[0]);
                mma_bf16(of[nfp * 2 + 0], pl[kf], &vh_[0]);
                mma_bf16(of[nfp * 2 + 1], ph[kf], &vh_[2]);
                mma_bf16(of[nfp * 2 + 1], ph[kf], &vl_[2]);
                mma_bf16(of[nfp * 2 + 1], pl[kf], &vh_[2]);
            }
        }
        __syncthreads();
    }

    // ---- merge the two key halves (exact flash merge), write hi/lo ----
    // kh=1 warps publish raw (of, m, l) to smem scratch; kh=0 warps combine.
    const uint32_t o_scr = sb;                        // 4*32*32*4 = 16384 B
    const uint32_t ml_scr = sb + 16384;               // 4*32*4*4  = 2048 B
    const int slot = qw * 32 + lane;
    if (kh == 1) {
        float* op = (float*)(smem + (o_scr - sb) + (size_t)slot * 32 * 4);
#pragma unroll
        for (int f = 0; f < 8; f++) {
            op[f * 4 + 0] = of[f][0]; op[f * 4 + 1] = of[f][1];
            op[f * 4 + 2] = of[f][2]; op[f * 4 + 3] = of[f][3];
        }
        float* mp = (float*)(smem + (ml_scr - sb) + (size_t)slot * 16);
        mp[0] = m1; mp[1] = l1; mp[2] = m2; mp[3] = l2;
    }
    __syncthreads();
    if (kh == 0) {
        const float* op = (const float*)(smem + (o_scr - sb) + (size_t)slot * 32 * 4);
        const float* mp = (const float*)(smem + (ml_scr - sb) + (size_t)slot * 16);
        float mb1 = mp[0], lb1 = mp[1], mb2 = mp[2], lb2 = mp[3];
        float M1 = fmaxf(m1, mb1), M2 = fmaxf(m2, mb2);
        float ea1 = __expf(m1 - M1), eb1 = __expf(mb1 - M1);
        float ea2 = __expf(m2 - M2), eb2 = __expf(mb2 - M2);
        float inv1 = 1.0f / (l1 * ea1 + lb1 * eb1);
        float inv2 = 1.0f / (l2 * ea2 + lb2 * eb2);

        const size_t row1 = (size_t)(b * 768 + t0 * 64 + qw * 16 + gid);
        const size_t row2 = row1 + 8;
#pragma unroll
        for (int nf = 0; nf < 8; nf++) {
            int col = h * 64 + nf * 8 + tig * 2;
            float v0 = (of[nf][0] * ea1 + op[nf * 4 + 0] * eb1) * inv1;
            float v1 = (of[nf][1] * ea1 + op[nf * 4 + 1] * eb1) * inv1;
            float v2 = (of[nf][2] * ea2 + op[nf * 4 + 2] * eb2) * inv2;
            float v3 = (of[nf][3] * ea2 + op[nf * 4 + 3] * eb2) * inv2;
            float r0a, r1a;
            uint32_t h0 = pack_hi(v0, v1, r0a, r1a);
            *(uint32_t*)&outh[row1 * 512 + col] = h0;
            *(uint32_t*)&outl[row1 * 512 + col] =
                pack_bf(__float2bfloat16(r0a), __float2bfloat16(r1a));
            uint32_t h1 = pack_hi(v2, v3, r0a, r1a);
            *(uint32_t*)&outh[row2 * 512 + col] = h1;
            *(uint32_t*)&outl[row2 * 512 + col] =
                pack_bf(__float2bfloat16(r0a), __float2bfloat16(r1a));
        }
    }
}

// ---------------- launcher ---------------------------------------------------
extern "C" void kernel_launch(void* const* d_in, const int* in_sizes, int n_in,
                              void* d_out, int out_size) {
    const float* x      = (const float*)d_in[0];
    const float* x_ctx  = (const float*)d_in[1];
    const float* dx_ctx = (const float*)d_in[2];
    const unsigned char* mask = (const unsigned char*)d_in[3];
    const float* qkv_w  = (const float*)d_in[4];
    const float* k_w    = (const float*)d_in[5];
    const float* v_w    = (const float*)d_in[6];
    const float* proj_w = (const float*)d_in[7];
    const float* proj_b = (const float*)d_in[8];
    float* out = (float*)d_out;

    __nv_bfloat16 *xh, *xl, *xch, *xcl, *dxh, *dxl, *qwh, *qwl,
                  *kwh, *kwl, *vwh, *vwl, *pwh, *pwl, *ah, *al,
                  *qkvh, *qkvl, *kcth, *kctl, *vcth, *vctl;
    cudaGetSymbolAddress((void**)&xh,  g_xh);  cudaGetSymbolAddress((void**)&xl,  g_xl);
    cudaGetSymbolAddress((void**)&xch, g_xch); cudaGetSymbolAddress((void**)&xcl, g_xcl);
    cudaGetSymbolAddress((void**)&dxh, g_dxh); cudaGetSymbolAddress((void**)&dxl, g_dxl);
    cudaGetSymbolAddress((void**)&qwh, g_qwh); cudaGetSymbolAddress((void**)&qwl, g_qwl);
    cudaGetSymbolAddress((void**)&kwh, g_kwh); cudaGetSymbolAddress((void**)&kwl, g_kwl);
    cudaGetSymbolAddress((void**)&vwh, g_vwh); cudaGetSymbolAddress((void**)&vwl, g_vwl);
    cudaGetSymbolAddress((void**)&pwh, g_pwh); cudaGetSymbolAddress((void**)&pwl, g_pwl);
    cudaGetSymbolAddress((void**)&ah,  g_ah);  cudaGetSymbolAddress((void**)&al,  g_al);
    cudaGetSymbolAddress((void**)&qkvh, g_qkvh); cudaGetSymbolAddress((void**)&qkvl, g_qkvl);
    cudaGetSymbolAddress((void**)&kcth, g_kcth); cudaGetSymbolAddress((void**)&kctl, g_kctl);
    cudaGetSymbolAddress((void**)&vcth, g_vcth); cudaGetSymbolAddress((void**)&vctl, g_vctl);

    cudaFuncSetAttribute(gemm3_fused, cudaFuncAttributeMaxDynamicSharedMemorySize, SGEMM_SMEM);
    cudaFuncSetAttribute(gemm_tc,     cudaFuncAttributeMaxDynamicSharedMemorySize, SGEMM_SMEM);
    cudaFuncSetAttribute(attn_tc,     cudaFuncAttributeMaxDynamicSharedMemorySize, ATTN_SMEM);

    // 1: mask
    normalize_mask_kernel<<<1, 64>>>(mask);

    // 2: all input splits in ONE launch
    SplitArgs sa;
    sa.src[0] = (const float4*)x;      sa.hi[0] = (uint2*)xh;  sa.lo[0] = (uint2*)xl;  sa.n4[0] = 3072 * 512 / 4;
    sa.src[1] = (const float4*)x_ctx;  sa.hi[1] = (uint2*)xch; sa.lo[1] = (uint2*)xcl; sa.n4[1] = 4096 * 512 / 4;
    sa.src[2] = (const float4*)dx_ctx; sa.hi[2] = (uint2*)dxh; sa.lo[2] = (uint2*)dxl; sa.n4[2] = 4096 * 512 / 4;
    sa.src[3] = (const float4*)qkv_w;  sa.hi[3] = (uint2*)qwh; sa.lo[3] = (uint2*)qwl; sa.n4[3] = 1536 * 512 / 4;
    sa.src[4] = (const float4*)k_w;    sa.hi[4] = (uint2*)kwh; sa.lo[4] = (uint2*)kwl; sa.n4[4] = 512 * 512 / 4;
    sa.src[5] = (const float4*)v_w;    sa.hi[5] = (uint2*)vwh; sa.lo[5] = (uint2*)vwl; sa.n4[5] = 512 * 512 / 4;
    sa.src[6] = (const float4*)proj_w; sa.hi[6] = (uint2*)pwh; sa.lo[6] = (uint2*)pwl; sa.n4[6] = 512 * 512 / 4;
    split_all<<<dim3(296, 7), 256>>>(sa);

    // 3: qkv + kctx + vctx in ONE fused launch (mask-aware early exit)
    Gemm3 g3;
    g3.Ah[0] = xh;  g3.Al[0] = xl;  g3.Wh[0] = qwh; g3.Wl[0] = qwl;
    g3.Ch[0] = qkvh; g3.Cl[0] = qkvl;
    g3.Ah[1] = dxh; g3.Al[1] = dxl; g3.Wh[1] = kwh; g3.Wl[1] = kwl;
    g3.Ch[1] = kcth; g3.Cl[1] = kctl;
    g3.Ah[2] = xch; g3.Al[2] = xcl; g3.Wh[2] = vwh; g3.Wl[2] = vwl;
    g3.Ch[2] = vcth; g3.Cl[2] = vctl;
    gemm3_fused<<<1088, 256, SGEMM_SMEM>>>(g3);

    // 4: key-split tensor-core flash attention (8 warps) -> hi/lo bf16
    attn_tc<<<dim3(12, 8, 4), 256, ATTN_SMEM>>>(
        qkvh, qkvl, kcth, kctl, vcth, vctl, ah, al);

    // 5: final projection + bias -> d_out (fp32)
    gemm_tc<<<dim3(512 / 64, 3072 / 128), 256, SGEMM_SMEM>>>(
        ah, al, pwh, pwl, proj_b, out, 3072, 512, 512);
}

// round 16
// speedup vs baseline: 1.2602x; 1.0083x over previous
#include <cuda_runtime.h>
#include <cuda_bf16.h>
#include <math.h>
#include <stdint.h>

// Problem constants: B=4, T=16, T0=12, L=64, C=512, H=8, hd=64, NUM_SEEDS=4

// ---------------- scratch (static device globals; no allocations) -----------
__device__ int g_maskn[64];                // normalized ctx_mask [b*16 + t]

__device__ __align__(16) __nv_bfloat16 g_xh [3072 * 512], g_xl [3072 * 512];
__device__ __align__(16) __nv_bfloat16 g_xch[4096 * 512], g_xcl[4096 * 512];
__device__ __align__(16) __nv_bfloat16 g_dxh[4096 * 512], g_dxl[4096 * 512];
__device__ __align__(16) __nv_bfloat16 g_qwh[1536 * 512], g_qwl[1536 * 512];
__device__ __align__(16) __nv_bfloat16 g_kwh[ 512 * 512], g_kwl[ 512 * 512];
__device__ __align__(16) __nv_bfloat16 g_vwh[ 512 * 512], g_vwl[ 512 * 512];
__device__ __align__(16) __nv_bfloat16 g_pwh[ 512 * 512], g_pwl[ 512 * 512];
__device__ __align__(16) __nv_bfloat16 g_qkvh[3072 * 1536], g_qkvl[3072 * 1536];
__device__ __align__(16) __nv_bfloat16 g_kcth[4096 * 512],  g_kctl[4096 * 512];
__device__ __align__(16) __nv_bfloat16 g_vcth[4096 * 512],  g_vctl[4096 * 512];
__device__ __align__(16) __nv_bfloat16 g_ah [3072 * 512], g_al [3072 * 512];

// ---------------- helpers ----------------------------------------------------
__device__ __forceinline__ uint32_t s2u(const void* p) {
    uint32_t a;
    asm("{ .reg .u64 t; cvta.to.shared.u64 t, %1; cvt.u32.u64 %0, t; }"
        : "=r"(a) : "l"(p));
    return a;
}
__device__ __forceinline__ void cp16(uint32_t dst, const void* src) {
    asm volatile("cp.async.cg.shared.global [%0], [%1], 16;"
                 :: "r"(dst), "l"(src));
}
__device__ __forceinline__ void ldm_x4(uint32_t* r, uint32_t addr) {
    asm volatile("ldmatrix.sync.aligned.m8n8.x4.shared.b16 {%0,%1,%2,%3}, [%4];"
                 : "=r"(r[0]), "=r"(r[1]), "=r"(r[2]), "=r"(r[3]) : "r"(addr));
}
__device__ __forceinline__ void ldm_x4t(uint32_t* r, uint32_t addr) {
    asm volatile("ldmatrix.sync.aligned.m8n8.x4.trans.shared.b16 {%0,%1,%2,%3}, [%4];"
                 : "=r"(r[0]), "=r"(r[1]), "=r"(r[2]), "=r"(r[3]) : "r"(addr));
}
__device__ __forceinline__ void mma_bf16(float* c, const uint32_t* a, const uint32_t* b) {
    asm volatile(
        "mma.sync.aligned.m16n8k16.row.col.f32.bf16.bf16.f32 "
        "{%0,%1,%2,%3}, {%4,%5,%6,%7}, {%8,%9}, {%0,%1,%2,%3};"
        : "+f"(c[0]), "+f"(c[1]), "+f"(c[2]), "+f"(c[3])
        : "r"(a[0]), "r"(a[1]), "r"(a[2]), "r"(a[3]), "r"(b[0]), "r"(b[1]));
}
__device__ __forceinline__ uint32_t pack_bf(__nv_bfloat16 a, __nv_bfloat16 b) {
    return (uint32_t)__bfloat16_as_ushort(a) | ((uint32_t)__bfloat16_as_ushort(b) << 16);
}
__device__ __forceinline__ uint32_t pack_hi(float x, float y, float& rx, float& ry) {
    __nv_bfloat16 hx = __float2bfloat16(x), hy = __float2bfloat16(y);
    rx = x - __bfloat162float(hx);
    ry = y - __bfloat162float(hy);
    return pack_bf(hx, hy);
}

// ---------------- fused split: fp32 -> hi/lo bf16 (ONE launch, 7 arrays) -----
struct SplitArgs {
    const float4* src[7];
    uint2* hi[7];
    uint2* lo[7];
    int n4[7];
};
__global__ __launch_bounds__(256)
void split_all(SplitArgs a) {
    const int arr = blockIdx.y;
    const int n4 = a.n4[arr];
    const float4* __restrict__ s = a.src[arr];
    uint2* __restrict__ hp = a.hi[arr];
    uint2* __restrict__ lp = a.lo[arr];
    const int step = gridDim.x * 256;
    for (int i = blockIdx.x * 256 + threadIdx.x; i < n4; i += step) {
        float4 v = s[i];
        __nv_bfloat16 h0 = __float2bfloat16(v.x), h1 = __float2bfloat16(v.y);
        __nv_bfloat16 h2 = __float2bfloat16(v.z), h3 = __float2bfloat16(v.w);
        __nv_bfloat16 l0 = __float2bfloat16(v.x - __bfloat162float(h0));
        __nv_bfloat16 l1 = __float2bfloat16(v.y - __bfloat162float(h1));
        __nv_bfloat16 l2 = __float2bfloat16(v.z - __bfloat162float(h2));
        __nv_bfloat16 l3 = __float2bfloat16(v.w - __bfloat162float(h3));
        hp[i] = make_uint2(pack_bf(h0, h1), pack_bf(h2, h3));
        lp[i] = make_uint2(pack_bf(l0, l1), pack_bf(l2, l3));
    }
}

// ---------------- mask normalization (dtype-robust) --------------------------
__global__ void normalize_mask_kernel(const unsigned char* __restrict__ m8) {
    __shared__ int flag;
    int i = threadIdx.x;
    if (i == 0) flag = 0;
    __syncthreads();
    if ((i & 3) != 0 && m8[i] != 0) atomicOr(&flag, 1);
    __syncthreads();
    int v;
    if (flag) v = (m8[i] != 0) ? 1 : 0;
    else      v = (((const int*)m8)[i] != 0) ? 1 : 0;
    g_maskn[i] = v;
}

// ======== SMALL GEMM body (128x64, BK=64, 2-stage, 2 CTA/SM) ================
#define GPITCH 144
#define GA_B (128 * GPITCH)
#define GB_B (64 * GPITCH)
#define GBUF (2 * GA_B + 2 * GB_B)       // 55296 per stage
#define SGEMM_SMEM (2 * GBUF)            // 110592

// ---- fused qkv + kctx + vctx: one launch, 1088 blocks -----------------------
struct Gemm3 {
    const __nv_bfloat16* Ah[3];
    const __nv_bfloat16* Al[3];
    const __nv_bfloat16* Wh[3];
    const __nv_bfloat16* Wl[3];
    __nv_bfloat16* Ch[3];
    __nv_bfloat16* Cl[3];
};

__global__ __launch_bounds__(256, 2)
void gemm3_fused(Gemm3 g) {
    const int idx = blockIdx.x;
    const int prob = (idx >= 576) + (idx >= 832);
    const int local = idx - (prob == 0 ? 0 : (prob == 1 ? 576 : 832));
    const int nbx = (prob == 0) ? 24 : 8;
    const int N   = (prob == 0) ? 1536 : 512;
    const int bx = local % nbx, by = local / nbx;

    if (prob != 0) {
        const int batch = by >> 3;
        const int f0 = (by & 7) * 2;
        if (!g_maskn[batch * 16 + f0] && !g_maskn[batch * 16 + f0 + 1]) return;
    }

    const __nv_bfloat16* __restrict__ Ah = g.Ah[prob];
    const __nv_bfloat16* __restrict__ Al = g.Al[prob];
    const __nv_bfloat16* __restrict__ Wh = g.Wh[prob];
    const __nv_bfloat16* __restrict__ Wl = g.Wl[prob];
    __nv_bfloat16* __restrict__ Ch = g.Ch[prob];
    __nv_bfloat16* __restrict__ Cl = g.Cl[prob];

    extern __shared__ char smem[];
    const uint32_t sb = s2u(smem);
    const int tid = threadIdx.x;
    const int wid = tid >> 5, lane = tid & 31;
    const int gid = lane >> 2, tig = lane & 3;
    const int bm = by * 128, bn = bx * 64;
    const int wm = wid & 3, wn = wid >> 2;

    const int lrow = tid >> 3;
    const int lseg = tid & 7;

    float acc[2][4][4];
#pragma unroll
    for (int mf = 0; mf < 2; mf++)
#pragma unroll
        for (int nf = 0; nf < 4; nf++)
#pragma unroll
            for (int r = 0; r < 4; r++) acc[mf][nf][r] = 0.f;

    auto issue = [&](int c, int buf) {
        uint32_t base = sb + buf * GBUF;
        const int kofs = c * 64 + lseg * 8;
#pragma unroll
        for (int i = 0; i < 4; i++) {
            int row = lrow + i * 32;
            uint32_t d = base + row * GPITCH + lseg * 16;
            cp16(d,         Ah + (size_t)(bm + row) * 512 + kofs);
            cp16(d + GA_B,  Al + (size_t)(bm + row) * 512 + kofs);
        }
#pragma unroll
        for (int i = 0; i < 2; i++) {
            int row = lrow + i * 32;
            uint32_t d = base + 2 * GA_B + row * GPITCH + lseg * 16;
            cp16(d,         Wh + (size_t)(bn + row) * 512 + kofs);
            cp16(d + GB_B,  Wl + (size_t)(bn + row) * 512 + kofs);
        }
        asm volatile("cp.async.commit_group;");
    };

    issue(0, 0);

    const uint32_t a_row16 = lane & 15;
    const uint32_t a_cofs  = (lane >> 4) * 16;
    const uint32_t b_nrow  = (lane & 7) + ((lane >> 4) & 1) * 8;
    const uint32_t b_kofs  = ((lane >> 3) & 1) * 16;

    for (int c = 0; c < 8; c++) {
        const int buf = c & 1;
        if (c + 1 < 8) {
            issue(c + 1, buf ^ 1);
            asm volatile("cp.async.wait_group 1;");
        } else {
            asm volatile("cp.async.wait_group 0;");
        }
        __syncthreads();

        const uint32_t abase = sb + buf * GBUF;
        const uint32_t bbase = abase + 2 * GA_B;

#pragma unroll
        for (int kf = 0; kf < 4; kf++) {
            uint32_t ah[2][4], al[2][4], bh[4][2], bl[4][2];
            const uint32_t kb = kf * 32;
#pragma unroll
            for (int mf = 0; mf < 2; mf++) {
                uint32_t ad = abase + (wm * 32 + mf * 16 + a_row16) * GPITCH
                            + a_cofs + kb;
                ldm_x4(ah[mf], ad);
                ldm_x4(al[mf], ad + GA_B);
            }
#pragma unroll
            for (int pr = 0; pr < 2; pr++) {
                uint32_t bd = bbase + (wn * 32 + pr * 16 + b_nrow) * GPITCH
                            + b_kofs + kb;
                uint32_t th[4], tl[4];
                ldm_x4(th, bd);
                ldm_x4(tl, bd + GB_B);
                bh[pr * 2 + 0][0] = th[0]; bh[pr * 2 + 0][1] = th[1];
                bh[pr * 2 + 1][0] = th[2]; bh[pr * 2 + 1][1] = th[3];
                bl[pr * 2 + 0][0] = tl[0]; bl[pr * 2 + 0][1] = tl[1];
                bl[pr * 2 + 1][0] = tl[2]; bl[pr * 2 + 1][1] = tl[3];
            }
#pragma unroll
            for (int mf = 0; mf < 2; mf++)
#pragma unroll
                for (int nf = 0; nf < 4; nf++) {
                    mma_bf16(acc[mf][nf], ah[mf], bh[nf]);
                    mma_bf16(acc[mf][nf], ah[mf], bl[nf]);
                    mma_bf16(acc[mf][nf], al[mf], bh[nf]);
                }
        }
        __syncthreads();
    }

#pragma unroll
    for (int mf = 0; mf < 2; mf++) {
#pragma unroll
        for (int nf = 0; nf < 4; nf++) {
            int row = bm + wm * 32 + mf * 16 + gid;
            int col = bn + wn * 32 + nf * 8 + tig * 2;
            float r0, r1, r2, r3;
            uint32_t h0 = pack_hi(acc[mf][nf][0], acc[mf][nf][1], r0, r1);
            uint32_t h1 = pack_hi(acc[mf][nf][2], acc[mf][nf][3], r2, r3);
            *(uint32_t*)&Ch[(size_t)row * N + col] = h0;
            *(uint32_t*)&Ch[(size_t)(row + 8) * N + col] = h1;
            *(uint32_t*)&Cl[(size_t)row * N + col] =
                pack_bf(__float2bfloat16(r0), __float2bfloat16(r1));
            *(uint32_t*)&Cl[(size_t)(row + 8) * N + col] =
                pack_bf(__float2bfloat16(r2), __float2bfloat16(r3));
        }
    }
}

// ---- proj GEMM: same BK=64 body, fp32 + bias output path --------------------
__global__ __launch_bounds__(256, 2)
void gemm_tc(const __nv_bfloat16* __restrict__ Ah, const __nv_bfloat16* __restrict__ Al,
             const __nv_bfloat16* __restrict__ Wh, const __nv_bfloat16* __restrict__ Wl,
             const float* __restrict__ bias, float* __restrict__ C,
             int M, int N, int K) {
    extern __shared__ char smem[];
    const uint32_t sb = s2u(smem);
    const int tid = threadIdx.x;
    const int wid = tid >> 5, lane = tid & 31;
    const int gid = lane >> 2, tig = lane & 3;
    const int bm = blockIdx.y * 128, bn = blockIdx.x * 64;
    const int wm = wid & 3, wn = wid >> 2;

    const int lrow = tid >> 3;
    const int lseg = tid & 7;

    float acc[2][4][4];
#pragma unroll
    for (int mf = 0; mf < 2; mf++)
#pragma unroll
        for (int nf = 0; nf < 4; nf++)
#pragma unroll
            for (int r = 0; r < 4; r++) acc[mf][nf][r] = 0.f;

    const int nc = K >> 6;

    auto issue = [&](int c, int buf) {
        uint32_t base = sb + buf * GBUF;
        const int kofs = c * 64 + lseg * 8;
#pragma unroll
        for (int i = 0; i < 4; i++) {
            int row = lrow + i * 32;
            uint32_t d = base + row * GPITCH + lseg * 16;
            cp16(d,         Ah + (size_t)(bm + row) * K + kofs);
            cp16(d + GA_B,  Al + (size_t)(bm + row) * K + kofs);
        }
#pragma unroll
        for (int i = 0; i < 2; i++) {
            int row = lrow + i * 32;
            uint32_t d = base + 2 * GA_B + row * GPITCH + lseg * 16;
            cp16(d,         Wh + (size_t)(bn + row) * K + kofs);
            cp16(d + GB_B,  Wl + (size_t)(bn + row) * K + kofs);
        }
        asm volatile("cp.async.commit_group;");
    };

    issue(0, 0);

    const uint32_t a_row16 = lane & 15;
    const uint32_t a_cofs  = (lane >> 4) * 16;
    const uint32_t b_nrow  = (lane & 7) + ((lane >> 4) & 1) * 8;
    const uint32_t b_kofs  = ((lane >> 3) & 1) * 16;

    for (int c = 0; c < nc; c++) {
        const int buf = c & 1;
        if (c + 1 < nc) {
            issue(c + 1, buf ^ 1);
            asm volatile("cp.async.wait_group 1;");
        } else {
            asm volatile("cp.async.wait_group 0;");
        }
        __syncthreads();

        const uint32_t abase = sb + buf * GBUF;
        const uint32_t bbase = abase + 2 * GA_B;

#pragma unroll
        for (int kf = 0; kf < 4; kf++) {
            uint32_t ah[2][4], al[2][4], bh[4][2], bl[4][2];
            const uint32_t kb = kf * 32;
#pragma unroll
            for (int mf = 0; mf < 2; mf++) {
                uint32_t ad = abase + (wm * 32 + mf * 16 + a_row16) * GPITCH
                            + a_cofs + kb;
                ldm_x4(ah[mf], ad);
                ldm_x4(al[mf], ad + GA_B);
            }
#pragma unroll
            for (int pr = 0; pr < 2; pr++) {
                uint32_t bd = bbase + (wn * 32 + pr * 16 + b_nrow) * GPITCH
                            + b_kofs + kb;
                uint32_t th[4], tl[4];
                ldm_x4(th, bd);
                ldm_x4(tl, bd + GB_B);
                bh[pr * 2 + 0][0] = th[0]; bh[pr * 2 + 0][1] = th[1];
                bh[pr * 2 + 1][0] = th[2]; bh[pr * 2 + 1][1] = th[3];
                bl[pr * 2 + 0][0] = tl[0]; bl[pr * 2 + 0][1] = tl[1];
                bl[pr * 2 + 1][0] = tl[2]; bl[pr * 2 + 1][1] = tl[3];
            }
#pragma unroll
            for (int mf = 0; mf < 2; mf++)
#pragma unroll
                for (int nf = 0; nf < 4; nf++) {
                    mma_bf16(acc[mf][nf], ah[mf], bh[nf]);
                    mma_bf16(acc[mf][nf], ah[mf], bl[nf]);
                    mma_bf16(acc[mf][nf], al[mf], bh[nf]);
                }
        }
        __syncthreads();
    }

#pragma unroll
    for (int mf = 0; mf < 2; mf++) {
#pragma unroll
        for (int nf = 0; nf < 4; nf++) {
            int row = bm + wm * 32 + mf * 16 + gid;
            int col = bn + wn * 32 + nf * 8 + tig * 2;
            float b0 = bias ? bias[col] : 0.f;
            float b1 = bias ? bias[col + 1] : 0.f;
            float2 v0 = make_float2(acc[mf][nf][0] + b0, acc[mf][nf][1] + b1);
            float2 v1 = make_float2(acc[mf][nf][2] + b0, acc[mf][nf][3] + b1);
            *(float2*)&C[(size_t)row * N + col] = v0;
            *(float2*)&C[(size_t)(row + 8) * N + col] = v1;
        }
    }
}

// ---------------- tensor-core flash attention: key-split, 3-buffer ring ------
// 256 threads: warp = (qw, kh). qw in [0,4): q-rows qw*16..+16.
// kh in {0,1}: keys kh*32..+32 of every chunk. Independent online softmax per
// key half, merged at the end via smem scratch.
// KV ring of 3 buffers -> ONE barrier per chunk. Q staged in buffer 2.
#define APITCH 144
#define TILE_B 9216
#define KVBUF_B (4 * TILE_B)
#define ATTN_SMEM (3 * KVBUF_B)   // 110592

__global__ __launch_bounds__(256, 2)
void attn_tc(const __nv_bfloat16* __restrict__ qkvh, const __nv_bfloat16* __restrict__ qkvl,
             const __nv_bfloat16* __restrict__ kcth, const __nv_bfloat16* __restrict__ kctl,
             const __nv_bfloat16* __restrict__ vcth, const __nv_bfloat16* __restrict__ vctl,
             __nv_bfloat16* __restrict__ outh, __nv_bfloat16* __restrict__ outl) {
    extern __shared__ char smem[];
    const uint32_t sb = s2u(smem);
    const int t0 = blockIdx.x, h = blockIdx.y, b = blockIdx.z;
    const int tid = threadIdx.x;
    const int wid = tid >> 5, lane = tid & 31;
    const int qw = wid & 3, kh = wid >> 2;
    const int gid = lane >> 2, tig = lane & 3;

    int ids[17], nv = 0;
    for (int t = 0; t < 16; t++)
        if (g_maskn[b * 16 + t] && t != t0 + 4) ids[nv++] = t;
    ids[nv++] = 16;

    const int seg = tid & 7;
    const int r0 = tid >> 3;    // 0..31

    auto issueKV = [&](int id, int buf) {
        const __nv_bfloat16 *ksh, *ksl, *vsh, *vsl;
        size_t kbase, vbase, rs;
        if (id < 16) {
            rs = 512;
            kbase = (size_t)(b * 1024 + id * 64) * 512 + h * 64 + seg * 8;
            vbase = kbase;
            ksh = kcth; ksl = kctl; vsh = vcth; vsl = vctl;
        } else {
            rs = 1536;
            size_t rb = (size_t)(b * 768 + t0 * 64) * 1536 + h * 64 + seg * 8;
            kbase = rb + 512; vbase = rb + 1024;
            ksh = qkvh; ksl = qkvl; vsh = qkvh; vsl = qkvl;
        }
        uint32_t base = sb + buf * KVBUF_B;
#pragma unroll
        for (int i = 0; i < 2; i++) {
            int row = r0 + i * 32;
            uint32_t d = base + row * APITCH + seg * 16;
            cp16(d,              ksh + kbase + (size_t)row * rs);
            cp16(d + TILE_B,     ksl + kbase + (size_t)row * rs);
            cp16(d + 2 * TILE_B, vsh + vbase + (size_t)row * rs);
            cp16(d + 3 * TILE_B, vsl + vbase + (size_t)row * rs);
        }
        asm volatile("cp.async.commit_group;");
    };

    // Q staged into buffer 2 + KV0 into buffer 0 (same commit group)
    {
        const size_t base = (size_t)(b * 768 + t0 * 64) * 1536 + h * 64 + seg * 8;
        const uint32_t qdst = sb + 2 * KVBUF_B;
#pragma unroll
        for (int i = 0; i < 2; i++) {
            int row = r0 + i * 32;
            uint32_t d = qdst + row * APITCH + seg * 16;
            cp16(d,          qkvh + base + (size_t)row * 1536);
            cp16(d + TILE_B, qkvl + base + (size_t)row * 1536);
        }
    }
    issueKV(ids[0], 0);
    if (nv > 1) issueKV(ids[1], 1);

    const uint32_t a_row16 = lane & 15;
    const uint32_t a_cofs  = (lane >> 4) * 16;
    const uint32_t b_nrow  = (lane & 7) + ((lane >> 4) & 1) * 8;
    const uint32_t b_kofs  = ((lane >> 3) & 1) * 16;
    const uint32_t v_krow = lane & 15;
    const uint32_t v_dofs = (lane >> 4) * 16;

    asm volatile("cp.async.wait_group 0;");
    __syncthreads();

    uint32_t qh[4][4], ql[4][4];
    {
        const uint32_t qsrc = sb + 2 * KVBUF_B;
#pragma unroll
        for (int kf = 0; kf < 4; kf++) {
            uint32_t ad = qsrc + (qw * 16 + a_row16) * APITCH + a_cofs + kf * 32;
            ldm_x4(qh[kf], ad);
            ldm_x4(ql[kf], ad + TILE_B);
        }
    }

    float of[8][4];
#pragma unroll
    for (int f = 0; f < 8; f++)
#pragma unroll
        for (int r = 0; r < 4; r++) of[f][r] = 0.f;
    float m1 = -INFINITY, m2 = -INFINITY, l1 = 0.f, l2 = 0.f;

    for (int i = 0; i < nv; i++) {
        if (i + 1 < nv) asm volatile("cp.async.wait_group 1;");
        else            asm volatile("cp.async.wait_group 0;");
        __syncthreads();   // single barrier per chunk; also covers Q-read at i=0
        if (i + 2 < nv) {
            int nb = i + 2; nb -= (nb >= 3) ? 3 : 0; nb -= (nb >= 3) ? 3 : 0;
            issueKV(ids[i + 2], (i + 2) % 3);
        }

        int bsel = i % 3;
        const uint32_t kvb = sb + bsel * KVBUF_B;

        // ---- S = Q @ K^T for this warp's 32 keys ----
        float sf[4][4];
#pragma unroll
        for (int f = 0; f < 4; f++)
#pragma unroll
            for (int r = 0; r < 4; r++) sf[f][r] = 0.f;

#pragma unroll
        for (int pr = 0; pr < 2; pr++) {
#pragma unroll
            for (int kf = 0; kf < 4; kf++) {
                uint32_t th[4], tl[4];
                uint32_t kd = kvb + (kh * 32 + pr * 16 + b_nrow) * APITCH
                            + b_kofs + kf * 32;
                ldm_x4(th, kd);
                ldm_x4(tl, kd + TILE_B);
                mma_bf16(sf[pr * 2 + 0], qh[kf], &th[0]);
                mma_bf16(sf[pr * 2 + 0], qh[kf], &tl[0]);
                mma_bf16(sf[pr * 2 + 0], ql[kf], &th[0]);
                mma_bf16(sf[pr * 2 + 1], qh[kf], &th[2]);
                mma_bf16(sf[pr * 2 + 1], qh[kf], &tl[2]);
                mma_bf16(sf[pr * 2 + 1], ql[kf], &th[2]);
            }
        }

        // ---- online softmax over this key half ----
        float cm1 = -INFINITY, cm2 = -INFINITY;
#pragma unroll
        for (int f = 0; f < 4; f++) {
            sf[f][0] *= 0.125f; sf[f][1] *= 0.125f;
            sf[f][2] *= 0.125f; sf[f][3] *= 0.125f;
            cm1 = fmaxf(cm1, fmaxf(sf[f][0], sf[f][1]));
            cm2 = fmaxf(cm2, fmaxf(sf[f][2], sf[f][3]));
        }
        cm1 = fmaxf(cm1, __shfl_xor_sync(0xffffffffu, cm1, 1));
        cm1 = fmaxf(cm1, __shfl_xor_sync(0xffffffffu, cm1, 2));
        cm2 = fmaxf(cm2, __shfl_xor_sync(0xffffffffu, cm2, 1));
        cm2 = fmaxf(cm2, __shfl_xor_sync(0xffffffffu, cm2, 2));
        float mn1 = fmaxf(m1, cm1), mn2 = fmaxf(m2, cm2);
        float f1 = __expf(m1 - mn1), f2 = __expf(m2 - mn2);
        float rs1 = 0.f, rs2 = 0.f;
#pragma unroll
        for (int f = 0; f < 4; f++) {
            sf[f][0] = __expf(sf[f][0] - mn1);
            sf[f][1] = __expf(sf[f][1] - mn1);
            sf[f][2] = __expf(sf[f][2] - mn2);
            sf[f][3] = __expf(sf[f][3] - mn2);
            rs1 += sf[f][0] + sf[f][1];
            rs2 += sf[f][2] + sf[f][3];
        }
        rs1 += __shfl_xor_sync(0xffffffffu, rs1, 1);
        rs1 += __shfl_xor_sync(0xffffffffu, rs1, 2);
        rs2 += __shfl_xor_sync(0xffffffffu, rs2, 1);
        rs2 += __shfl_xor_sync(0xffffffffu, rs2, 2);
        l1 = l1 * f1 + rs1; l2 = l2 * f2 + rs2;
        m1 = mn1; m2 = mn2;
#pragma unroll
        for (int f = 0; f < 8; f++) {
            of[f][0] *= f1; of[f][1] *= f1;
            of[f][2] *= f2; of[f][3] *= f2;
        }

        // ---- P -> A fragments ----
        uint32_t ph[2][4], pl[2][4];
#pragma unroll
        for (int kf = 0; kf < 2; kf++) {
            float r0a, r1a, r2a, r3a;
            ph[kf][0] = pack_hi(sf[2 * kf][0], sf[2 * kf][1], r0a, r1a);
            pl[kf][0] = pack_bf(__float2bfloat16(r0a), __float2bfloat16(r1a));
            ph[kf][1] = pack_hi(sf[2 * kf][2], sf[2 * kf][3], r0a, r1a);
            pl[kf][1] = pack_bf(__float2bfloat16(r0a), __float2bfloat16(r1a));
            ph[kf][2] = pack_hi(sf[2 * kf + 1][0], sf[2 * kf + 1][1], r2a, r3a);
            pl[kf][2] = pack_bf(__float2bfloat16(r2a), __float2bfloat16(r3a));
            ph[kf][3] = pack_hi(sf[2 * kf + 1][2], sf[2 * kf + 1][3], r2a, r3a);
            pl[kf][3] = pack_bf(__float2bfloat16(r2a), __float2bfloat16(r3a));
        }

        // ---- O += P @ V over this warp's 32 key rows ----
        const uint32_t vb = kvb + 2 * TILE_B;
#pragma unroll
        for (int nfp = 0; nfp < 4; nfp++) {
#pragma unroll
            for (int kf = 0; kf < 2; kf++) {
                uint32_t vh_[4], vl_[4];
                uint32_t vd = vb + (kh * 32 + kf * 16 + v_krow) * APITCH
                            + nfp * 32 + v_dofs;
                ldm_x4t(vh_, vd);
                ldm_x4t(vl_, vd + TILE_B);
                mma_bf16(of[nfp * 2 + 0], ph[kf], &vh_[0]);
                mma_bf16(of[nfp * 2 + 0], ph[kf], &vl_[0]);
                mma_bf16(of[nfp * 2 + 0], pl[kf], &vh_[0]);
                mma_bf16(of[nfp * 2 + 1], ph[kf], &vh_[2]);
                mma_bf16(of[nfp * 2 + 1], ph[kf], &vl_[2]);
                mma_bf16(of[nfp * 2 + 1], pl[kf], &vh_[2]);
            }
        }
        // no end-of-loop barrier: buf (i+2)%3's last reader finished before
        // the top barrier of iter i (it was read at iter i-1).
    }
    __syncthreads();   // all warps done with KV buffers before scratch reuse

    // ---- merge the two key halves (exact flash merge), write hi/lo ----
    const uint32_t o_scr = sb;                        // 4*32*32*4 = 16384 B
    const uint32_t ml_scr = sb + 16384;               // 4*32*4*4  = 2048 B
    const int slot = qw * 32 + lane;
    if (kh == 1) {
        float* op = (float*)(smem + (o_scr - sb) + (size_t)slot * 32 * 4);
#pragma unroll
        for (int f = 0; f < 8; f++) {
            op[f * 4 + 0] = of[f][0]; op[f * 4 + 1] = of[f][1];
            op[f * 4 + 2] = of[f][2]; op[f * 4 + 3] = of[f][3];
        }
        float* mp = (float*)(smem + (ml_scr - sb) + (size_t)slot * 16);
        mp[0] = m1; mp[1] = l1; mp[2] = m2; mp[3] = l2;
    }
    __syncthreads();
    if (kh == 0) {
        const float* op = (const float*)(smem + (o_scr - sb) + (size_t)slot * 32 * 4);
        const float* mp = (const float*)(smem + (ml_scr - sb) + (size_t)slot * 16);
        float mb1 = mp[0], lb1 = mp[1], mb2 = mp[2], lb2 = mp[3];
        float M1 = fmaxf(m1, mb1), M2 = fmaxf(m2, mb2);
        float ea1 = __expf(m1 - M1), eb1 = __expf(mb1 - M1);
        float ea2 = __expf(m2 - M2), eb2 = __expf(mb2 - M2);
        float inv1 = 1.0f / (l1 * ea1 + lb1 * eb1);
        float inv2 = 1.0f / (l2 * ea2 + lb2 * eb2);

        const size_t row1 = (size_t)(b * 768 + t0 * 64 + qw * 16 + gid);
        const size_t row2 = row1 + 8;
#pragma unroll
        for (int nf = 0; nf < 8; nf++) {
            int col = h * 64 + nf * 8 + tig * 2;
            float v0 = (of[nf][0] * ea1 + op[nf * 4 + 0] * eb1) * inv1;
            float v1 = (of[nf][1] * ea1 + op[nf * 4 + 1] * eb1) * inv1;
            float v2 = (of[nf][2] * ea2 + op[nf * 4 + 2] * eb2) * inv2;
            float v3 = (of[nf][3] * ea2 + op[nf * 4 + 3] * eb2) * inv2;
            float r0a, r1a;
            uint32_t h0 = pack_hi(v0, v1, r0a, r1a);
            *(uint32_t*)&outh[row1 * 512 + col] = h0;
            *(uint32_t*)&outl[row1 * 512 + col] =
                pack_bf(__float2bfloat16(r0a), __float2bfloat16(r1a));
            uint32_t h1 = pack_hi(v2, v3, r0a, r1a);
            *(uint32_t*)&outh[row2 * 512 + col] = h1;
            *(uint32_t*)&outl[row2 * 512 + col] =
                pack_bf(__float2bfloat16(r0a), __float2bfloat16(r1a));
        }
    }
}

// ---------------- launcher ---------------------------------------------------
extern "C" void kernel_launch(void* const* d_in, const int* in_sizes, int n_in,
                              void* d_out, int out_size) {
    const float* x      = (const float*)d_in[0];
    const float* x_ctx  = (const float*)d_in[1];
    const float* dx_ctx = (const float*)d_in[2];
    const unsigned char* mask = (const unsigned char*)d_in[3];
    const float* qkv_w  = (const float*)d_in[4];
    const float* k_w    = (const float*)d_in[5];
    const float* v_w    = (const float*)d_in[6];
    const float* proj_w = (const float*)d_in[7];
    const float* proj_b = (const float*)d_in[8];
    float* out = (float*)d_out;

    __nv_bfloat16 *xh, *xl, *xch, *xcl, *dxh, *dxl, *qwh, *qwl,
                  *kwh, *kwl, *vwh, *vwl, *pwh, *pwl, *ah, *al,
                  *qkvh, *qkvl, *kcth, *kctl, *vcth, *vctl;
    cudaGetSymbolAddress((void**)&xh,  g_xh);  cudaGetSymbolAddress((void**)&xl,  g_xl);
    cudaGetSymbolAddress((void**)&xch, g_xch); cudaGetSymbolAddress((void**)&xcl, g_xcl);
    cudaGetSymbolAddress((void**)&dxh, g_dxh); cudaGetSymbolAddress((void**)&dxl, g_dxl);
    cudaGetSymbolAddress((void**)&qwh, g_qwh); cudaGetSymbolAddress((void**)&qwl, g_qwl);
    cudaGetSymbolAddress((void**)&kwh, g_kwh); cudaGetSymbolAddress((void**)&kwl, g_kwl);
    cudaGetSymbolAddress((void**)&vwh, g_vwh); cudaGetSymbolAddress((void**)&vwl, g_vwl);
    cudaGetSymbolAddress((void**)&pwh, g_pwh); cudaGetSymbolAddress((void**)&pwl, g_pwl);
    cudaGetSymbolAddress((void**)&ah,  g_ah);  cudaGetSymbolAddress((void**)&al,  g_al);
    cudaGetSymbolAddress((void**)&qkvh, g_qkvh); cudaGetSymbolAddress((void**)&qkvl, g_qkvl);
    cudaGetSymbolAddress((void**)&kcth, g_kcth); cudaGetSymbolAddress((void**)&kctl, g_kctl);
    cudaGetSymbolAddress((void**)&vcth, g_vcth); cudaGetSymbolAddress((void**)&vctl, g_vctl);

    cudaFuncSetAttribute(gemm3_fused, cudaFuncAttributeMaxDynamicSharedMemorySize, SGEMM_SMEM);
    cudaFuncSetAttribute(gemm_tc,     cudaFuncAttributeMaxDynamicSharedMemorySize, SGEMM_SMEM);
    cudaFuncSetAttribute(attn_tc,     cudaFuncAttributeMaxDynamicSharedMemorySize, ATTN_SMEM);

    // 1: mask
    normalize_mask_kernel<<<1, 64>>>(mask);

    // 2: all input splits in ONE launch
    SplitArgs sa;
    sa.src[0] = (const float4*)x;      sa.hi[0] = (uint2*)xh;  sa.lo[0] = (uint2*)xl;  sa.n4[0] = 3072 * 512 / 4;
    sa.src[1] = (const float4*)x_ctx;  sa.hi[1] = (uint2*)xch; sa.lo[1] = (uint2*)xcl; sa.n4[1] = 4096 * 512 / 4;
    sa.src[2] = (const float4*)dx_ctx; sa.hi[2] = (uint2*)dxh; sa.lo[2] = (uint2*)dxl; sa.n4[2] = 4096 * 512 / 4;
    sa.src[3] = (const float4*)qkv_w;  sa.hi[3] = (uint2*)qwh; sa.lo[3] = (uint2*)qwl; sa.n4[3] = 1536 * 512 / 4;
    sa.src[4] = (const float4*)k_w;    sa.hi[4] = (uint2*)kwh; sa.lo[4] = (uint2*)kwl; sa.n4[4] = 512 * 512 / 4;
    sa.src[5] = (const float4*)v_w;    sa.hi[5] = (uint2*)vwh; sa.lo[5] = (uint2*)vwl; sa.n4[5] = 512 * 512 / 4;
    sa.src[6] = (const float4*)proj_w; sa.hi[6] = (uint2*)pwh; sa.lo[6] = (uint2*)pwl; sa.n4[6] = 512 * 512 / 4;
    split_all<<<dim3(296, 7), 256>>>(sa);

    // 3: qkv + kctx + vctx in ONE fused launch (mask-aware early exit)
    Gemm3 g3;
    g3.Ah[0] = xh;  g3.Al[0] = xl;  g3.Wh[0] = qwh; g3.Wl[0] = qwl;
    g3.Ch[0] = qkvh; g3.Cl[0] = qkvl;
    g3.Ah[1] = dxh; g3.Al[1] = dxl; g3.Wh[1] = kwh; g3.Wl[1] = kwl;
    g3.Ch[1] = kcth; g3.Cl[1] = kctl;
    g3.Ah[2] = xch; g3.Al[2] = xcl; g3.Wh[2] = vwh; g3.Wl[2] = vwl;
    g3.Ch[2] = vcth; g3.Cl[2] = vctl;
    gemm3_fused<<<1088, 256, SGEMM_SMEM>>>(g3);

    // 4: key-split flash attention, 3-buffer ring -> hi/lo bf16
    attn_tc<<<dim3(12, 8, 4), 256, ATTN_SMEM>>>(
        qkvh, qkvl, kcth, kctl, vcth, vctl, ah, al);

    // 5: final projection + bias -> d_out (fp32)
    gemm_tc<<<dim3(512 / 64, 3072 / 128), 256, SGEMM_SMEM>>>(
        ah, al, pwh, pwl, proj_b, out, 3072, 512, 512);
}